// round 4
// baseline (speedup 1.0000x reference)
#include <cuda_runtime.h>
#include <cuda_bf16.h>
#include <math_constants.h>

#define T_TOK 8192
#define DIM   256
#define NSLOT 4096
#define FULLM 0xffffffffu
#define GPAD  136          // smem row pitch (floats) for a 128-wide tile
#define BK    16

typedef unsigned long long ull;

// ---------------- scratch (device globals; no allocation) ----------------
__device__ float g_k[T_TOK * DIM];
__device__ float g_v[T_TOK * DIM];
__device__ float g_q[T_TOK * DIM];
__device__ float g_pmax[32 * T_TOK];
__device__ int   g_pidx[32 * T_TOK];
__device__ unsigned g_info[T_TOK];     // best | novel<<16 | m<<17
__device__ unsigned g_pick[T_TOK];     // slot | novel<<16 | applied<<17
__device__ float g_act[NSLOT];
__device__ float g_lb[NSLOT];
__device__ float g_kb[NSLOT * DIM];
__device__ float g_vb[NSLOT * DIM];
__device__ float g_rowsum[T_TOK];
__device__ float g_S[(size_t)T_TOK * NSLOT];   // 134MB logits/exp buffer

// ---------------- f32x2 helpers ------------------------------------------
__device__ __forceinline__ ull dupf(float b) {
    ull r;
    asm("mov.b64 %0, {%1, %1};" : "=l"(r) : "f"(b));
    return r;
}
__device__ __forceinline__ void fma2(ull& d, ull a, ull b) {
    asm("fma.rn.f32x2 %0, %1, %2, %0;" : "+l"(d) : "l"(a), "l"(b));
}
__device__ __forceinline__ float2 up2(ull u) {
    float2 f;
    asm("mov.b64 {%0, %1}, %2;" : "=f"(f.x), "=f"(f.y) : "l"(u));
    return f;
}

// ---------------- generic 128x128 f32x2 GEMM mainloop ---------------------
// A: gmem, row-major [128 rows][K], k contiguous (pre-offset to tile row 0)
// B (BDIRECT=false): gmem row-major [128 rows][K]  -> smem transposed [k][n]
// B (BDIRECT=true) : gmem row-major [K][ldb], pre-offset to col 0 of tile
// acc[rp][c] packs output rows (ty*8+2rp, ty*8+2rp+1), col = tx*8+c.
template<bool BDIRECT>
__device__ __forceinline__ void gemm128(
    const float* __restrict__ A, const float* __restrict__ B,
    int lda, int ldb, int K, ull acc[4][8], float* sA, float* sB, int tid)
{
    const int tx = tid & 15, ty = tid >> 4;
    const int arow = tid >> 1;          // 0..127
    const int akb  = (tid & 1) * 8;     // 0 or 8
    const int bkr  = tid >> 4;          // 0..15 (direct-B)
    const int bnc  = (tid & 15) * 8;    // 0..120 (direct-B)

#pragma unroll
    for (int rp = 0; rp < 4; rp++)
#pragma unroll
        for (int c = 0; c < 8; c++) acc[rp][c] = 0ull;

    // prologue: chunk 0 -> smem
    {
        float4 ra0 = *(const float4*)&A[arow * lda + akb];
        float4 ra1 = *(const float4*)&A[arow * lda + akb + 4];
        sA[(akb + 0) * GPAD + arow] = ra0.x; sA[(akb + 1) * GPAD + arow] = ra0.y;
        sA[(akb + 2) * GPAD + arow] = ra0.z; sA[(akb + 3) * GPAD + arow] = ra0.w;
        sA[(akb + 4) * GPAD + arow] = ra1.x; sA[(akb + 5) * GPAD + arow] = ra1.y;
        sA[(akb + 6) * GPAD + arow] = ra1.z; sA[(akb + 7) * GPAD + arow] = ra1.w;
        if (BDIRECT) {
            float4 rb0 = *(const float4*)&B[bkr * ldb + bnc];
            float4 rb1 = *(const float4*)&B[bkr * ldb + bnc + 4];
            *(float4*)&sB[bkr * GPAD + bnc]     = rb0;
            *(float4*)&sB[bkr * GPAD + bnc + 4] = rb1;
        } else {
            float4 rb0 = *(const float4*)&B[arow * ldb + akb];
            float4 rb1 = *(const float4*)&B[arow * ldb + akb + 4];
            sB[(akb + 0) * GPAD + arow] = rb0.x; sB[(akb + 1) * GPAD + arow] = rb0.y;
            sB[(akb + 2) * GPAD + arow] = rb0.z; sB[(akb + 3) * GPAD + arow] = rb0.w;
            sB[(akb + 4) * GPAD + arow] = rb1.x; sB[(akb + 5) * GPAD + arow] = rb1.y;
            sB[(akb + 6) * GPAD + arow] = rb1.z; sB[(akb + 7) * GPAD + arow] = rb1.w;
        }
    }
    __syncthreads();

    for (int kk = 0; kk < K; kk += BK) {
        const bool more = (kk + BK) < K;
        float4 ra0, ra1, rb0, rb1;
        if (more) {
            ra0 = *(const float4*)&A[arow * lda + kk + BK + akb];
            ra1 = *(const float4*)&A[arow * lda + kk + BK + akb + 4];
            if (BDIRECT) {
                rb0 = *(const float4*)&B[(kk + BK + bkr) * ldb + bnc];
                rb1 = *(const float4*)&B[(kk + BK + bkr) * ldb + bnc + 4];
            } else {
                rb0 = *(const float4*)&B[arow * ldb + kk + BK + akb];
                rb1 = *(const float4*)&B[arow * ldb + kk + BK + akb + 4];
            }
        }
        // compute on resident chunk
#pragma unroll
        for (int kc = 0; kc < BK; kc++) {
            const float* ar = sA + kc * GPAD + ty * 8;
            ull a0 = *(const ull*)(ar + 0);
            ull a1 = *(const ull*)(ar + 2);
            ull a2 = *(const ull*)(ar + 4);
            ull a3 = *(const ull*)(ar + 6);
            const float* br = sB + kc * GPAD + tx * 8;
#pragma unroll
            for (int c = 0; c < 8; c++) {
                ull bd = dupf(br[c]);
                fma2(acc[0][c], a0, bd);
                fma2(acc[1][c], a1, bd);
                fma2(acc[2][c], a2, bd);
                fma2(acc[3][c], a3, bd);
            }
        }
        __syncthreads();
        if (more) {
            sA[(akb + 0) * GPAD + arow] = ra0.x; sA[(akb + 1) * GPAD + arow] = ra0.y;
            sA[(akb + 2) * GPAD + arow] = ra0.z; sA[(akb + 3) * GPAD + arow] = ra0.w;
            sA[(akb + 4) * GPAD + arow] = ra1.x; sA[(akb + 5) * GPAD + arow] = ra1.y;
            sA[(akb + 6) * GPAD + arow] = ra1.z; sA[(akb + 7) * GPAD + arow] = ra1.w;
            if (BDIRECT) {
                *(float4*)&sB[bkr * GPAD + bnc]     = rb0;
                *(float4*)&sB[bkr * GPAD + bnc + 4] = rb1;
            } else {
                sB[(akb + 0) * GPAD + arow] = rb0.x; sB[(akb + 1) * GPAD + arow] = rb0.y;
                sB[(akb + 2) * GPAD + arow] = rb0.z; sB[(akb + 3) * GPAD + arow] = rb0.w;
                sB[(akb + 4) * GPAD + arow] = rb1.x; sB[(akb + 5) * GPAD + arow] = rb1.y;
                sB[(akb + 6) * GPAD + arow] = rb1.z; sB[(akb + 7) * GPAD + arow] = rb1.w;
            }
            __syncthreads();
        }
    }
}

// ---------------- 1) projections -----------------------------------------
__global__ __launch_bounds__(256, 2) void proj_kernel(
    const float* __restrict__ x,
    const float* __restrict__ Wk, const float* __restrict__ bk,
    const float* __restrict__ Wv, const float* __restrict__ bv,
    const float* __restrict__ Wq, const float* __restrict__ bq)
{
    __shared__ float sA[BK * GPAD];
    __shared__ float sB[BK * GPAD];
    const float* W; const float* bvec; float* out;
    if (blockIdx.z == 0)      { W = Wk; bvec = bk; out = g_k; }
    else if (blockIdx.z == 1) { W = Wv; bvec = bv; out = g_v; }
    else                      { W = Wq; bvec = bq; out = g_q; }

    int tid = threadIdx.x;
    int m0 = blockIdx.x * 128, n0 = blockIdx.y * 128;
    ull acc[4][8];
    gemm128<false>(x + (size_t)m0 * DIM, W + (size_t)n0 * DIM, DIM, DIM, DIM,
                   acc, sA, sB, tid);
    int tx = tid & 15, ty = tid >> 4;
    int col0 = n0 + tx * 8;
    float bb[8];
#pragma unroll
    for (int c = 0; c < 8; c++) bb[c] = bvec[col0 + c];
#pragma unroll
    for (int rp = 0; rp < 4; rp++) {
        int row = m0 + ty * 8 + 2 * rp;
        float v0[8], v1[8];
#pragma unroll
        for (int c = 0; c < 8; c++) {
            float2 f = up2(acc[rp][c]);
            v0[c] = f.x + bb[c];
            v1[c] = f.y + bb[c];
        }
        *(float4*)&out[(size_t)row * DIM + col0]         = make_float4(v0[0], v0[1], v0[2], v0[3]);
        *(float4*)&out[(size_t)row * DIM + col0 + 4]     = make_float4(v0[4], v0[5], v0[6], v0[7]);
        *(float4*)&out[(size_t)(row + 1) * DIM + col0]     = make_float4(v1[0], v1[1], v1[2], v1[3]);
        *(float4*)&out[(size_t)(row + 1) * DIM + col0 + 4] = make_float4(v1[4], v1[5], v1[6], v1[7]);
    }
}

// ---------------- 2) simmax: per-token max/argmax partials ----------------
__global__ __launch_bounds__(256, 2) void simmax_kernel(const float* __restrict__ keys0)
{
    __shared__ float sA[BK * GPAD];
    __shared__ float sB[BK * GPAD];
    int tid = threadIdx.x;
    int m0 = blockIdx.x * 128, n0 = blockIdx.y * 128;
    ull acc[4][8];
    gemm128<false>(g_k + (size_t)m0 * DIM, keys0 + (size_t)n0 * DIM, DIM, DIM, DIM,
                   acc, sA, sB, tid);
    int tx = tid & 15, ty = tid >> 4;
#pragma unroll
    for (int r = 0; r < 8; r++) {
        float best = -CUDART_INF_F; int bi = 0x7fffffff;
#pragma unroll
        for (int c = 0; c < 8; c++) {
            float2 f = up2(acc[r >> 1][c]);
            float v = (r & 1) ? f.y : f.x;
            if (v > best) { best = v; bi = n0 + tx * 8 + c; }
        }
#pragma unroll
        for (int o = 1; o < 16; o <<= 1) {
            float ov = __shfl_xor_sync(FULLM, best, o);
            int   oi = __shfl_xor_sync(FULLM, bi, o);
            if (ov > best || (ov == best && oi < bi)) { best = ov; bi = oi; }
        }
        if (tx == 0) {
            int t = m0 + ty * 8 + r;
            g_pmax[blockIdx.y * T_TOK + t] = best;
            g_pidx[blockIdx.y * T_TOK + t] = bi;
        }
    }
}

// ---------------- 3) combine segments -> g_info ---------------------------
__global__ void combine_kernel(const void* __restrict__ maskptr)
{
    int t = blockIdx.x * blockDim.x + threadIdx.x;
    if (t >= T_TOK) return;
    float best = -CUDART_INF_F; int bi = 0;
#pragma unroll
    for (int s = 0; s < 32; s++) {
        float v = g_pmax[s * T_TOK + t];
        int   i = g_pidx[s * T_TOK + t];
        if (v > best) { best = v; bi = i; }   // segments ascend in index
    }
    bool novel = (best * 0.0625f) < 0.5f;
    const unsigned* w = (const unsigned*)maskptr;
    bool bytemode = (w[0] == 0x01010101u);
    bool m;
    if (bytemode) m = ((const unsigned char*)maskptr)[t] != 0;
    else          m = (w[t] != 0);
    g_info[t] = (unsigned)bi | (novel ? 0x10000u : 0u) | (m ? 0x20000u : 0u);
}

// ---------------- 4) sequential scan (unchanged) --------------------------
__global__ __launch_bounds__(256) void scan_kernel(const float* __restrict__ act0)
{
    __shared__ __align__(16) float s_act[NSLOT];
    __shared__ __align__(16) float s_gmin[128];
    __shared__ int s_gidx[128];
    int tid = threadIdx.x;
    for (int i = tid; i < NSLOT; i += 256) s_act[i] = act0[i];
    __syncthreads();
    int wid = tid >> 5, lane = tid & 31;
    for (int g = wid; g < 128; g += 8) {
        float v = s_act[g * 32 + lane];
        unsigned mv = __reduce_min_sync(FULLM, __float_as_uint(v));
        unsigned bal = __ballot_sync(FULLM, __float_as_uint(v) == mv);
        if (lane == 0) { s_gmin[g] = __uint_as_float(mv); s_gidx[g] = g * 32 + (__ffs(bal) - 1); }
    }
    __syncthreads();

    if (wid == 0) {
        unsigned myinfo = 0;
        for (int t = 0; t < T_TOK; t++) {
            if ((t & 31) == 0) myinfo = __ldg(&g_info[t + lane]);
            unsigned info = __shfl_sync(FULLM, myinfo, t & 31);
            if (info & 0x20000u) {
                int slot;
                if (info & 0x10000u) {
                    float4 q4 = *(const float4*)&s_gmin[lane * 4];
                    float bv = q4.x; int bg = lane * 4;
                    if (q4.y < bv) { bv = q4.y; bg = lane * 4 + 1; }
                    if (q4.z < bv) { bv = q4.z; bg = lane * 4 + 2; }
                    if (q4.w < bv) { bv = q4.w; bg = lane * 4 + 3; }
                    unsigned mv = __reduce_min_sync(FULLM, __float_as_uint(bv));
                    unsigned bal = __ballot_sync(FULLM, __float_as_uint(bv) == mv);
                    int L = __ffs(bal) - 1;
                    int grp = __shfl_sync(FULLM, bg, L);
                    slot = s_gidx[grp];
                } else {
                    slot = (int)(info & 0xFFFFu);
                }
                float na = fminf(1.0f, s_act[slot] + 0.1f);
                if (lane == 0) s_act[slot] = na;
                __syncwarp();
                int g = slot >> 5;
                float v = s_act[g * 32 + lane];
                unsigned mv2 = __reduce_min_sync(FULLM, __float_as_uint(v));
                unsigned bal2 = __ballot_sync(FULLM, __float_as_uint(v) == mv2);
                if (lane == 0) {
                    s_gmin[g] = __uint_as_float(mv2);
                    s_gidx[g] = g * 32 + (__ffs(bal2) - 1);
                    g_pick[t] = (unsigned)slot | (info & 0x10000u) | 0x20000u;
                }
                __syncwarp();
            } else {
                if (lane == 0) g_pick[t] = 0u;
            }
        }
    }
    __syncthreads();
    for (int i = tid; i < NSLOT; i += 256) g_act[i] = s_act[i];
}

// ---------------- 5) rebuild kb/vb (unchanged) ----------------------------
__global__ __launch_bounds__(256) void rebuild_kernel(
    const float* __restrict__ keys0, const float* __restrict__ values0)
{
    int wid = threadIdx.x >> 5, lane = threadIdx.x & 31;
    int s = blockIdx.x * 8 + wid;
    float kreg[8], vreg[8];
#pragma unroll
    for (int r = 0; r < 8; r++) {
        kreg[r] = keys0[s * DIM + lane + 32 * r];
        vreg[r] = values0[s * DIM + lane + 32 * r];
    }
    for (int base = 0; base < T_TOK; base += 32) {
        unsigned pk = __ldg(&g_pick[base + lane]);
        unsigned match = __ballot_sync(FULLM,
            (pk & 0x20000u) && ((pk & 0xFFFFu) == (unsigned)s));
        while (match) {
            int bl = __ffs(match) - 1;
            match &= match - 1;
            unsigned pkb = __shfl_sync(FULLM, pk, bl);
            float alpha = (pkb & 0x10000u) ? 0.9f : 0.3f;
            float om = 1.0f - alpha;
            int t = base + bl;
            const float* kr = &g_k[(size_t)t * DIM];
            const float* vr = &g_v[(size_t)t * DIM];
#pragma unroll
            for (int r = 0; r < 8; r++) {
                kreg[r] = om * kreg[r] + alpha * __ldg(&kr[lane + 32 * r]);
                vreg[r] = om * vreg[r] + alpha * __ldg(&vr[lane + 32 * r]);
            }
        }
    }
#pragma unroll
    for (int r = 0; r < 8; r++) {
        g_kb[s * DIM + lane + 32 * r] = kreg[r];
        g_vb[s * DIM + lane + 32 * r] = vreg[r];
    }
}

// ---------------- 5b) activation bias -------------------------------------
__global__ void actbias_kernel()
{
    int n = blockIdx.x * blockDim.x + threadIdx.x;
    if (n >= NSLOT) return;
    float a = g_act[n];
    g_lb[n] = (a < 0.01f) ? -1e30f : logf(a);
}

// ---------------- 6a) attnA: S = q@kb^T*scale + lbias, row-max partials ---
__global__ __launch_bounds__(256, 2) void attnA_kernel()
{
    __shared__ float sA[BK * GPAD];
    __shared__ float sB[BK * GPAD];
    int tid = threadIdx.x;
    int m0 = blockIdx.x * 128, n0 = blockIdx.y * 128;
    ull acc[4][8];
    gemm128<false>(g_q + (size_t)m0 * DIM, g_kb + (size_t)n0 * DIM, DIM, DIM, DIM,
                   acc, sA, sB, tid);
    int tx = tid & 15, ty = tid >> 4;
    int col0 = n0 + tx * 8;
    float lbv[8];
#pragma unroll
    for (int c = 0; c < 8; c++) lbv[c] = g_lb[col0 + c];
#pragma unroll
    for (int r = 0; r < 8; r++) {
        int row = m0 + ty * 8 + r;
        float v[8]; float rmax = -CUDART_INF_F;
#pragma unroll
        for (int c = 0; c < 8; c++) {
            float2 f = up2(acc[r >> 1][c]);
            float s = ((r & 1) ? f.y : f.x) * 0.0625f + lbv[c];
            v[c] = s;
            rmax = fmaxf(rmax, s);
        }
        *(float4*)&g_S[(size_t)row * NSLOT + col0]     = make_float4(v[0], v[1], v[2], v[3]);
        *(float4*)&g_S[(size_t)row * NSLOT + col0 + 4] = make_float4(v[4], v[5], v[6], v[7]);
#pragma unroll
        for (int o = 1; o < 16; o <<= 1)
            rmax = fmaxf(rmax, __shfl_xor_sync(FULLM, rmax, o));
        if (tx == 0) g_pmax[blockIdx.y * T_TOK + row] = rmax;
    }
}

// ---------------- 6b) attnB: E = exp(S - m), row sums ---------------------
__global__ __launch_bounds__(256) void attnB_kernel()
{
    int tid = threadIdx.x;
    int w = tid >> 5, lane = tid & 31;
    int rbase = blockIdx.x * 64 + w * 8;
#pragma unroll
    for (int rr = 0; rr < 8; rr++) {
        int row = rbase + rr;
        float m = g_pmax[lane * T_TOK + row];
#pragma unroll
        for (int o = 16; o > 0; o >>= 1)
            m = fmaxf(m, __shfl_xor_sync(FULLM, m, o));
        float* Sr = &g_S[(size_t)row * NSLOT];
        float sum = 0.f;
#pragma unroll 4
        for (int q = 0; q < 32; q++) {
            float4 v = *(float4*)&Sr[lane * 4 + q * 128];
            v.x = __expf(v.x - m); v.y = __expf(v.y - m);
            v.z = __expf(v.z - m); v.w = __expf(v.w - m);
            *(float4*)&Sr[lane * 4 + q * 128] = v;
            sum += v.x + v.y + v.z + v.w;
        }
#pragma unroll
        for (int o = 16; o > 0; o >>= 1)
            sum += __shfl_xor_sync(FULLM, sum, o);
        if (lane == 0) g_rowsum[row] = sum;
    }
}

// ---------------- 6c) attnC: O = (E @ vb) / rowsum -------------------------
__global__ __launch_bounds__(256, 2) void attnC_kernel(float* __restrict__ out)
{
    __shared__ float sA[BK * GPAD];
    __shared__ float sB[BK * GPAD];
    int tid = threadIdx.x;
    int m0 = blockIdx.x * 128, n0 = blockIdx.y * 128;
    ull acc[4][8];
    gemm128<true>(g_S + (size_t)m0 * NSLOT, g_vb + n0, NSLOT, DIM, NSLOT,
                  acc, sA, sB, tid);
    int tx = tid & 15, ty = tid >> 4;
    int col0 = n0 + tx * 8;
#pragma unroll
    for (int rp = 0; rp < 4; rp++) {
        int row = m0 + ty * 8 + 2 * rp;
        float inv0 = 1.0f / g_rowsum[row];
        float inv1 = 1.0f / g_rowsum[row + 1];
        float v0[8], v1[8];
#pragma unroll
        for (int c = 0; c < 8; c++) {
            float2 f = up2(acc[rp][c]);
            v0[c] = f.x * inv0;
            v1[c] = f.y * inv1;
        }
        *(float4*)&out[(size_t)row * DIM + col0]           = make_float4(v0[0], v0[1], v0[2], v0[3]);
        *(float4*)&out[(size_t)row * DIM + col0 + 4]       = make_float4(v0[4], v0[5], v0[6], v0[7]);
        *(float4*)&out[(size_t)(row + 1) * DIM + col0]     = make_float4(v1[0], v1[1], v1[2], v1[3]);
        *(float4*)&out[(size_t)(row + 1) * DIM + col0 + 4] = make_float4(v1[4], v1[5], v1[6], v1[7]);
    }
}

// --------------------------------- launch --------------------------------
extern "C" void kernel_launch(void* const* d_in, const int* in_sizes, int n_in,
                              void* d_out, int out_size)
{
    const float* x     = (const float*)d_in[0];
    const void*  wmask = d_in[1];
    const float* keys0 = (const float*)d_in[2];
    const float* vals0 = (const float*)d_in[3];
    const float* act0  = (const float*)d_in[4];
    const float* Wk    = (const float*)d_in[5];
    const float* bk    = (const float*)d_in[6];
    const float* Wv    = (const float*)d_in[7];
    const float* bv    = (const float*)d_in[8];
    const float* Wq    = (const float*)d_in[9];
    const float* bq    = (const float*)d_in[10];
    float* out = (float*)d_out;

    proj_kernel<<<dim3(T_TOK / 128, DIM / 128, 3), 256>>>(x, Wk, bk, Wv, bv, Wq, bq);
    simmax_kernel<<<dim3(T_TOK / 128, NSLOT / 128), 256>>>(keys0);
    combine_kernel<<<T_TOK / 256, 256>>>(wmask);
    scan_kernel<<<1, 256>>>(act0);
    rebuild_kernel<<<NSLOT / 8, 256>>>(keys0, vals0);
    actbias_kernel<<<NSLOT / 256, 256>>>();
    attnA_kernel<<<dim3(T_TOK / 128, NSLOT / 128), 256>>>();
    attnB_kernel<<<T_TOK / 64, 256>>>();
    attnC_kernel<<<dim3(T_TOK / 128, DIM / 128), 256>>>(out);
}

// round 6
// speedup vs baseline: 1.2041x; 1.2041x over previous
#include <cuda_runtime.h>
#include <cuda_bf16.h>
#include <math_constants.h>

#define T_TOK 8192
#define DIM   256
#define NSLOT 4096
#define FULLM 0xffffffffu
typedef unsigned int u32;
typedef unsigned long long u64;
typedef __nv_bfloat16 bf16;

// ---------------- scratch ----------------
__device__ float g_k[T_TOK * DIM];
__device__ float g_v[T_TOK * DIM];
__device__ float g_q[T_TOK * DIM];
__device__ float g_pmax[32 * T_TOK];
__device__ int   g_pidx[32 * T_TOK];
__device__ unsigned g_info[T_TOK];
__device__ unsigned g_pick[T_TOK];
__device__ float g_act[NSLOT];
__device__ float g_lb[NSLOT];
__device__ float g_kb[NSLOT * DIM];
__device__ float g_vb[NSLOT * DIM];
__device__ float g_rowsum[T_TOK];
__device__ float g_S[(size_t)T_TOK * NSLOT];

__device__ bf16 g_xhi[T_TOK*DIM], g_xlo[T_TOK*DIM];
__device__ bf16 g_khi[T_TOK*DIM], g_klo[T_TOK*DIM];
__device__ bf16 g_qhi[T_TOK*DIM], g_qlo[T_TOK*DIM];
__device__ bf16 g_wkh[DIM*DIM], g_wkl[DIM*DIM];
__device__ bf16 g_wvh[DIM*DIM], g_wvl[DIM*DIM];
__device__ bf16 g_wqh[DIM*DIM], g_wql[DIM*DIM];
__device__ bf16 g_k0h[NSLOT*DIM], g_k0l[NSLOT*DIM];
__device__ bf16 g_kbh[NSLOT*DIM], g_kbl[NSLOT*DIM];
__device__ bf16 g_vth[DIM*NSLOT], g_vtl[DIM*NSLOT];
__device__ bf16 g_Eh[(size_t)T_TOK*NSLOT], g_El[(size_t)T_TOK*NSLOT];

// ---------------- helpers ----------------
__device__ __forceinline__ u32 cvta_sm(const void* p){
    u32 a; asm("{.reg .u64 t; cvta.to.shared.u64 t, %1; cvt.u32.u64 %0, t;}" : "=r"(a) : "l"(p));
    return a;
}
#define CPA(dst, src) asm volatile("cp.async.cg.shared.global [%0], [%1], 16;" :: "r"(dst), "l"(src))
#define CPCOMMIT()    asm volatile("cp.async.commit_group;" ::: "memory")
#define CPWAIT1()     asm volatile("cp.async.wait_group 1;" ::: "memory")
#define CPWAIT0()     asm volatile("cp.async.wait_group 0;" ::: "memory")
#define LDX4(r, a) asm volatile("ldmatrix.sync.aligned.m8n8.x4.shared.b16 {%0,%1,%2,%3}, [%4];" \
    : "=r"((r)[0]), "=r"((r)[1]), "=r"((r)[2]), "=r"((r)[3]) : "r"(a))
#define MMA(D, A, B0, B1) asm volatile( \
    "mma.sync.aligned.m16n8k16.row.col.f32.bf16.bf16.f32 " \
    "{%0,%1,%2,%3}, {%4,%5,%6,%7}, {%8,%9}, {%0,%1,%2,%3};" \
    : "+f"((D)[0]), "+f"((D)[1]), "+f"((D)[2]), "+f"((D)[3]) \
    : "r"((A)[0]), "r"((A)[1]), "r"((A)[2]), "r"((A)[3]), "r"(B0), "r"(B1))

#define PITCH 80
#define ABUF  10240      // 128 rows * 80B
#define BUFSZ 40960      // 4 arrays
#define SMEMSZ 81920     // double buffered

// ---------------- universal mma.sync GEMM ----------------
// mode: 0 proj-k, 1 proj-v, 2 proj-q, 3 simmax, 4 attnA, 5 attnC
__global__ __launch_bounds__(256) void mm_gemm(int mode, const float* __restrict__ aux,
                                               float* __restrict__ outp)
{
    extern __shared__ char smx[];
    u32 smb = cvta_sm(smx);
    int tid = threadIdx.x, lane = tid & 31, wid = tid >> 5;
    int wm = wid >> 2, wn = wid & 3;                // 2 x 4 warp grid
    int m0 = blockIdx.x * 128, n0 = blockIdx.y * 128;

    const bf16 *Ah, *Al, *Bh, *Bl; size_t lda, ldb; int K;
    float* out = 0; bf16 *oh = 0, *ol = 0;
    switch (mode){
    case 0: Ah=g_xhi; Al=g_xlo; Bh=g_wkh; Bl=g_wkl; lda=ldb=DIM; K=DIM; out=g_k; oh=g_khi; ol=g_klo; break;
    case 1: Ah=g_xhi; Al=g_xlo; Bh=g_wvh; Bl=g_wvl; lda=ldb=DIM; K=DIM; out=g_v; break;
    case 2: Ah=g_xhi; Al=g_xlo; Bh=g_wqh; Bl=g_wql; lda=ldb=DIM; K=DIM; out=g_q; oh=g_qhi; ol=g_qlo; break;
    case 3: Ah=g_khi; Al=g_klo; Bh=g_k0h; Bl=g_k0l; lda=ldb=DIM; K=DIM; break;
    case 4: Ah=g_qhi; Al=g_qlo; Bh=g_kbh; Bl=g_kbl; lda=ldb=DIM; K=DIM; break;
    default: Ah=g_Eh; Al=g_El; Bh=g_vth; Bl=g_vtl; lda=ldb=NSLOT; K=NSLOT; out=outp; break;
    }
    const char* gsrc[4];
    gsrc[0] = (const char*)Ah + (size_t)m0*lda*2;
    gsrc[1] = (const char*)Al + (size_t)m0*lda*2;
    gsrc[2] = (const char*)Bh + (size_t)n0*ldb*2;
    gsrc[3] = (const char*)Bl + (size_t)n0*ldb*2;
    size_t rstA = lda*2, rstB = ldb*2;

    // per-lane ldmatrix offsets
    int a_ro = (lane & 7) + ((lane & 8) ? 8 : 0);
    int a_ko = (lane & 16) ? 8 : 0;
    int b_ro = (lane & 7) + ((lane & 16) ? 8 : 0);
    int b_ko = (lane & 8) ? 8 : 0;

    float d[4][4][4] = {};

    int nk = K / 32;
    // prologue copy chunk 0
    {
        int row = (tid >> 2), kc = tid & 3;       // two chunks per thread per array
#pragma unroll
        for (int arr = 0; arr < 4; arr++){
            size_t rs = (arr < 2) ? rstA : rstB;
            u32 db = smb + arr*ABUF;
            CPA(db + (u32)row*PITCH + kc*16, gsrc[arr] + (size_t)row*rs + kc*16);
            CPA(db + (u32)(row+64)*PITCH + kc*16, gsrc[arr] + (size_t)(row+64)*rs + kc*16);
        }
        CPCOMMIT();
    }

    for (int ck = 0; ck < nk; ck++){
        if (ck + 1 < nk){
            int row = (tid >> 2), kc = tid & 3;
            size_t koff = (size_t)(ck + 1) * 64;   // 32 bf16 = 64B
            u32 db = smb + ((ck + 1) & 1) * BUFSZ;
#pragma unroll
            for (int arr = 0; arr < 4; arr++){
                size_t rs = (arr < 2) ? rstA : rstB;
                const char* s = gsrc[arr] + koff;
                CPA(db + arr*ABUF + (u32)row*PITCH + kc*16, s + (size_t)row*rs + kc*16);
                CPA(db + arr*ABUF + (u32)(row+64)*PITCH + kc*16, s + (size_t)(row+64)*rs + kc*16);
            }
            CPCOMMIT();
            CPWAIT1();
        } else {
            CPWAIT0();
        }
        __syncthreads();
        u32 bb = smb + (ck & 1) * BUFSZ;
#pragma unroll
        for (int ks = 0; ks < 2; ks++){
            u32 Abase = bb + (u32)(wm*64 + a_ro)*PITCH + (ks*16 + a_ko)*2;
            u32 Bbase = bb + 2*ABUF + (u32)(wn*32 + b_ro)*PITCH + (ks*16 + b_ko)*2;
            u32 bh[2][4], blr[2][4], a[4][4];
            LDX4(bh[0], Bbase);            LDX4(bh[1], Bbase + 16*PITCH);
            LDX4(blr[0], Bbase + ABUF);    LDX4(blr[1], Bbase + ABUF + 16*PITCH);
#pragma unroll
            for (int ma = 0; ma < 4; ma++) LDX4(a[ma], Abase + ma*16*PITCH);
#pragma unroll
            for (int ma = 0; ma < 4; ma++)
#pragma unroll
                for (int na = 0; na < 4; na++){
                    MMA(d[ma][na], a[ma], bh[na>>1][(na&1)*2],  bh[na>>1][(na&1)*2+1]);
                    MMA(d[ma][na], a[ma], blr[na>>1][(na&1)*2], blr[na>>1][(na&1)*2+1]);
                }
#pragma unroll
            for (int ma = 0; ma < 4; ma++) LDX4(a[ma], Abase + ABUF + ma*16*PITCH);
#pragma unroll
            for (int ma = 0; ma < 4; ma++)
#pragma unroll
                for (int na = 0; na < 4; na++)
                    MMA(d[ma][na], a[ma], bh[na>>1][(na&1)*2], bh[na>>1][(na&1)*2+1]);
        }
        __syncthreads();
    }

    // -------- epilogues --------
    float* redv = (float*)smx;
    int*   redi = (int*)(smx + 2048);
    int qr = lane >> 2, qc = lane & 3;

    if (mode <= 2){
#pragma unroll
        for (int ma = 0; ma < 4; ma++)
#pragma unroll
            for (int rs = 0; rs < 2; rs++){
                int row = m0 + wm*64 + ma*16 + rs*8 + qr;
#pragma unroll
                for (int na = 0; na < 4; na++){
                    int cg = n0 + wn*32 + na*8 + 2*qc;
                    float v0 = d[ma][na][rs*2]   + aux[cg];
                    float v1 = d[ma][na][rs*2+1] + aux[cg+1];
                    *(float2*)&out[(size_t)row*DIM + cg] = make_float2(v0, v1);
                    if (oh){
                        bf16 h0 = __float2bfloat16(v0), h1 = __float2bfloat16(v1);
                        *(__nv_bfloat162*)&oh[(size_t)row*DIM+cg] = __nv_bfloat162(h0, h1);
                        *(__nv_bfloat162*)&ol[(size_t)row*DIM+cg] = __nv_bfloat162(
                            __float2bfloat16(v0 - __bfloat162float(h0)),
                            __float2bfloat16(v1 - __bfloat162float(h1)));
                    }
                }
            }
    } else if (mode == 3){
#pragma unroll
        for (int ma = 0; ma < 4; ma++)
#pragma unroll
            for (int rs = 0; rs < 2; rs++){
                int lrow = wm*64 + ma*16 + rs*8 + qr;
                float bv = -CUDART_INF_F; int bi = 0x7fffffff;
#pragma unroll
                for (int na = 0; na < 4; na++)
#pragma unroll
                    for (int e = 0; e < 2; e++){
                        float v = d[ma][na][rs*2+e];
                        int col = n0 + wn*32 + na*8 + 2*qc + e;
                        if (v > bv){ bv = v; bi = col; }
                    }
#pragma unroll
                for (int o = 1; o < 4; o <<= 1){
                    float ov = __shfl_xor_sync(FULLM, bv, o);
                    int   oi = __shfl_xor_sync(FULLM, bi, o);
                    if (ov > bv || (ov == bv && oi < bi)){ bv = ov; bi = oi; }
                }
                if (qc == 0){ redv[wn*128 + lrow] = bv; redi[wn*128 + lrow] = bi; }
            }
        __syncthreads();
        if (tid < 128){
            float bv = -CUDART_INF_F; int bi = 0x7fffffff;
#pragma unroll
            for (int w = 0; w < 4; w++){
                float v = redv[w*128 + tid]; int i = redi[w*128 + tid];
                if (v > bv || (v == bv && i < bi)){ bv = v; bi = i; }
            }
            g_pmax[blockIdx.y * T_TOK + m0 + tid] = bv;
            g_pidx[blockIdx.y * T_TOK + m0 + tid] = bi;
        }
    } else if (mode == 4){
#pragma unroll
        for (int ma = 0; ma < 4; ma++)
#pragma unroll
            for (int rs = 0; rs < 2; rs++){
                int row = m0 + wm*64 + ma*16 + rs*8 + qr;
                float bv = -CUDART_INF_F;
#pragma unroll
                for (int na = 0; na < 4; na++){
                    int cg = n0 + wn*32 + na*8 + 2*qc;
                    float v0 = d[ma][na][rs*2]  *0.0625f + g_lb[cg];
                    float v1 = d[ma][na][rs*2+1]*0.0625f + g_lb[cg+1];
                    *(float2*)&g_S[(size_t)row*NSLOT + cg] = make_float2(v0, v1);
                    bv = fmaxf(bv, fmaxf(v0, v1));
                }
#pragma unroll
                for (int o = 1; o < 4; o <<= 1)
                    bv = fmaxf(bv, __shfl_xor_sync(FULLM, bv, o));
                if (qc == 0) redv[wn*128 + (row - m0)] = bv;
            }
        __syncthreads();
        if (tid < 128){
            float bv = -CUDART_INF_F;
#pragma unroll
            for (int w = 0; w < 4; w++) bv = fmaxf(bv, redv[w*128 + tid]);
            g_pmax[blockIdx.y * T_TOK + m0 + tid] = bv;
        }
    } else {
#pragma unroll
        for (int ma = 0; ma < 4; ma++)
#pragma unroll
            for (int rs = 0; rs < 2; rs++){
                int row = m0 + wm*64 + ma*16 + rs*8 + qr;
                float inv = 1.0f / g_rowsum[row];
#pragma unroll
                for (int na = 0; na < 4; na++){
                    int cg = n0 + wn*32 + na*8 + 2*qc;
                    *(float2*)&out[(size_t)row*DIM + cg] =
                        make_float2(d[ma][na][rs*2]*inv, d[ma][na][rs*2+1]*inv);
                }
            }
    }
}

// ---------------- splits ----------------
__global__ void split_kernel(const float* __restrict__ src, int mode, int n)
{
    bf16 *h, *l;
    switch (mode){
    case 0: h=g_xhi; l=g_xlo; break;
    case 1: h=g_wkh; l=g_wkl; break;
    case 2: h=g_wvh; l=g_wvl; break;
    case 3: h=g_wqh; l=g_wql; break;
    case 4: h=g_k0h; l=g_k0l; break;
    default: h=g_kbh; l=g_kbl; src=g_kb; break;
    }
    for (int i = blockIdx.x*blockDim.x + threadIdx.x; i < n; i += gridDim.x*blockDim.x){
        float v = src[i];
        bf16 hi = __float2bfloat16(v);
        h[i] = hi;
        l[i] = __float2bfloat16(v - __bfloat162float(hi));
    }
}

__global__ void tsplit_vb()
{
    __shared__ float t[32][33];
    int x = threadIdx.x, y = threadIdx.y;
    int nb = blockIdx.x * 32, db = blockIdx.y * 32;
#pragma unroll
    for (int j = 0; j < 4; j++)
        t[y + 8*j][x] = g_vb[(size_t)(nb + y + 8*j)*DIM + db + x];
    __syncthreads();
#pragma unroll
    for (int j = 0; j < 4; j++){
        float v = t[x][y + 8*j];
        bf16 hi = __float2bfloat16(v);
        size_t o = (size_t)(db + y + 8*j)*NSLOT + nb + x;
        g_vth[o] = hi;
        g_vtl[o] = __float2bfloat16(v - __bfloat162float(hi));
    }
}

// ---------------- combine ----------------
__global__ void combine_kernel(const void* __restrict__ maskptr)
{
    int t = blockIdx.x * blockDim.x + threadIdx.x;
    if (t >= T_TOK) return;
    float best = -CUDART_INF_F; int bi = 0;
#pragma unroll
    for (int s = 0; s < 32; s++){
        float v = g_pmax[s * T_TOK + t];
        int   i = g_pidx[s * T_TOK + t];
        if (v > best){ best = v; bi = i; }
    }
    bool novel = (best * 0.0625f) < 0.5f;
    const unsigned* w = (const unsigned*)maskptr;
    bool bytemode = (w[0] == 0x01010101u);
    bool m;
    if (bytemode) m = ((const unsigned char*)maskptr)[t] != 0;
    else          m = (w[t] != 0);
    g_info[t] = (unsigned)bi | (novel ? 0x10000u : 0u) | (m ? 0x20000u : 0u);
}

// ---------------- scan ----------------
__global__ __launch_bounds__(256) void scan_kernel(const float* __restrict__ act0)
{
    __shared__ __align__(16) float s_act[NSLOT];
    __shared__ __align__(16) float s_gmin[128];
    __shared__ int s_gidx[128];
    int tid = threadIdx.x;
    for (int i = tid; i < NSLOT; i += 256) s_act[i] = act0[i];
    __syncthreads();
    int wid = tid >> 5, lane = tid & 31;
    for (int g = wid; g < 128; g += 8){
        float v = s_act[g * 32 + lane];
        unsigned mv = __reduce_min_sync(FULLM, __float_as_uint(v));
        unsigned bal = __ballot_sync(FULLM, __float_as_uint(v) == mv);
        if (lane == 0){ s_gmin[g] = __uint_as_float(mv); s_gidx[g] = g * 32 + (__ffs(bal) - 1); }
    }
    __syncthreads();

    if (wid == 0){
        unsigned myinfo = 0;
        for (int t = 0; t < T_TOK; t++){
            if ((t & 31) == 0) myinfo = __ldg(&g_info[t + lane]);
            unsigned info = __shfl_sync(FULLM, myinfo, t & 31);
            if (info & 0x20000u){
                int slot;
                if (info & 0x10000u){
                    float4 q4 = *(const float4*)&s_gmin[lane * 4];
                    float bv = q4.x; int bg = lane * 4;
                    if (q4.y < bv){ bv = q4.y; bg = lane * 4 + 1; }
                    if (q4.z < bv){ bv = q4.z; bg = lane * 4 + 2; }
                    if (q4.w < bv){ bv = q4.w; bg = lane * 4 + 3; }
                    unsigned mv = __reduce_min_sync(FULLM, __float_as_uint(bv));
                    unsigned bal = __ballot_sync(FULLM, __float_as_uint(bv) == mv);
                    int L = __ffs(bal) - 1;
                    int grp = __shfl_sync(FULLM, bg, L);
                    slot = s_gidx[grp];
                } else {
                    slot = (int)(info & 0xFFFFu);
                }
                float na = fminf(1.0f, s_act[slot] + 0.1f);
                if (lane == 0) s_act[slot] = na;
                __syncwarp();
                int g = slot >> 5;
                float v = s_act[g * 32 + lane];
                unsigned mv2 = __reduce_min_sync(FULLM, __float_as_uint(v));
                unsigned bal2 = __ballot_sync(FULLM, __float_as_uint(v) == mv2);
                if (lane == 0){
                    s_gmin[g] = __uint_as_float(mv2);
                    s_gidx[g] = g * 32 + (__ffs(bal2) - 1);
                    g_pick[t] = (unsigned)slot | (info & 0x10000u) | 0x20000u;
                }
                __syncwarp();
            } else {
                if (lane == 0) g_pick[t] = 0u;
            }
        }
    }
    __syncthreads();
    for (int i = tid; i < NSLOT; i += 256) g_act[i] = s_act[i];
}

// ---------------- rebuild ----------------
__global__ __launch_bounds__(256) void rebuild_kernel(
    const float* __restrict__ keys0, const float* __restrict__ values0)
{
    int wid = threadIdx.x >> 5, lane = threadIdx.x & 31;
    int s = blockIdx.x * 8 + wid;
    float kreg[8], vreg[8];
#pragma unroll
    for (int r = 0; r < 8; r++){
        kreg[r] = keys0[s * DIM + lane + 32 * r];
        vreg[r] = values0[s * DIM + lane + 32 * r];
    }
    for (int base = 0; base < T_TOK; base += 32){
        unsigned pk = __ldg(&g_pick[base + lane]);
        unsigned match = __ballot_sync(FULLM,
            (pk & 0x20000u) && ((pk & 0xFFFFu) == (unsigned)s));
        while (match){
            int bl = __ffs(match) - 1;
            match &= match - 1;
            unsigned pkb = __shfl_sync(FULLM, pk, bl);
            float alpha = (pkb & 0x10000u) ? 0.9f : 0.3f;
            float om = 1.0f - alpha;
            int t = base + bl;
            const float* kr = &g_k[(size_t)t * DIM];
            const float* vr = &g_v[(size_t)t * DIM];
#pragma unroll
            for (int r = 0; r < 8; r++){
                kreg[r] = om * kreg[r] + alpha * __ldg(&kr[lane + 32 * r]);
                vreg[r] = om * vreg[r] + alpha * __ldg(&vr[lane + 32 * r]);
            }
        }
    }
#pragma unroll
    for (int r = 0; r < 8; r++){
        g_kb[s * DIM + lane + 32 * r] = kreg[r];
        g_vb[s * DIM + lane + 32 * r] = vreg[r];
    }
}

__global__ void actbias_kernel()
{
    int n = blockIdx.x * blockDim.x + threadIdx.x;
    if (n >= NSLOT) return;
    float a = g_act[n];
    g_lb[n] = (a < 0.01f) ? -1e30f : logf(a);
}

// ---------------- attnB ----------------
__global__ __launch_bounds__(256) void attnB_kernel()
{
    int tid = threadIdx.x;
    int w = tid >> 5, lane = tid & 31;
    int rbase = blockIdx.x * 64 + w * 8;
#pragma unroll
    for (int rr = 0; rr < 8; rr++){
        int row = rbase + rr;
        float m = g_pmax[lane * T_TOK + row];
#pragma unroll
        for (int o = 16; o > 0; o >>= 1)
            m = fmaxf(m, __shfl_xor_sync(FULLM, m, o));
        const float* Sr = &g_S[(size_t)row * NSLOT];
        bf16* Eh = &g_Eh[(size_t)row * NSLOT];
        bf16* El = &g_El[(size_t)row * NSLOT];
        float sum = 0.f;
#pragma unroll 4
        for (int q = 0; q < 32; q++){
            int c = lane * 4 + q * 128;
            float4 v = *(const float4*)&Sr[c];
            v.x = __expf(v.x - m); v.y = __expf(v.y - m);
            v.z = __expf(v.z - m); v.w = __expf(v.w - m);
            sum += v.x + v.y + v.z + v.w;
            bf16 h0=__float2bfloat16(v.x), h1=__float2bfloat16(v.y);
            bf16 h2=__float2bfloat16(v.z), h3=__float2bfloat16(v.w);
            *(__nv_bfloat162*)&Eh[c]   = __nv_bfloat162(h0,h1);
            *(__nv_bfloat162*)&Eh[c+2] = __nv_bfloat162(h2,h3);
            *(__nv_bfloat162*)&El[c]   = __nv_bfloat162(
                __float2bfloat16(v.x-__bfloat162float(h0)), __float2bfloat16(v.y-__bfloat162float(h1)));
            *(__nv_bfloat162*)&El[c+2] = __nv_bfloat162(
                __float2bfloat16(v.z-__bfloat162float(h2)), __float2bfloat16(v.w-__bfloat162float(h3)));
        }
#pragma unroll
        for (int o = 16; o > 0; o >>= 1)
            sum += __shfl_xor_sync(FULLM, sum, o);
        if (lane == 0) g_rowsum[row] = sum;
    }
}

// --------------------------------- launch --------------------------------
extern "C" void kernel_launch(void* const* d_in, const int* in_sizes, int n_in,
                              void* d_out, int out_size)
{
    const float* x     = (const float*)d_in[0];
    const void*  wmask = d_in[1];
    const float* keys0 = (const float*)d_in[2];
    const float* vals0 = (const float*)d_in[3];
    const float* act0  = (const float*)d_in[4];
    const float* Wk    = (const float*)d_in[5];
    const float* bk    = (const float*)d_in[6];
    const float* Wv    = (const float*)d_in[7];
    const float* bv    = (const float*)d_in[8];
    const float* Wq    = (const float*)d_in[9];
    const float* bq    = (const float*)d_in[10];
    float* out = (float*)d_out;

    cudaFuncSetAttribute(mm_gemm, cudaFuncAttributeMaxDynamicSharedMemorySize, SMEMSZ);

    split_kernel<<<256, 256>>>(x, 0, T_TOK*DIM);
    split_kernel<<<64, 256>>>(Wk, 1, DIM*DIM);
    split_kernel<<<64, 256>>>(Wv, 2, DIM*DIM);
    split_kernel<<<64, 256>>>(Wq, 3, DIM*DIM);
    split_kernel<<<256, 256>>>(keys0, 4, NSLOT*DIM);

    mm_gemm<<<dim3(64,2), 256, SMEMSZ>>>(0, bk, nullptr);
    mm_gemm<<<dim3(64,2), 256, SMEMSZ>>>(1, bv, nullptr);
    mm_gemm<<<dim3(64,2), 256, SMEMSZ>>>(2, bq, nullptr);
    mm_gemm<<<dim3(64,32), 256, SMEMSZ>>>(3, nullptr, nullptr);

    combine_kernel<<<T_TOK/256, 256>>>(wmask);
    scan_kernel<<<1, 256>>>(act0);
    rebuild_kernel<<<NSLOT/8, 256>>>(keys0, vals0);
    split_kernel<<<256, 256>>>(nullptr, 5, NSLOT*DIM);
    actbias_kernel<<<NSLOT/256, 256>>>();
    tsplit_vb<<<dim3(128,8), dim3(32,8)>>>();

    mm_gemm<<<dim3(64,32), 256, SMEMSZ>>>(4, nullptr, nullptr);
    attnB_kernel<<<T_TOK/64, 256>>>();
    mm_gemm<<<dim3(64,2), 256, SMEMSZ>>>(5, nullptr, out);
}

// round 7
// speedup vs baseline: 1.2083x; 1.0035x over previous
#include <cuda_runtime.h>
#include <cuda_bf16.h>
#include <math_constants.h>

#define T_TOK 8192
#define DIM   256
#define NSLOT 4096
#define FULLM 0xffffffffu
typedef unsigned int u32;
typedef unsigned long long u64;
typedef __nv_bfloat16 bf16;

// ---------------- scratch ----------------
__device__ float g_k[T_TOK * DIM];
__device__ float g_v[T_TOK * DIM];
__device__ float g_q[T_TOK * DIM];
__device__ float g_pmax[32 * T_TOK];
__device__ int   g_pidx[32 * T_TOK];
__device__ unsigned g_info[T_TOK];
__device__ unsigned g_pick[T_TOK];
__device__ float g_act[NSLOT];
__device__ float g_lb[NSLOT];
__device__ float g_kb[NSLOT * DIM];
__device__ float g_vb[NSLOT * DIM];
__device__ float g_rowsum[T_TOK];
__device__ int   g_scanflag;
__device__ float g_S[(size_t)T_TOK * NSLOT];

__device__ bf16 g_xhi[T_TOK*DIM], g_xlo[T_TOK*DIM];
__device__ bf16 g_khi[T_TOK*DIM], g_klo[T_TOK*DIM];
__device__ bf16 g_qhi[T_TOK*DIM], g_qlo[T_TOK*DIM];
__device__ bf16 g_wkh[DIM*DIM], g_wkl[DIM*DIM];
__device__ bf16 g_wvh[DIM*DIM], g_wvl[DIM*DIM];
__device__ bf16 g_wqh[DIM*DIM], g_wql[DIM*DIM];
__device__ bf16 g_k0h[NSLOT*DIM], g_k0l[NSLOT*DIM];
__device__ bf16 g_kbh[NSLOT*DIM], g_kbl[NSLOT*DIM];
__device__ bf16 g_vth[DIM*NSLOT], g_vtl[DIM*NSLOT];
__device__ bf16 g_Eh[(size_t)T_TOK*NSLOT], g_El[(size_t)T_TOK*NSLOT];

// ---------------- helpers ----------------
__device__ __forceinline__ u32 cvta_sm(const void* p){
    u32 a; asm("{.reg .u64 t; cvta.to.shared.u64 t, %1; cvt.u32.u64 %0, t;}" : "=r"(a) : "l"(p));
    return a;
}
#define CPA(dst, src) asm volatile("cp.async.cg.shared.global [%0], [%1], 16;" :: "r"(dst), "l"(src))
#define CPCOMMIT()    asm volatile("cp.async.commit_group;" ::: "memory")
#define CPWAIT1()     asm volatile("cp.async.wait_group 1;" ::: "memory")
#define CPWAIT0()     asm volatile("cp.async.wait_group 0;" ::: "memory")
#define LDX4(r, a) asm volatile("ldmatrix.sync.aligned.m8n8.x4.shared.b16 {%0,%1,%2,%3}, [%4];" \
    : "=r"((r)[0]), "=r"((r)[1]), "=r"((r)[2]), "=r"((r)[3]) : "r"(a))
#define MMA(D, A, B0, B1) asm volatile( \
    "mma.sync.aligned.m16n8k16.row.col.f32.bf16.bf16.f32 " \
    "{%0,%1,%2,%3}, {%4,%5,%6,%7}, {%8,%9}, {%0,%1,%2,%3};" \
    : "+f"((D)[0]), "+f"((D)[1]), "+f"((D)[2]), "+f"((D)[3]) \
    : "r"((A)[0]), "r"((A)[1]), "r"((A)[2]), "r"((A)[3]), "r"(B0), "r"(B1))

#define PITCH 80
#define ABUF  10240
#define BUFSZ 40960
#define SMEMSZ 81920

// ---------------- universal mma.sync GEMM (unchanged from R6) -------------
__global__ __launch_bounds__(256) void mm_gemm(int mode, const float* __restrict__ aux,
                                               float* __restrict__ outp)
{
    extern __shared__ char smx[];
    u32 smb = cvta_sm(smx);
    int tid = threadIdx.x, lane = tid & 31, wid = tid >> 5;
    int wm = wid >> 2, wn = wid & 3;
    int m0 = blockIdx.x * 128, n0 = blockIdx.y * 128;

    const bf16 *Ah, *Al, *Bh, *Bl; size_t lda, ldb; int K;
    float* out = 0; bf16 *oh = 0, *ol = 0;
    switch (mode){
    case 0: Ah=g_xhi; Al=g_xlo; Bh=g_wkh; Bl=g_wkl; lda=ldb=DIM; K=DIM; out=g_k; oh=g_khi; ol=g_klo; break;
    case 1: Ah=g_xhi; Al=g_xlo; Bh=g_wvh; Bl=g_wvl; lda=ldb=DIM; K=DIM; out=g_v; break;
    case 2: Ah=g_xhi; Al=g_xlo; Bh=g_wqh; Bl=g_wql; lda=ldb=DIM; K=DIM; out=g_q; oh=g_qhi; ol=g_qlo; break;
    case 3: Ah=g_khi; Al=g_klo; Bh=g_k0h; Bl=g_k0l; lda=ldb=DIM; K=DIM; break;
    case 4: Ah=g_qhi; Al=g_qlo; Bh=g_kbh; Bl=g_kbl; lda=ldb=DIM; K=DIM; break;
    default: Ah=g_Eh; Al=g_El; Bh=g_vth; Bl=g_vtl; lda=ldb=NSLOT; K=NSLOT; out=outp; break;
    }
    const char* gsrc[4];
    gsrc[0] = (const char*)Ah + (size_t)m0*lda*2;
    gsrc[1] = (const char*)Al + (size_t)m0*lda*2;
    gsrc[2] = (const char*)Bh + (size_t)n0*ldb*2;
    gsrc[3] = (const char*)Bl + (size_t)n0*ldb*2;
    size_t rstA = lda*2, rstB = ldb*2;

    int a_ro = (lane & 7) + ((lane & 8) ? 8 : 0);
    int a_ko = (lane & 16) ? 8 : 0;
    int b_ro = (lane & 7) + ((lane & 16) ? 8 : 0);
    int b_ko = (lane & 8) ? 8 : 0;

    float d[4][4][4] = {};
    int nk = K / 32;
    {
        int row = (tid >> 2), kc = tid & 3;
#pragma unroll
        for (int arr = 0; arr < 4; arr++){
            size_t rs = (arr < 2) ? rstA : rstB;
            u32 db = smb + arr*ABUF;
            CPA(db + (u32)row*PITCH + kc*16, gsrc[arr] + (size_t)row*rs + kc*16);
            CPA(db + (u32)(row+64)*PITCH + kc*16, gsrc[arr] + (size_t)(row+64)*rs + kc*16);
        }
        CPCOMMIT();
    }

    for (int ck = 0; ck < nk; ck++){
        if (ck + 1 < nk){
            int row = (tid >> 2), kc = tid & 3;
            size_t koff = (size_t)(ck + 1) * 64;
            u32 db = smb + ((ck + 1) & 1) * BUFSZ;
#pragma unroll
            for (int arr = 0; arr < 4; arr++){
                size_t rs = (arr < 2) ? rstA : rstB;
                const char* s = gsrc[arr] + koff;
                CPA(db + arr*ABUF + (u32)row*PITCH + kc*16, s + (size_t)row*rs + kc*16);
                CPA(db + arr*ABUF + (u32)(row+64)*PITCH + kc*16, s + (size_t)(row+64)*rs + kc*16);
            }
            CPCOMMIT();
            CPWAIT1();
        } else {
            CPWAIT0();
        }
        __syncthreads();
        u32 bb = smb + (ck & 1) * BUFSZ;
#pragma unroll
        for (int ks = 0; ks < 2; ks++){
            u32 Abase = bb + (u32)(wm*64 + a_ro)*PITCH + (ks*16 + a_ko)*2;
            u32 Bbase = bb + 2*ABUF + (u32)(wn*32 + b_ro)*PITCH + (ks*16 + b_ko)*2;
            u32 bh[2][4], blr[2][4], a[4][4];
            LDX4(bh[0], Bbase);            LDX4(bh[1], Bbase + 16*PITCH);
            LDX4(blr[0], Bbase + ABUF);    LDX4(blr[1], Bbase + ABUF + 16*PITCH);
#pragma unroll
            for (int ma = 0; ma < 4; ma++) LDX4(a[ma], Abase + ma*16*PITCH);
#pragma unroll
            for (int ma = 0; ma < 4; ma++)
#pragma unroll
                for (int na = 0; na < 4; na++){
                    MMA(d[ma][na], a[ma], bh[na>>1][(na&1)*2],  bh[na>>1][(na&1)*2+1]);
                    MMA(d[ma][na], a[ma], blr[na>>1][(na&1)*2], blr[na>>1][(na&1)*2+1]);
                }
#pragma unroll
            for (int ma = 0; ma < 4; ma++) LDX4(a[ma], Abase + ABUF + ma*16*PITCH);
#pragma unroll
            for (int ma = 0; ma < 4; ma++)
#pragma unroll
                for (int na = 0; na < 4; na++)
                    MMA(d[ma][na], a[ma], bh[na>>1][(na&1)*2], bh[na>>1][(na&1)*2+1]);
        }
        __syncthreads();
    }

    float* redv = (float*)smx;
    int*   redi = (int*)(smx + 2048);
    int qr = lane >> 2, qc = lane & 3;

    if (mode <= 2){
#pragma unroll
        for (int ma = 0; ma < 4; ma++)
#pragma unroll
            for (int rs = 0; rs < 2; rs++){
                int row = m0 + wm*64 + ma*16 + rs*8 + qr;
#pragma unroll
                for (int na = 0; na < 4; na++){
                    int cg = n0 + wn*32 + na*8 + 2*qc;
                    float v0 = d[ma][na][rs*2]   + aux[cg];
                    float v1 = d[ma][na][rs*2+1] + aux[cg+1];
                    *(float2*)&out[(size_t)row*DIM + cg] = make_float2(v0, v1);
                    if (oh){
                        bf16 h0 = __float2bfloat16(v0), h1 = __float2bfloat16(v1);
                        *(__nv_bfloat162*)&oh[(size_t)row*DIM+cg] = __nv_bfloat162(h0, h1);
                        *(__nv_bfloat162*)&ol[(size_t)row*DIM+cg] = __nv_bfloat162(
                            __float2bfloat16(v0 - __bfloat162float(h0)),
                            __float2bfloat16(v1 - __bfloat162float(h1)));
                    }
                }
            }
    } else if (mode == 3){
#pragma unroll
        for (int ma = 0; ma < 4; ma++)
#pragma unroll
            for (int rs = 0; rs < 2; rs++){
                int lrow = wm*64 + ma*16 + rs*8 + qr;
                float bv = -CUDART_INF_F; int bi = 0x7fffffff;
#pragma unroll
                for (int na = 0; na < 4; na++)
#pragma unroll
                    for (int e = 0; e < 2; e++){
                        float v = d[ma][na][rs*2+e];
                        int col = n0 + wn*32 + na*8 + 2*qc + e;
                        if (v > bv){ bv = v; bi = col; }
                    }
#pragma unroll
                for (int o = 1; o < 4; o <<= 1){
                    float ov = __shfl_xor_sync(FULLM, bv, o);
                    int   oi = __shfl_xor_sync(FULLM, bi, o);
                    if (ov > bv || (ov == bv && oi < bi)){ bv = ov; bi = oi; }
                }
                if (qc == 0){ redv[wn*128 + lrow] = bv; redi[wn*128 + lrow] = bi; }
            }
        __syncthreads();
        if (tid < 128){
            float bv = -CUDART_INF_F; int bi = 0x7fffffff;
#pragma unroll
            for (int w = 0; w < 4; w++){
                float v = redv[w*128 + tid]; int i = redi[w*128 + tid];
                if (v > bv || (v == bv && i < bi)){ bv = v; bi = i; }
            }
            g_pmax[blockIdx.y * T_TOK + m0 + tid] = bv;
            g_pidx[blockIdx.y * T_TOK + m0 + tid] = bi;
        }
    } else if (mode == 4){
#pragma unroll
        for (int ma = 0; ma < 4; ma++)
#pragma unroll
            for (int rs = 0; rs < 2; rs++){
                int row = m0 + wm*64 + ma*16 + rs*8 + qr;
                float bv = -CUDART_INF_F;
#pragma unroll
                for (int na = 0; na < 4; na++){
                    int cg = n0 + wn*32 + na*8 + 2*qc;
                    float v0 = d[ma][na][rs*2]  *0.0625f + g_lb[cg];
                    float v1 = d[ma][na][rs*2+1]*0.0625f + g_lb[cg+1];
                    *(float2*)&g_S[(size_t)row*NSLOT + cg] = make_float2(v0, v1);
                    bv = fmaxf(bv, fmaxf(v0, v1));
                }
#pragma unroll
                for (int o = 1; o < 4; o <<= 1)
                    bv = fmaxf(bv, __shfl_xor_sync(FULLM, bv, o));
                if (qc == 0) redv[wn*128 + (row - m0)] = bv;
            }
        __syncthreads();
        if (tid < 128){
            float bv = -CUDART_INF_F;
#pragma unroll
            for (int w = 0; w < 4; w++) bv = fmaxf(bv, redv[w*128 + tid]);
            g_pmax[blockIdx.y * T_TOK + m0 + tid] = bv;
        }
    } else {
#pragma unroll
        for (int ma = 0; ma < 4; ma++)
#pragma unroll
            for (int rs = 0; rs < 2; rs++){
                int row = m0 + wm*64 + ma*16 + rs*8 + qr;
                float inv = 1.0f / g_rowsum[row];
#pragma unroll
                for (int na = 0; na < 4; na++){
                    int cg = n0 + wn*32 + na*8 + 2*qc;
                    *(float2*)&out[(size_t)row*DIM + cg] =
                        make_float2(d[ma][na][rs*2]*inv, d[ma][na][rs*2+1]*inv);
                }
            }
    }
}

// ---------------- splits ----------------
__global__ void split_kernel(const float* __restrict__ src, int mode, int n)
{
    bf16 *h, *l;
    switch (mode){
    case 0: h=g_xhi; l=g_xlo; break;
    case 1: h=g_wkh; l=g_wkl; break;
    case 2: h=g_wvh; l=g_wvl; break;
    case 3: h=g_wqh; l=g_wql; break;
    case 4: h=g_k0h; l=g_k0l; break;
    default: h=g_kbh; l=g_kbl; src=g_kb; break;
    }
    for (int i = blockIdx.x*blockDim.x + threadIdx.x; i < n; i += gridDim.x*blockDim.x){
        float v = src[i];
        bf16 hi = __float2bfloat16(v);
        h[i] = hi;
        l[i] = __float2bfloat16(v - __bfloat162float(hi));
    }
}

__global__ void tsplit_vb()
{
    __shared__ float t[32][33];
    int x = threadIdx.x, y = threadIdx.y;
    int nb = blockIdx.x * 32, db = blockIdx.y * 32;
#pragma unroll
    for (int j = 0; j < 4; j++)
        t[y + 8*j][x] = g_vb[(size_t)(nb + y + 8*j)*DIM + db + x];
    __syncthreads();
#pragma unroll
    for (int j = 0; j < 4; j++){
        float v = t[x][y + 8*j];
        bf16 hi = __float2bfloat16(v);
        size_t o = (size_t)(db + y + 8*j)*NSLOT + nb + x;
        g_vth[o] = hi;
        g_vtl[o] = __float2bfloat16(v - __bfloat162float(hi));
    }
}

// ---------------- combine ----------------
__global__ void combine_kernel(const void* __restrict__ maskptr)
{
    int t = blockIdx.x * blockDim.x + threadIdx.x;
    if (t >= T_TOK) return;
    float best = -CUDART_INF_F; int bi = 0;
#pragma unroll
    for (int s = 0; s < 32; s++){
        float v = g_pmax[s * T_TOK + t];
        int   i = g_pidx[s * T_TOK + t];
        if (v > best){ best = v; bi = i; }
    }
    bool novel = (best * 0.0625f) < 0.5f;
    const unsigned* w = (const unsigned*)maskptr;
    bool bytemode = (w[0] == 0x01010101u);
    bool m;
    if (bytemode) m = ((const unsigned char*)maskptr)[t] != 0;
    else          m = (w[t] != 0);
    g_info[t] = (unsigned)bi | (novel ? 0x10000u : 0u) | (m ? 0x20000u : 0u);
}

// ---------------- fast scan: sorted two-queue merge ------------------------
#define SCAN_SMEM (NSLOT*8 + T_TOK*8 + T_TOK*4 + 64)
__global__ __launch_bounds__(256) void scan_fast(const float* __restrict__ act0)
{
    extern __shared__ char sm[];
    u64* sS = (u64*)sm;                           // 4096 sorted initial keys
    u64* sQ = (u64*)(sm + NSLOT*8);               // 8192 FIFO
    u32* sInfo = (u32*)(sm + NSLOT*8 + T_TOK*8);  // 8192 info
    int* sCtl = (int*)(sm + NSLOT*8 + T_TOK*8 + T_TOK*4);
    int tid = threadIdx.x;

    if (tid == 0) sCtl[0] = 0;
    __syncthreads();
    int local = 0;
    for (int t = tid; t < T_TOK; t += 256){
        u32 inf = g_info[t];
        sInfo[t] = inf;
        if ((inf & 0x30000u) == 0x20000u) local = 1;   // masked & non-novel
    }
    if (local) atomicOr(&sCtl[0], 1);
    __syncthreads();
    if (tid == 0) g_scanflag = sCtl[0];
    if (sCtl[0]){ return; }                            // slow kernel takes over

    // pack + bitonic sort ascending by (value, index)
    for (int i = tid; i < NSLOT; i += 256)
        sS[i] = ((u64)__float_as_uint(act0[i]) << 32) | (u32)i;
    __syncthreads();
    for (int k = 2; k <= NSLOT; k <<= 1){
        for (int j = k >> 1; j > 0; j >>= 1){
            for (int i = tid; i < NSLOT; i += 256){
                int ixj = i ^ j;
                if (ixj > i){
                    u64 a = sS[i], b = sS[ixj];
                    bool up = ((i & k) == 0);
                    if ((a > b) == up){ sS[i] = b; sS[ixj] = a; }
                }
            }
            __syncthreads();
        }
    }

    if (tid == 0){
        int p1 = 0, h2 = 0, t2 = 0;
        for (int t = 0; t < T_TOK; t++){
            u32 inf = sInfo[t];
            if (!(inf & 0x20000u)){ g_pick[t] = 0u; continue; }
            while (p1 < NSLOT && (u32)sS[p1] == 0xFFFFFFFFu) p1++;
            while (h2 < t2 && (u32)sQ[h2] == 0xFFFFFFFFu) h2++;
            u64 k1 = (p1 < NSLOT) ? sS[p1] : ~0ull;
            u64 k2 = (h2 < t2) ? sQ[h2] : ~0ull;
            u32 v1b = (u32)(k1 >> 32), v2b = (u32)(k2 >> 32);
            u32 slot; float v;
            if (v1b < v2b){
                slot = (u32)k1; v = __uint_as_float(v1b); p1++;
            } else {
                // candidates: whole equal-value run in Q2, plus k1 if equal value
                u64 best = (v1b == v2b) ? k1 : ~0ull;
                int bj = -1;
                for (int j = h2; j < t2 && (u32)(sQ[j] >> 32) == v2b; j++){
                    u64 kk = sQ[j];
                    if ((u32)kk != 0xFFFFFFFFu && kk < best){ best = kk; bj = j; }
                }
                slot = (u32)best; v = __uint_as_float((u32)(best >> 32));
                if (bj < 0) p1++;
                else if (bj == h2) h2++;
                else sQ[bj] |= 0xFFFFFFFFull;           // tombstone mid-run
            }
            float nv = fminf(1.0f, v + 0.1f);
            sQ[t2++] = ((u64)__float_as_uint(nv) << 32) | slot;
            g_pick[t] = slot | 0x30000u;
        }
        sCtl[1] = h2; sCtl[2] = t2;
    }
    __syncthreads();
    int h2 = sCtl[1], t2 = sCtl[2];
    for (int i = tid; i < NSLOT; i += 256) g_act[i] = act0[i];
    __syncthreads();
    for (int e = h2 + tid; e < t2; e += 256){
        u64 key = sQ[e];
        u32 idx = (u32)key;
        if (idx != 0xFFFFFFFFu) g_act[idx] = __uint_as_float((u32)(key >> 32));
    }
}

// ---------------- slow exact scan (fallback, flag-gated) -------------------
__global__ __launch_bounds__(256) void scan_kernel(const float* __restrict__ act0)
{
    if (g_scanflag == 0) return;
    __shared__ __align__(16) float s_act[NSLOT];
    __shared__ __align__(16) float s_gmin[128];
    __shared__ int s_gidx[128];
    int tid = threadIdx.x;
    for (int i = tid; i < NSLOT; i += 256) s_act[i] = act0[i];
    __syncthreads();
    int wid = tid >> 5, lane = tid & 31;
    for (int g = wid; g < 128; g += 8){
        float v = s_act[g * 32 + lane];
        unsigned mv = __reduce_min_sync(FULLM, __float_as_uint(v));
        unsigned bal = __ballot_sync(FULLM, __float_as_uint(v) == mv);
        if (lane == 0){ s_gmin[g] = __uint_as_float(mv); s_gidx[g] = g * 32 + (__ffs(bal) - 1); }
    }
    __syncthreads();

    if (wid == 0){
        unsigned myinfo = 0;
        for (int t = 0; t < T_TOK; t++){
            if ((t & 31) == 0) myinfo = __ldg(&g_info[t + lane]);
            unsigned info = __shfl_sync(FULLM, myinfo, t & 31);
            if (info & 0x20000u){
                int slot;
                if (info & 0x10000u){
                    float4 q4 = *(const float4*)&s_gmin[lane * 4];
                    float bv = q4.x; int bg = lane * 4;
                    if (q4.y < bv){ bv = q4.y; bg = lane * 4 + 1; }
                    if (q4.z < bv){ bv = q4.z; bg = lane * 4 + 2; }
                    if (q4.w < bv){ bv = q4.w; bg = lane * 4 + 3; }
                    unsigned mv = __reduce_min_sync(FULLM, __float_as_uint(bv));
                    unsigned bal = __ballot_sync(FULLM, __float_as_uint(bv) == mv);
                    int L = __ffs(bal) - 1;
                    int grp = __shfl_sync(FULLM, bg, L);
                    slot = s_gidx[grp];
                } else {
                    slot = (int)(info & 0xFFFFu);
                }
                float na = fminf(1.0f, s_act[slot] + 0.1f);
                if (lane == 0) s_act[slot] = na;
                __syncwarp();
                int g = slot >> 5;
                float v = s_act[g * 32 + lane];
                unsigned mv2 = __reduce_min_sync(FULLM, __float_as_uint(v));
                unsigned bal2 = __ballot_sync(FULLM, __float_as_uint(v) == mv2);
                if (lane == 0){
                    s_gmin[g] = __uint_as_float(mv2);
                    s_gidx[g] = g * 32 + (__ffs(bal2) - 1);
                    g_pick[t] = (unsigned)slot | (info & 0x10000u) | 0x20000u;
                }
                __syncwarp();
            } else {
                if (lane == 0) g_pick[t] = 0u;
            }
        }
    }
    __syncthreads();
    for (int i = tid; i < NSLOT; i += 256) g_act[i] = s_act[i];
}

// ---------------- rebuild ----------------
__global__ __launch_bounds__(256) void rebuild_kernel(
    const float* __restrict__ keys0, const float* __restrict__ values0)
{
    int wid = threadIdx.x >> 5, lane = threadIdx.x & 31;
    int s = blockIdx.x * 8 + wid;
    float kreg[8], vreg[8];
#pragma unroll
    for (int r = 0; r < 8; r++){
        kreg[r] = keys0[s * DIM + lane + 32 * r];
        vreg[r] = values0[s * DIM + lane + 32 * r];
    }
    for (int base = 0; base < T_TOK; base += 32){
        unsigned pk = __ldg(&g_pick[base + lane]);
        unsigned match = __ballot_sync(FULLM,
            (pk & 0x20000u) && ((pk & 0xFFFFu) == (unsigned)s));
        while (match){
            int bl = __ffs(match) - 1;
            match &= match - 1;
            unsigned pkb = __shfl_sync(FULLM, pk, bl);
            float alpha = (pkb & 0x10000u) ? 0.9f : 0.3f;
            float om = 1.0f - alpha;
            int t = base + bl;
            const float* kr = &g_k[(size_t)t * DIM];
            const float* vr = &g_v[(size_t)t * DIM];
#pragma unroll
            for (int r = 0; r < 8; r++){
                kreg[r] = om * kreg[r] + alpha * __ldg(&kr[lane + 32 * r]);
                vreg[r] = om * vreg[r] + alpha * __ldg(&vr[lane + 32 * r]);
            }
        }
    }
#pragma unroll
    for (int r = 0; r < 8; r++){
        g_kb[s * DIM + lane + 32 * r] = kreg[r];
        g_vb[s * DIM + lane + 32 * r] = vreg[r];
    }
}

__global__ void actbias_kernel()
{
    int n = blockIdx.x * blockDim.x + threadIdx.x;
    if (n >= NSLOT) return;
    float a = g_act[n];
    g_lb[n] = (a < 0.01f) ? -1e30f : logf(a);
}

// ---------------- attnB ----------------
__global__ __launch_bounds__(256) void attnB_kernel()
{
    int tid = threadIdx.x;
    int w = tid >> 5, lane = tid & 31;
    int rbase = blockIdx.x * 64 + w * 8;
#pragma unroll
    for (int rr = 0; rr < 8; rr++){
        int row = rbase + rr;
        float m = g_pmax[lane * T_TOK + row];
#pragma unroll
        for (int o = 16; o > 0; o >>= 1)
            m = fmaxf(m, __shfl_xor_sync(FULLM, m, o));
        const float* Sr = &g_S[(size_t)row * NSLOT];
        bf16* Eh = &g_Eh[(size_t)row * NSLOT];
        bf16* El = &g_El[(size_t)row * NSLOT];
        float sum = 0.f;
#pragma unroll 4
        for (int q = 0; q < 32; q++){
            int c = lane * 4 + q * 128;
            float4 v = *(const float4*)&Sr[c];
            v.x = __expf(v.x - m); v.y = __expf(v.y - m);
            v.z = __expf(v.z - m); v.w = __expf(v.w - m);
            sum += v.x + v.y + v.z + v.w;
            bf16 h0=__float2bfloat16(v.x), h1=__float2bfloat16(v.y);
            bf16 h2=__float2bfloat16(v.z), h3=__float2bfloat16(v.w);
            *(__nv_bfloat162*)&Eh[c]   = __nv_bfloat162(h0,h1);
            *(__nv_bfloat162*)&Eh[c+2] = __nv_bfloat162(h2,h3);
            *(__nv_bfloat162*)&El[c]   = __nv_bfloat162(
                __float2bfloat16(v.x-__bfloat162float(h0)), __float2bfloat16(v.y-__bfloat162float(h1)));
            *(__nv_bfloat162*)&El[c+2] = __nv_bfloat162(
                __float2bfloat16(v.z-__bfloat162float(h2)), __float2bfloat16(v.w-__bfloat162float(h3)));
        }
#pragma unroll
        for (int o = 16; o > 0; o >>= 1)
            sum += __shfl_xor_sync(FULLM, sum, o);
        if (lane == 0) g_rowsum[row] = sum;
    }
}

// --------------------------------- launch --------------------------------
extern "C" void kernel_launch(void* const* d_in, const int* in_sizes, int n_in,
                              void* d_out, int out_size)
{
    const float* x     = (const float*)d_in[0];
    const void*  wmask = d_in[1];
    const float* keys0 = (const float*)d_in[2];
    const float* vals0 = (const float*)d_in[3];
    const float* act0  = (const float*)d_in[4];
    const float* Wk    = (const float*)d_in[5];
    const float* bk    = (const float*)d_in[6];
    const float* Wv    = (const float*)d_in[7];
    const float* bv    = (const float*)d_in[8];
    const float* Wq    = (const float*)d_in[9];
    const float* bq    = (const float*)d_in[10];
    float* out = (float*)d_out;

    cudaFuncSetAttribute(mm_gemm, cudaFuncAttributeMaxDynamicSharedMemorySize, SMEMSZ);
    cudaFuncSetAttribute(scan_fast, cudaFuncAttributeMaxDynamicSharedMemorySize, SCAN_SMEM);

    split_kernel<<<256, 256>>>(x, 0, T_TOK*DIM);
    split_kernel<<<64, 256>>>(Wk, 1, DIM*DIM);
    split_kernel<<<64, 256>>>(Wv, 2, DIM*DIM);
    split_kernel<<<64, 256>>>(Wq, 3, DIM*DIM);
    split_kernel<<<256, 256>>>(keys0, 4, NSLOT*DIM);

    mm_gemm<<<dim3(64,2), 256, SMEMSZ>>>(0, bk, nullptr);
    mm_gemm<<<dim3(64,2), 256, SMEMSZ>>>(1, bv, nullptr);
    mm_gemm<<<dim3(64,2), 256, SMEMSZ>>>(2, bq, nullptr);
    mm_gemm<<<dim3(64,32), 256, SMEMSZ>>>(3, nullptr, nullptr);

    combine_kernel<<<T_TOK/256, 256>>>(wmask);
    scan_fast<<<1, 256, SCAN_SMEM>>>(act0);
    scan_kernel<<<1, 256>>>(act0);
    rebuild_kernel<<<NSLOT/8, 256>>>(keys0, vals0);
    split_kernel<<<256, 256>>>(nullptr, 5, NSLOT*DIM);
    actbias_kernel<<<NSLOT/256, 256>>>();
    tsplit_vb<<<dim3(128,8), dim3(32,8)>>>();

    mm_gemm<<<dim3(64,32), 256, SMEMSZ>>>(4, nullptr, nullptr);
    attnB_kernel<<<T_TOK/64, 256>>>();
    mm_gemm<<<dim3(64,2), 256, SMEMSZ>>>(5, nullptr, out);
}

// round 8
// speedup vs baseline: 1.2788x; 1.0583x over previous
#include <cuda_runtime.h>
#include <cuda_bf16.h>
#include <math_constants.h>

#define T_TOK 8192
#define DIM   256
#define NSLOT 4096
#define FULLM 0xffffffffu
typedef unsigned int u32;
typedef unsigned long long u64;
typedef __nv_bfloat16 bf16;

// ---------------- scratch ----------------
__device__ float g_k[T_TOK * DIM];
__device__ float g_v[T_TOK * DIM];
__device__ float g_q[T_TOK * DIM];
__device__ float g_pmax[32 * T_TOK];
__device__ int   g_pidx[32 * T_TOK];
__device__ unsigned g_info[T_TOK];
__device__ unsigned g_pick[T_TOK];
__device__ float g_act[NSLOT];
__device__ float g_lb[NSLOT];
__device__ float g_kb[NSLOT * DIM];
__device__ float g_vb[NSLOT * DIM];
__device__ float g_rowsum[T_TOK];
__device__ int   g_scanflag;
__device__ int   g_simflag;
__device__ float g_part[4 * T_TOK * DIM];
__device__ float g_S[(size_t)T_TOK * NSLOT];

__device__ bf16 g_xhi[T_TOK*DIM], g_xlo[T_TOK*DIM];
__device__ bf16 g_khi[T_TOK*DIM], g_klo[T_TOK*DIM];
__device__ bf16 g_qhi[T_TOK*DIM], g_qlo[T_TOK*DIM];
__device__ bf16 g_wkh[DIM*DIM], g_wkl[DIM*DIM];
__device__ bf16 g_wvh[DIM*DIM], g_wvl[DIM*DIM];
__device__ bf16 g_wqh[DIM*DIM], g_wql[DIM*DIM];
__device__ bf16 g_k0h[NSLOT*DIM], g_k0l[NSLOT*DIM];
__device__ bf16 g_kbh[NSLOT*DIM], g_kbl[NSLOT*DIM];
__device__ bf16 g_vth[DIM*NSLOT], g_vtl[DIM*NSLOT];
__device__ bf16 g_Eh[(size_t)T_TOK*NSLOT], g_El[(size_t)T_TOK*NSLOT];

// ---------------- helpers ----------------
__device__ __forceinline__ u32 cvta_sm(const void* p){
    u32 a; asm("{.reg .u64 t; cvta.to.shared.u64 t, %1; cvt.u32.u64 %0, t;}" : "=r"(a) : "l"(p));
    return a;
}
#define CPA(dst, src) asm volatile("cp.async.cg.shared.global [%0], [%1], 16;" :: "r"(dst), "l"(src))
#define CPCOMMIT()    asm volatile("cp.async.commit_group;" ::: "memory")
#define CPWAIT1()     asm volatile("cp.async.wait_group 1;" ::: "memory")
#define CPWAIT0()     asm volatile("cp.async.wait_group 0;" ::: "memory")
#define LDX4(r, a) asm volatile("ldmatrix.sync.aligned.m8n8.x4.shared.b16 {%0,%1,%2,%3}, [%4];" \
    : "=r"((r)[0]), "=r"((r)[1]), "=r"((r)[2]), "=r"((r)[3]) : "r"(a))
#define MMA(D, A, B0, B1) asm volatile( \
    "mma.sync.aligned.m16n8k16.row.col.f32.bf16.bf16.f32 " \
    "{%0,%1,%2,%3}, {%4,%5,%6,%7}, {%8,%9}, {%0,%1,%2,%3};" \
    : "+f"((D)[0]), "+f"((D)[1]), "+f"((D)[2]), "+f"((D)[3]) \
    : "r"((A)[0]), "r"((A)[1]), "r"((A)[2]), "r"((A)[3]), "r"(B0), "r"(B1))

#define PITCH 80
#define ABUF  10240
#define BUFSZ 40960
#define SMEMSZ 81920

// ---------------- universal mma.sync GEMM ----------------
// mode: 0 proj-k, 1 proj-v, 2 proj-q, 3 simmax(1-term+guard),
//       4 attnA, 5 attnC(split-K partials), 6 simmax exact (flag-gated)
__global__ __launch_bounds__(256, 2) void mm_gemm(int mode, const float* __restrict__ aux,
                                                  float* __restrict__ outp)
{
    if (mode == 6 && g_simflag == 0) return;
    const bool guard = (mode == 3);
    const int terms = (mode == 3) ? 1 : 3;
    if (mode == 6) mode = 3;

    extern __shared__ char smx[];
    u32 smb = cvta_sm(smx);
    int tid = threadIdx.x, lane = tid & 31, wid = tid >> 5;
    int wm = wid >> 2, wn = wid & 3;
    int m0 = blockIdx.x * 128, n0 = blockIdx.y * 128;

    const bf16 *Ah, *Al, *Bh, *Bl; size_t lda, ldb; int K;
    float* out = 0; bf16 *oh = 0, *ol = 0;
    switch (mode){
    case 0: Ah=g_xhi; Al=g_xlo; Bh=g_wkh; Bl=g_wkl; lda=ldb=DIM; K=DIM; out=g_k; oh=g_khi; ol=g_klo; break;
    case 1: Ah=g_xhi; Al=g_xlo; Bh=g_wvh; Bl=g_wvl; lda=ldb=DIM; K=DIM; out=g_v; break;
    case 2: Ah=g_xhi; Al=g_xlo; Bh=g_wqh; Bl=g_wql; lda=ldb=DIM; K=DIM; out=g_q; oh=g_qhi; ol=g_qlo; break;
    case 3: Ah=g_khi; Al=g_klo; Bh=g_k0h; Bl=g_k0l; lda=ldb=DIM; K=DIM; break;
    case 4: Ah=g_qhi; Al=g_qlo; Bh=g_kbh; Bl=g_kbl; lda=ldb=DIM; K=DIM; break;
    default: Ah=g_Eh; Al=g_El; Bh=g_vth; Bl=g_vtl; lda=ldb=NSLOT; K=NSLOT;
             out=g_part + (size_t)blockIdx.z * T_TOK * DIM; break;
    }
    int Kper = K / gridDim.z;
    size_t kbase = (size_t)blockIdx.z * Kper * 2;   // bytes
    const char* gsrc[4];
    gsrc[0] = (const char*)Ah + (size_t)m0*lda*2 + kbase;
    gsrc[1] = (const char*)Al + (size_t)m0*lda*2 + kbase;
    gsrc[2] = (const char*)Bh + (size_t)n0*ldb*2 + kbase;
    gsrc[3] = (const char*)Bl + (size_t)n0*ldb*2 + kbase;
    size_t rstA = lda*2, rstB = ldb*2;

    int a_ro = (lane & 7) + ((lane & 8) ? 8 : 0);
    int a_ko = (lane & 16) ? 8 : 0;
    int b_ro = (lane & 7) + ((lane & 16) ? 8 : 0);
    int b_ko = (lane & 8) ? 8 : 0;

    float d[4][4][4] = {};
    int nk = Kper / 32;
    {
        int row = (tid >> 2), kc = tid & 3;
#pragma unroll
        for (int arr = 0; arr < 4; arr++){
            if (terms == 1 && (arr & 1)) continue;
            size_t rs = (arr < 2) ? rstA : rstB;
            u32 db = smb + arr*ABUF;
            CPA(db + (u32)row*PITCH + kc*16, gsrc[arr] + (size_t)row*rs + kc*16);
            CPA(db + (u32)(row+64)*PITCH + kc*16, gsrc[arr] + (size_t)(row+64)*rs + kc*16);
        }
        CPCOMMIT();
    }

    for (int ck = 0; ck < nk; ck++){
        if (ck + 1 < nk){
            int row = (tid >> 2), kc = tid & 3;
            size_t koff = (size_t)(ck + 1) * 64;
            u32 db = smb + ((ck + 1) & 1) * BUFSZ;
#pragma unroll
            for (int arr = 0; arr < 4; arr++){
                if (terms == 1 && (arr & 1)) continue;
                size_t rs = (arr < 2) ? rstA : rstB;
                const char* s = gsrc[arr] + koff;
                CPA(db + arr*ABUF + (u32)row*PITCH + kc*16, s + (size_t)row*rs + kc*16);
                CPA(db + arr*ABUF + (u32)(row+64)*PITCH + kc*16, s + (size_t)(row+64)*rs + kc*16);
            }
            CPCOMMIT();
            CPWAIT1();
        } else {
            CPWAIT0();
        }
        __syncthreads();
        u32 bb = smb + (ck & 1) * BUFSZ;
#pragma unroll
        for (int ks = 0; ks < 2; ks++){
            u32 Abase = bb + (u32)(wm*64 + a_ro)*PITCH + (ks*16 + a_ko)*2;
            u32 Bbase = bb + 2*ABUF + (u32)(wn*32 + b_ro)*PITCH + (ks*16 + b_ko)*2;
            u32 bh[2][4], a[4][4];
            LDX4(bh[0], Bbase); LDX4(bh[1], Bbase + 16*PITCH);
#pragma unroll
            for (int ma = 0; ma < 4; ma++) LDX4(a[ma], Abase + ma*16*PITCH);
#pragma unroll
            for (int ma = 0; ma < 4; ma++)
#pragma unroll
                for (int na = 0; na < 4; na++)
                    MMA(d[ma][na], a[ma], bh[na>>1][(na&1)*2], bh[na>>1][(na&1)*2+1]);
            if (terms == 3){
                u32 blr[2][4];
                LDX4(blr[0], Bbase + ABUF); LDX4(blr[1], Bbase + ABUF + 16*PITCH);
#pragma unroll
                for (int ma = 0; ma < 4; ma++)
#pragma unroll
                    for (int na = 0; na < 4; na++)
                        MMA(d[ma][na], a[ma], blr[na>>1][(na&1)*2], blr[na>>1][(na&1)*2+1]);
#pragma unroll
                for (int ma = 0; ma < 4; ma++) LDX4(a[ma], Abase + ABUF + ma*16*PITCH);
#pragma unroll
                for (int ma = 0; ma < 4; ma++)
#pragma unroll
                    for (int na = 0; na < 4; na++)
                        MMA(d[ma][na], a[ma], bh[na>>1][(na&1)*2], bh[na>>1][(na&1)*2+1]);
            }
        }
        __syncthreads();
    }

    float* redv = (float*)smx;
    int*   redi = (int*)(smx + 2048);
    int qr = lane >> 2, qc = lane & 3;

    if (mode <= 2){
#pragma unroll
        for (int ma = 0; ma < 4; ma++)
#pragma unroll
            for (int rs = 0; rs < 2; rs++){
                int row = m0 + wm*64 + ma*16 + rs*8 + qr;
#pragma unroll
                for (int na = 0; na < 4; na++){
                    int cg = n0 + wn*32 + na*8 + 2*qc;
                    float v0 = d[ma][na][rs*2]   + aux[cg];
                    float v1 = d[ma][na][rs*2+1] + aux[cg+1];
                    *(float2*)&out[(size_t)row*DIM + cg] = make_float2(v0, v1);
                    if (oh){
                        bf16 h0 = __float2bfloat16(v0), h1 = __float2bfloat16(v1);
                        *(__nv_bfloat162*)&oh[(size_t)row*DIM+cg] = __nv_bfloat162(h0, h1);
                        *(__nv_bfloat162*)&ol[(size_t)row*DIM+cg] = __nv_bfloat162(
                            __float2bfloat16(v0 - __bfloat162float(h0)),
                            __float2bfloat16(v1 - __bfloat162float(h1)));
                    }
                }
            }
    } else if (mode == 3){
#pragma unroll
        for (int ma = 0; ma < 4; ma++)
#pragma unroll
            for (int rs = 0; rs < 2; rs++){
                int lrow = wm*64 + ma*16 + rs*8 + qr;
                float bv = -CUDART_INF_F; int bi = 0x7fffffff;
#pragma unroll
                for (int na = 0; na < 4; na++)
#pragma unroll
                    for (int e = 0; e < 2; e++){
                        float v = d[ma][na][rs*2+e];
                        int col = n0 + wn*32 + na*8 + 2*qc + e;
                        if (v > bv){ bv = v; bi = col; }
                    }
#pragma unroll
                for (int o = 1; o < 4; o <<= 1){
                    float ov = __shfl_xor_sync(FULLM, bv, o);
                    int   oi = __shfl_xor_sync(FULLM, bi, o);
                    if (ov > bv || (ov == bv && oi < bi)){ bv = ov; bi = oi; }
                }
                if (qc == 0){ redv[wn*128 + lrow] = bv; redi[wn*128 + lrow] = bi; }
            }
        __syncthreads();
        if (tid < 128){
            float bv = -CUDART_INF_F; int bi = 0x7fffffff;
#pragma unroll
            for (int w = 0; w < 4; w++){
                float v = redv[w*128 + tid]; int i = redi[w*128 + tid];
                if (v > bv || (v == bv && i < bi)){ bv = v; bi = i; }
            }
            g_pmax[blockIdx.y * T_TOK + m0 + tid] = bv;
            g_pidx[blockIdx.y * T_TOK + m0 + tid] = bi;
            if (guard && bv >= 7.4f) atomicOr(&g_simflag, 1);  // unscaled 0.4625
        }
    } else if (mode == 4){
#pragma unroll
        for (int ma = 0; ma < 4; ma++)
#pragma unroll
            for (int rs = 0; rs < 2; rs++){
                int row = m0 + wm*64 + ma*16 + rs*8 + qr;
                float bv = -CUDART_INF_F;
#pragma unroll
                for (int na = 0; na < 4; na++){
                    int cg = n0 + wn*32 + na*8 + 2*qc;
                    float v0 = d[ma][na][rs*2]  *0.0625f + g_lb[cg];
                    float v1 = d[ma][na][rs*2+1]*0.0625f + g_lb[cg+1];
                    *(float2*)&g_S[(size_t)row*NSLOT + cg] = make_float2(v0, v1);
                    bv = fmaxf(bv, fmaxf(v0, v1));
                }
#pragma unroll
                for (int o = 1; o < 4; o <<= 1)
                    bv = fmaxf(bv, __shfl_xor_sync(FULLM, bv, o));
                if (qc == 0) redv[wn*128 + (row - m0)] = bv;
            }
        __syncthreads();
        if (tid < 128){
            float bv = -CUDART_INF_F;
#pragma unroll
            for (int w = 0; w < 4; w++) bv = fmaxf(bv, redv[w*128 + tid]);
            g_pmax[blockIdx.y * T_TOK + m0 + tid] = bv;
        }
    } else {
#pragma unroll
        for (int ma = 0; ma < 4; ma++)
#pragma unroll
            for (int rs = 0; rs < 2; rs++){
                int row = m0 + wm*64 + ma*16 + rs*8 + qr;
#pragma unroll
                for (int na = 0; na < 4; na++){
                    int cg = n0 + wn*32 + na*8 + 2*qc;
                    *(float2*)&out[(size_t)row*DIM + cg] =
                        make_float2(d[ma][na][rs*2], d[ma][na][rs*2+1]);
                }
            }
    }
}

// ---------------- attnC reduce: out = (sum of 4 partials) / rowsum ---------
__global__ void attnC_red(float* __restrict__ out)
{
    int i = blockIdx.x * blockDim.x + threadIdx.x;   // float4 index
    int row = i >> 6;
    float inv = 1.0f / g_rowsum[row];
    float4 s = *(float4*)&g_part[(size_t)i*4];
    float4 b = *(float4*)&g_part[(size_t)T_TOK*DIM + i*4];
    float4 c = *(float4*)&g_part[(size_t)2*T_TOK*DIM + i*4];
    float4 e = *(float4*)&g_part[(size_t)3*T_TOK*DIM + i*4];
    s.x = (s.x+b.x+c.x+e.x)*inv; s.y = (s.y+b.y+c.y+e.y)*inv;
    s.z = (s.z+b.z+c.z+e.z)*inv; s.w = (s.w+b.w+c.w+e.w)*inv;
    *(float4*)&out[(size_t)i*4] = s;
}

// ---------------- splits ----------------
__device__ __forceinline__ void split_range(const float* src, bf16* h, bf16* l, int n, int tid, int nth)
{
    for (int i = tid; i < n; i += nth){
        float v = src[i];
        bf16 hi = __float2bfloat16(v);
        h[i] = hi;
        l[i] = __float2bfloat16(v - __bfloat162float(hi));
    }
}
__global__ void splitA_kernel(const float* __restrict__ x, const float* __restrict__ Wk,
                              const float* __restrict__ Wv, const float* __restrict__ Wq)
{
    int tid = blockIdx.x * blockDim.x + threadIdx.x;
    if (tid == 0) g_simflag = 0;
    int nth = gridDim.x * blockDim.x;
    split_range(x, g_xhi, g_xlo, T_TOK*DIM, tid, nth);
    split_range(Wk, g_wkh, g_wkl, DIM*DIM, tid, nth);
    split_range(Wv, g_wvh, g_wvl, DIM*DIM, tid, nth);
    split_range(Wq, g_wqh, g_wql, DIM*DIM, tid, nth);
}
__global__ void splitB_kernel(const float* __restrict__ keys0)
{
    int tid = blockIdx.x * blockDim.x + threadIdx.x;
    split_range(keys0, g_k0h, g_k0l, NSLOT*DIM, tid, gridDim.x * blockDim.x);
}
__global__ void splitKB_kernel()
{
    int tid = blockIdx.x * blockDim.x + threadIdx.x;
    split_range(g_kb, g_kbh, g_kbl, NSLOT*DIM, tid, gridDim.x * blockDim.x);
}

__global__ void tsplit_vb()
{
    __shared__ float t[32][33];
    int x = threadIdx.x, y = threadIdx.y;
    int nb = blockIdx.x * 32, db = blockIdx.y * 32;
#pragma unroll
    for (int j = 0; j < 4; j++)
        t[y + 8*j][x] = g_vb[(size_t)(nb + y + 8*j)*DIM + db + x];
    __syncthreads();
#pragma unroll
    for (int j = 0; j < 4; j++){
        float v = t[x][y + 8*j];
        bf16 hi = __float2bfloat16(v);
        size_t o = (size_t)(db + y + 8*j)*NSLOT + nb + x;
        g_vth[o] = hi;
        g_vtl[o] = __float2bfloat16(v - __bfloat162float(hi));
    }
}

// ---------------- combine ----------------
__global__ void combine_kernel(const void* __restrict__ maskptr)
{
    int t = blockIdx.x * blockDim.x + threadIdx.x;
    if (t >= T_TOK) return;
    float best = -CUDART_INF_F; int bi = 0;
#pragma unroll
    for (int s = 0; s < 32; s++){
        float v = g_pmax[s * T_TOK + t];
        int   i = g_pidx[s * T_TOK + t];
        if (v > best){ best = v; bi = i; }
    }
    bool novel = (best * 0.0625f) < 0.5f;
    const unsigned* w = (const unsigned*)maskptr;
    bool bytemode = (w[0] == 0x01010101u);
    bool m;
    if (bytemode) m = ((const unsigned char*)maskptr)[t] != 0;
    else          m = (w[t] != 0);
    g_info[t] = (unsigned)bi | (novel ? 0x10000u : 0u) | (m ? 0x20000u : 0u);
}

// ---------------- fast scan: sorted two-queue merge ------------------------
#define SCAN_SMEM (NSLOT*8 + T_TOK*8 + T_TOK*4 + 64)
__global__ __launch_bounds__(256) void scan_fast(const float* __restrict__ act0)
{
    extern __shared__ char sm[];
    u64* sS = (u64*)sm;
    u64* sQ = (u64*)(sm + NSLOT*8);
    u32* sInfo = (u32*)(sm + NSLOT*8 + T_TOK*8);
    int* sCtl = (int*)(sm + NSLOT*8 + T_TOK*8 + T_TOK*4);
    int tid = threadIdx.x;

    if (tid == 0) sCtl[0] = 0;
    __syncthreads();
    int local = 0;
    for (int t = tid; t < T_TOK; t += 256){
        u32 inf = g_info[t];
        sInfo[t] = inf;
        if ((inf & 0x30000u) == 0x20000u) local = 1;
    }
    if (local) atomicOr(&sCtl[0], 1);
    __syncthreads();
    if (tid == 0) g_scanflag = sCtl[0];
    if (sCtl[0]){ return; }

    for (int i = tid; i < NSLOT; i += 256)
        sS[i] = ((u64)__float_as_uint(act0[i]) << 32) | (u32)i;
    __syncthreads();
    for (int k = 2; k <= NSLOT; k <<= 1){
        for (int j = k >> 1; j > 0; j >>= 1){
            for (int i = tid; i < NSLOT; i += 256){
                int ixj = i ^ j;
                if (ixj > i){
                    u64 a = sS[i], b = sS[ixj];
                    bool up = ((i & k) == 0);
                    if ((a > b) == up){ sS[i] = b; sS[ixj] = a; }
                }
            }
            __syncthreads();
        }
    }

    if (tid == 0){
        int p1 = 0, h2 = 0, t2 = 0;
        for (int t = 0; t < T_TOK; t++){
            u32 inf = sInfo[t];
            if (!(inf & 0x20000u)){ g_pick[t] = 0u; continue; }
            while (p1 < NSLOT && (u32)sS[p1] == 0xFFFFFFFFu) p1++;
            while (h2 < t2 && (u32)sQ[h2] == 0xFFFFFFFFu) h2++;
            u64 k1 = (p1 < NSLOT) ? sS[p1] : ~0ull;
            u64 k2 = (h2 < t2) ? sQ[h2] : ~0ull;
            u32 v1b = (u32)(k1 >> 32), v2b = (u32)(k2 >> 32);
            u32 slot; float v;
            if (v1b < v2b){
                slot = (u32)k1; v = __uint_as_float(v1b); p1++;
            } else {
                u64 best = (v1b == v2b) ? k1 : ~0ull;
                int bj = -1;
                for (int j = h2; j < t2 && (u32)(sQ[j] >> 32) == v2b; j++){
                    u64 kk = sQ[j];
                    if ((u32)kk != 0xFFFFFFFFu && kk < best){ best = kk; bj = j; }
                }
                slot = (u32)best; v = __uint_as_float((u32)(best >> 32));
                if (bj < 0) p1++;
                else if (bj == h2) h2++;
                else sQ[bj] |= 0xFFFFFFFFull;
            }
            float nv = fminf(1.0f, v + 0.1f);
            sQ[t2++] = ((u64)__float_as_uint(nv) << 32) | slot;
            g_pick[t] = slot | 0x30000u;
        }
        sCtl[1] = h2; sCtl[2] = t2;
    }
    __syncthreads();
    int h2 = sCtl[1], t2 = sCtl[2];
    for (int i = tid; i < NSLOT; i += 256) g_act[i] = act0[i];
    __syncthreads();
    for (int e = h2 + tid; e < t2; e += 256){
        u64 key = sQ[e];
        u32 idx = (u32)key;
        if (idx != 0xFFFFFFFFu) g_act[idx] = __uint_as_float((u32)(key >> 32));
    }
}

// ---------------- slow exact scan (fallback) -------------------------------
__global__ __launch_bounds__(256) void scan_kernel(const float* __restrict__ act0)
{
    if (g_scanflag == 0) return;
    __shared__ __align__(16) float s_act[NSLOT];
    __shared__ __align__(16) float s_gmin[128];
    __shared__ int s_gidx[128];
    int tid = threadIdx.x;
    for (int i = tid; i < NSLOT; i += 256) s_act[i] = act0[i];
    __syncthreads();
    int wid = tid >> 5, lane = tid & 31;
    for (int g = wid; g < 128; g += 8){
        float v = s_act[g * 32 + lane];
        unsigned mv = __reduce_min_sync(FULLM, __float_as_uint(v));
        unsigned bal = __ballot_sync(FULLM, __float_as_uint(v) == mv);
        if (lane == 0){ s_gmin[g] = __uint_as_float(mv); s_gidx[g] = g * 32 + (__ffs(bal) - 1); }
    }
    __syncthreads();

    if (wid == 0){
        unsigned myinfo = 0;
        for (int t = 0; t < T_TOK; t++){
            if ((t & 31) == 0) myinfo = __ldg(&g_info[t + lane]);
            unsigned info = __shfl_sync(FULLM, myinfo, t & 31);
            if (info & 0x20000u){
                int slot;
                if (info & 0x10000u){
                    float4 q4 = *(const float4*)&s_gmin[lane * 4];
                    float bv = q4.x; int bg = lane * 4;
                    if (q4.y < bv){ bv = q4.y; bg = lane * 4 + 1; }
                    if (q4.z < bv){ bv = q4.z; bg = lane * 4 + 2; }
                    if (q4.w < bv){ bv = q4.w; bg = lane * 4 + 3; }
                    unsigned mv = __reduce_min_sync(FULLM, __float_as_uint(bv));
                    unsigned bal = __ballot_sync(FULLM, __float_as_uint(bv) == mv);
                    int L = __ffs(bal) - 1;
                    int grp = __shfl_sync(FULLM, bg, L);
                    slot = s_gidx[grp];
                } else {
                    slot = (int)(info & 0xFFFFu);
                }
                float na = fminf(1.0f, s_act[slot] + 0.1f);
                if (lane == 0) s_act[slot] = na;
                __syncwarp();
                int g = slot >> 5;
                float v = s_act[g * 32 + lane];
                unsigned mv2 = __reduce_min_sync(FULLM, __float_as_uint(v));
                unsigned bal2 = __ballot_sync(FULLM, __float_as_uint(v) == mv2);
                if (lane == 0){
                    s_gmin[g] = __uint_as_float(mv2);
                    s_gidx[g] = g * 32 + (__ffs(bal2) - 1);
                    g_pick[t] = (unsigned)slot | (info & 0x10000u) | 0x20000u;
                }
                __syncwarp();
            } else {
                if (lane == 0) g_pick[t] = 0u;
            }
        }
    }
    __syncthreads();
    for (int i = tid; i < NSLOT; i += 256) g_act[i] = s_act[i];
}

// ---------------- rebuild ----------------
__global__ __launch_bounds__(256) void rebuild_kernel(
    const float* __restrict__ keys0, const float* __restrict__ values0)
{
    int wid = threadIdx.x >> 5, lane = threadIdx.x & 31;
    int s = blockIdx.x * 8 + wid;
    float kreg[8], vreg[8];
#pragma unroll
    for (int r = 0; r < 8; r++){
        kreg[r] = keys0[s * DIM + lane + 32 * r];
        vreg[r] = values0[s * DIM + lane + 32 * r];
    }
    for (int base = 0; base < T_TOK; base += 32){
        unsigned pk = __ldg(&g_pick[base + lane]);
        unsigned match = __ballot_sync(FULLM,
            (pk & 0x20000u) && ((pk & 0xFFFFu) == (unsigned)s));
        while (match){
            int bl = __ffs(match) - 1;
            match &= match - 1;
            unsigned pkb = __shfl_sync(FULLM, pk, bl);
            float alpha = (pkb & 0x10000u) ? 0.9f : 0.3f;
            float om = 1.0f - alpha;
            int t = base + bl;
            const float* kr = &g_k[(size_t)t * DIM];
            const float* vr = &g_v[(size_t)t * DIM];
#pragma unroll
            for (int r = 0; r < 8; r++){
                kreg[r] = om * kreg[r] + alpha * __ldg(&kr[lane + 32 * r]);
                vreg[r] = om * vreg[r] + alpha * __ldg(&vr[lane + 32 * r]);
            }
        }
    }
#pragma unroll
    for (int r = 0; r < 8; r++){
        g_kb[s * DIM + lane + 32 * r] = kreg[r];
        g_vb[s * DIM + lane + 32 * r] = vreg[r];
    }
}

__global__ void actbias_kernel()
{
    int n = blockIdx.x * blockDim.x + threadIdx.x;
    if (n >= NSLOT) return;
    float a = g_act[n];
    g_lb[n] = (a < 0.01f) ? -1e30f : logf(a);
}

// ---------------- attnB ----------------
__global__ __launch_bounds__(256) void attnB_kernel()
{
    int tid = threadIdx.x;
    int w = tid >> 5, lane = tid & 31;
    int rbase = blockIdx.x * 64 + w * 8;
#pragma unroll
    for (int rr = 0; rr < 8; rr++){
        int row = rbase + rr;
        float m = g_pmax[lane * T_TOK + row];
#pragma unroll
        for (int o = 16; o > 0; o >>= 1)
            m = fmaxf(m, __shfl_xor_sync(FULLM, m, o));
        const float* Sr = &g_S[(size_t)row * NSLOT];
        bf16* Eh = &g_Eh[(size_t)row * NSLOT];
        bf16* El = &g_El[(size_t)row * NSLOT];
        float sum = 0.f;
#pragma unroll 4
        for (int q = 0; q < 32; q++){
            int c = lane * 4 + q * 128;
            float4 v = *(const float4*)&Sr[c];
            v.x = __expf(v.x - m); v.y = __expf(v.y - m);
            v.z = __expf(v.z - m); v.w = __expf(v.w - m);
            sum += v.x + v.y + v.z + v.w;
            bf16 h0=__float2bfloat16(v.x), h1=__float2bfloat16(v.y);
            bf16 h2=__float2bfloat16(v.z), h3=__float2bfloat16(v.w);
            *(__nv_bfloat162*)&Eh[c]   = __nv_bfloat162(h0,h1);
            *(__nv_bfloat162*)&Eh[c+2] = __nv_bfloat162(h2,h3);
            *(__nv_bfloat162*)&El[c]   = __nv_bfloat162(
                __float2bfloat16(v.x-__bfloat162float(h0)), __float2bfloat16(v.y-__bfloat162float(h1)));
            *(__nv_bfloat162*)&El[c+2] = __nv_bfloat162(
                __float2bfloat16(v.z-__bfloat162float(h2)), __float2bfloat16(v.w-__bfloat162float(h3)));
        }
#pragma unroll
        for (int o = 16; o > 0; o >>= 1)
            sum += __shfl_xor_sync(FULLM, sum, o);
        if (lane == 0) g_rowsum[row] = sum;
    }
}

// --------------------------------- launch --------------------------------
extern "C" void kernel_launch(void* const* d_in, const int* in_sizes, int n_in,
                              void* d_out, int out_size)
{
    const float* x     = (const float*)d_in[0];
    const void*  wmask = d_in[1];
    const float* keys0 = (const float*)d_in[2];
    const float* vals0 = (const float*)d_in[3];
    const float* act0  = (const float*)d_in[4];
    const float* Wk    = (const float*)d_in[5];
    const float* bk    = (const float*)d_in[6];
    const float* Wv    = (const float*)d_in[7];
    const float* bv    = (const float*)d_in[8];
    const float* Wq    = (const float*)d_in[9];
    const float* bq    = (const float*)d_in[10];
    float* out = (float*)d_out;

    cudaFuncSetAttribute(mm_gemm, cudaFuncAttributeMaxDynamicSharedMemorySize, SMEMSZ);
    cudaFuncSetAttribute(scan_fast, cudaFuncAttributeMaxDynamicSharedMemorySize, SCAN_SMEM);

    splitA_kernel<<<256, 256>>>(x, Wk, Wv, Wq);
    splitB_kernel<<<256, 256>>>(keys0);

    mm_gemm<<<dim3(64,2), 256, SMEMSZ>>>(0, bk, nullptr);
    mm_gemm<<<dim3(64,2), 256, SMEMSZ>>>(1, bv, nullptr);
    mm_gemm<<<dim3(64,2), 256, SMEMSZ>>>(2, bq, nullptr);
    mm_gemm<<<dim3(64,32), 256, SMEMSZ>>>(3, nullptr, nullptr);   // 1-term + guard
    mm_gemm<<<dim3(64,32), 256, SMEMSZ>>>(6, nullptr, nullptr);   // exact, flag-gated

    combine_kernel<<<T_TOK/256, 256>>>(wmask);
    scan_fast<<<1, 256, SCAN_SMEM>>>(act0);
    scan_kernel<<<1, 256>>>(act0);
    rebuild_kernel<<<NSLOT/8, 256>>>(keys0, vals0);
    splitKB_kernel<<<256, 256>>>();
    actbias_kernel<<<NSLOT/256, 256>>>();
    tsplit_vb<<<dim3(128,8), dim3(32,8)>>>();

    mm_gemm<<<dim3(64,32), 256, SMEMSZ>>>(4, nullptr, nullptr);
    attnB_kernel<<<T_TOK/64, 256>>>();
    mm_gemm<<<dim3(64,2,4), 256, SMEMSZ>>>(5, nullptr, nullptr);  // split-K partials
    attnC_red<<<T_TOK*DIM/1024, 256>>>(out);
}

// round 9
// speedup vs baseline: 1.3506x; 1.0561x over previous
#include <cuda_runtime.h>
#include <cuda_bf16.h>
#include <math_constants.h>

#define T_TOK 8192
#define DIM   256
#define NSLOT 4096
#define FULLM 0xffffffffu
typedef unsigned int u32;
typedef unsigned long long u64;
typedef __nv_bfloat16 bf16;

// ---------------- scratch ----------------
__device__ float g_k[T_TOK * DIM];
__device__ float g_v[T_TOK * DIM];
__device__ float g_q[T_TOK * DIM];
__device__ float g_pmax[32 * T_TOK];
__device__ int   g_pidx[32 * T_TOK];
__device__ unsigned g_info[T_TOK];
__device__ unsigned g_pick[T_TOK];
__device__ float g_act[NSLOT];
__device__ float g_lb[NSLOT];
__device__ float g_bias[3 * DIM];
__device__ float g_kb[NSLOT * DIM];
__device__ float g_vb[NSLOT * DIM];
__device__ float g_rowsum[T_TOK];
__device__ int   g_scanflag;
__device__ int   g_simflag;
__device__ float g_part[4 * T_TOK * DIM];

__device__ bf16 g_xhi[T_TOK*DIM], g_xlo[T_TOK*DIM];
__device__ bf16 g_khi[T_TOK*DIM], g_klo[T_TOK*DIM];
__device__ bf16 g_qhi[T_TOK*DIM], g_qlo[T_TOK*DIM];
__device__ bf16 g_wkh[DIM*DIM], g_wkl[DIM*DIM];
__device__ bf16 g_wvh[DIM*DIM], g_wvl[DIM*DIM];
__device__ bf16 g_wqh[DIM*DIM], g_wql[DIM*DIM];
__device__ bf16 g_k0h[NSLOT*DIM], g_k0l[NSLOT*DIM];
__device__ bf16 g_kbh[NSLOT*DIM], g_kbl[NSLOT*DIM];
__device__ bf16 g_vth[DIM*NSLOT], g_vtl[DIM*NSLOT];
__device__ bf16 g_Eh[(size_t)T_TOK*NSLOT], g_El[(size_t)T_TOK*NSLOT];

// ---------------- helpers ----------------
__device__ __forceinline__ u32 cvta_sm(const void* p){
    u32 a; asm("{.reg .u64 t; cvta.to.shared.u64 t, %1; cvt.u32.u64 %0, t;}" : "=r"(a) : "l"(p));
    return a;
}
#define CPA(dst, src) asm volatile("cp.async.cg.shared.global [%0], [%1], 16;" :: "r"(dst), "l"(src))
#define CPCOMMIT()    asm volatile("cp.async.commit_group;" ::: "memory")
#define CPWAIT1()     asm volatile("cp.async.wait_group 1;" ::: "memory")
#define CPWAIT0()     asm volatile("cp.async.wait_group 0;" ::: "memory")
#define LDX4(r, a) asm volatile("ldmatrix.sync.aligned.m8n8.x4.shared.b16 {%0,%1,%2,%3}, [%4];" \
    : "=r"((r)[0]), "=r"((r)[1]), "=r"((r)[2]), "=r"((r)[3]) : "r"(a))
#define MMA(D, A, B0, B1) asm volatile( \
    "mma.sync.aligned.m16n8k16.row.col.f32.bf16.bf16.f32 " \
    "{%0,%1,%2,%3}, {%4,%5,%6,%7}, {%8,%9}, {%0,%1,%2,%3};" \
    : "+f"((D)[0]), "+f"((D)[1]), "+f"((D)[2]), "+f"((D)[3]) \
    : "r"((A)[0]), "r"((A)[1]), "r"((A)[2]), "r"((A)[3]), "r"(B0), "r"(B1))

#define PITCH 80
#define ABUF  10240
#define BUFSZ 40960
#define SMEMSZ 81920
#define SHIFTC 1.0f

// ---------------- universal mma.sync GEMM ----------------
// mode: 0 fused proj (blockIdx.z = k/v/q), 3 simmax(1-term+guard),
//       4 attnA (exp epilogue, shift-invariant softmax), 5 attnC splitK,
//       6 simmax exact (flag-gated)
__global__ __launch_bounds__(256, 2) void mm_gemm(int mode)
{
    if (mode == 6 && g_simflag == 0) return;
    const bool guard = (mode == 3);
    const int terms = (mode == 3) ? 1 : 3;
    if (mode == 6) mode = 3;

    extern __shared__ char smx[];
    u32 smb = cvta_sm(smx);
    int tid = threadIdx.x, lane = tid & 31, wid = tid >> 5;
    int wm = wid >> 2, wn = wid & 3;
    int m0 = blockIdx.x * 128, n0 = blockIdx.y * 128;
    int bz = blockIdx.z;

    const bf16 *Ah, *Al, *Bh, *Bl; size_t lda, ldb; int K;
    float* out = 0; bf16 *oh = 0, *ol = 0;
    switch (mode){
    case 0:
        Ah = g_xhi; Al = g_xlo; lda = ldb = DIM; K = DIM;
        if (bz == 0){ Bh=g_wkh; Bl=g_wkl; out=g_k; oh=g_khi; ol=g_klo; }
        else if (bz == 1){ Bh=g_wvh; Bl=g_wvl; out=g_v; }
        else { Bh=g_wqh; Bl=g_wql; out=g_q; oh=g_qhi; ol=g_qlo; }
        break;
    case 3: Ah=g_khi; Al=g_klo; Bh=g_k0h; Bl=g_k0l; lda=ldb=DIM; K=DIM; break;
    case 4: Ah=g_qhi; Al=g_qlo; Bh=g_kbh; Bl=g_kbl; lda=ldb=DIM; K=DIM; break;
    default: Ah=g_Eh; Al=g_El; Bh=g_vth; Bl=g_vtl; lda=ldb=NSLOT; K=NSLOT;
             out=g_part + (size_t)bz * T_TOK * DIM; break;
    }
    int Kper = (mode == 5) ? K / gridDim.z : K;
    size_t kbase = (mode == 5) ? (size_t)bz * Kper * 2 : 0;
    const char* gsrc[4];
    gsrc[0] = (const char*)Ah + (size_t)m0*lda*2 + kbase;
    gsrc[1] = (const char*)Al + (size_t)m0*lda*2 + kbase;
    gsrc[2] = (const char*)Bh + (size_t)n0*ldb*2 + kbase;
    gsrc[3] = (const char*)Bl + (size_t)n0*ldb*2 + kbase;
    size_t rstA = lda*2, rstB = ldb*2;

    int a_ro = (lane & 7) + ((lane & 8) ? 8 : 0);
    int a_ko = (lane & 16) ? 8 : 0;
    int b_ro = (lane & 7) + ((lane & 16) ? 8 : 0);
    int b_ko = (lane & 8) ? 8 : 0;

    float d[4][4][4] = {};
    int nk = Kper / 32;
    {
        int row = (tid >> 2), kc = tid & 3;
#pragma unroll
        for (int arr = 0; arr < 4; arr++){
            if (terms == 1 && (arr & 1)) continue;
            size_t rs = (arr < 2) ? rstA : rstB;
            u32 db = smb + arr*ABUF;
            CPA(db + (u32)row*PITCH + kc*16, gsrc[arr] + (size_t)row*rs + kc*16);
            CPA(db + (u32)(row+64)*PITCH + kc*16, gsrc[arr] + (size_t)(row+64)*rs + kc*16);
        }
        CPCOMMIT();
    }

    for (int ck = 0; ck < nk; ck++){
        if (ck + 1 < nk){
            int row = (tid >> 2), kc = tid & 3;
            size_t koff = (size_t)(ck + 1) * 64;
            u32 db = smb + ((ck + 1) & 1) * BUFSZ;
#pragma unroll
            for (int arr = 0; arr < 4; arr++){
                if (terms == 1 && (arr & 1)) continue;
                size_t rs = (arr < 2) ? rstA : rstB;
                const char* s = gsrc[arr] + koff;
                CPA(db + arr*ABUF + (u32)row*PITCH + kc*16, s + (size_t)row*rs + kc*16);
                CPA(db + arr*ABUF + (u32)(row+64)*PITCH + kc*16, s + (size_t)(row+64)*rs + kc*16);
            }
            CPCOMMIT();
            CPWAIT1();
        } else {
            CPWAIT0();
        }
        __syncthreads();
        u32 bb = smb + (ck & 1) * BUFSZ;
#pragma unroll
        for (int ks = 0; ks < 2; ks++){
            u32 Abase = bb + (u32)(wm*64 + a_ro)*PITCH + (ks*16 + a_ko)*2;
            u32 Bbase = bb + 2*ABUF + (u32)(wn*32 + b_ro)*PITCH + (ks*16 + b_ko)*2;
            u32 bh[2][4], a[4][4];
            LDX4(bh[0], Bbase); LDX4(bh[1], Bbase + 16*PITCH);
#pragma unroll
            for (int ma = 0; ma < 4; ma++) LDX4(a[ma], Abase + ma*16*PITCH);
#pragma unroll
            for (int ma = 0; ma < 4; ma++)
#pragma unroll
                for (int na = 0; na < 4; na++)
                    MMA(d[ma][na], a[ma], bh[na>>1][(na&1)*2], bh[na>>1][(na&1)*2+1]);
            if (terms == 3){
                u32 blr[2][4];
                LDX4(blr[0], Bbase + ABUF); LDX4(blr[1], Bbase + ABUF + 16*PITCH);
#pragma unroll
                for (int ma = 0; ma < 4; ma++)
#pragma unroll
                    for (int na = 0; na < 4; na++)
                        MMA(d[ma][na], a[ma], blr[na>>1][(na&1)*2], blr[na>>1][(na&1)*2+1]);
#pragma unroll
                for (int ma = 0; ma < 4; ma++) LDX4(a[ma], Abase + ABUF + ma*16*PITCH);
#pragma unroll
                for (int ma = 0; ma < 4; ma++)
#pragma unroll
                    for (int na = 0; na < 4; na++)
                        MMA(d[ma][na], a[ma], bh[na>>1][(na&1)*2], bh[na>>1][(na&1)*2+1]);
            }
        }
        __syncthreads();
    }

    float* redv = (float*)smx;
    int*   redi = (int*)(smx + 2048);
    int qr = lane >> 2, qc = lane & 3;

    if (mode == 0){
        const float* bias = g_bias + bz * DIM;
#pragma unroll
        for (int ma = 0; ma < 4; ma++)
#pragma unroll
            for (int rs = 0; rs < 2; rs++){
                int row = m0 + wm*64 + ma*16 + rs*8 + qr;
#pragma unroll
                for (int na = 0; na < 4; na++){
                    int cg = n0 + wn*32 + na*8 + 2*qc;
                    float v0 = d[ma][na][rs*2]   + bias[cg];
                    float v1 = d[ma][na][rs*2+1] + bias[cg+1];
                    *(float2*)&out[(size_t)row*DIM + cg] = make_float2(v0, v1);
                    if (oh){
                        bf16 h0 = __float2bfloat16(v0), h1 = __float2bfloat16(v1);
                        *(__nv_bfloat162*)&oh[(size_t)row*DIM+cg] = __nv_bfloat162(h0, h1);
                        *(__nv_bfloat162*)&ol[(size_t)row*DIM+cg] = __nv_bfloat162(
                            __float2bfloat16(v0 - __bfloat162float(h0)),
                            __float2bfloat16(v1 - __bfloat162float(h1)));
                    }
                }
            }
    } else if (mode == 3){
#pragma unroll
        for (int ma = 0; ma < 4; ma++)
#pragma unroll
            for (int rs = 0; rs < 2; rs++){
                int lrow = wm*64 + ma*16 + rs*8 + qr;
                float bv = -CUDART_INF_F; int bi = 0x7fffffff;
#pragma unroll
                for (int na = 0; na < 4; na++)
#pragma unroll
                    for (int e = 0; e < 2; e++){
                        float v = d[ma][na][rs*2+e];
                        int col = n0 + wn*32 + na*8 + 2*qc + e;
                        if (v > bv){ bv = v; bi = col; }
                    }
#pragma unroll
                for (int o = 1; o < 4; o <<= 1){
                    float ov = __shfl_xor_sync(FULLM, bv, o);
                    int   oi = __shfl_xor_sync(FULLM, bi, o);
                    if (ov > bv || (ov == bv && oi < bi)){ bv = ov; bi = oi; }
                }
                if (qc == 0){ redv[wn*128 + lrow] = bv; redi[wn*128 + lrow] = bi; }
            }
        __syncthreads();
        if (tid < 128){
            float bv = -CUDART_INF_F; int bi = 0x7fffffff;
#pragma unroll
            for (int w = 0; w < 4; w++){
                float v = redv[w*128 + tid]; int i = redi[w*128 + tid];
                if (v > bv || (v == bv && i < bi)){ bv = v; bi = i; }
            }
            g_pmax[blockIdx.y * T_TOK + m0 + tid] = bv;
            g_pidx[blockIdx.y * T_TOK + m0 + tid] = bi;
            if (guard && bv >= 7.4f) atomicOr(&g_simflag, 1);
        }
    } else if (mode == 4){
        // shift-invariant softmax: E = exp(logit - SHIFTC), bf16 split + rowsum
#pragma unroll
        for (int ma = 0; ma < 4; ma++)
#pragma unroll
            for (int rs = 0; rs < 2; rs++){
                int row = m0 + wm*64 + ma*16 + rs*8 + qr;
                float rsum = 0.f;
#pragma unroll
                for (int na = 0; na < 4; na++){
                    int cg = n0 + wn*32 + na*8 + 2*qc;
                    float e0 = __expf(d[ma][na][rs*2]  *0.0625f + g_lb[cg]   - SHIFTC);
                    float e1 = __expf(d[ma][na][rs*2+1]*0.0625f + g_lb[cg+1] - SHIFTC);
                    rsum += e0 + e1;
                    bf16 h0 = __float2bfloat16(e0), h1 = __float2bfloat16(e1);
                    size_t o = (size_t)row*NSLOT + cg;
                    *(__nv_bfloat162*)&g_Eh[o] = __nv_bfloat162(h0, h1);
                    *(__nv_bfloat162*)&g_El[o] = __nv_bfloat162(
                        __float2bfloat16(e0 - __bfloat162float(h0)),
                        __float2bfloat16(e1 - __bfloat162float(h1)));
                }
                rsum += __shfl_xor_sync(FULLM, rsum, 1);
                rsum += __shfl_xor_sync(FULLM, rsum, 2);
                if (qc == 0) atomicAdd(&g_rowsum[row], rsum);
            }
    } else {
#pragma unroll
        for (int ma = 0; ma < 4; ma++)
#pragma unroll
            for (int rs = 0; rs < 2; rs++){
                int row = m0 + wm*64 + ma*16 + rs*8 + qr;
#pragma unroll
                for (int na = 0; na < 4; na++){
                    int cg = n0 + wn*32 + na*8 + 2*qc;
                    *(float2*)&out[(size_t)row*DIM + cg] =
                        make_float2(d[ma][na][rs*2], d[ma][na][rs*2+1]);
                }
            }
    }
}

// ---------------- attnC reduce ----------------
__global__ void attnC_red(float* __restrict__ out)
{
    int i = blockIdx.x * blockDim.x + threadIdx.x;
    int row = i >> 6;
    float inv = 1.0f / g_rowsum[row];
    float4 s = *(float4*)&g_part[(size_t)i*4];
    float4 b = *(float4*)&g_part[(size_t)T_TOK*DIM + i*4];
    float4 c = *(float4*)&g_part[(size_t)2*T_TOK*DIM + i*4];
    float4 e = *(float4*)&g_part[(size_t)3*T_TOK*DIM + i*4];
    s.x = (s.x+b.x+c.x+e.x)*inv; s.y = (s.y+b.y+c.y+e.y)*inv;
    s.z = (s.z+b.z+c.z+e.z)*inv; s.w = (s.w+b.w+c.w+e.w)*inv;
    *(float4*)&out[(size_t)i*4] = s;
}

// ---------------- splits ----------------
__device__ __forceinline__ void split_range(const float* src, bf16* h, bf16* l, int n, int tid, int nth)
{
    for (int i = tid; i < n; i += nth){
        float v = src[i];
        bf16 hi = __float2bfloat16(v);
        h[i] = hi;
        l[i] = __float2bfloat16(v - __bfloat162float(hi));
    }
}
__global__ void splitA_kernel(const float* __restrict__ x, const float* __restrict__ Wk,
                              const float* __restrict__ Wv, const float* __restrict__ Wq,
                              const float* __restrict__ bk, const float* __restrict__ bv,
                              const float* __restrict__ bq)
{
    int tid = blockIdx.x * blockDim.x + threadIdx.x;
    if (tid == 0) g_simflag = 0;
    int nth = gridDim.x * blockDim.x;
    if (tid < DIM){
        g_bias[tid] = bk[tid];
        g_bias[DIM + tid] = bv[tid];
        g_bias[2*DIM + tid] = bq[tid];
    }
    split_range(x, g_xhi, g_xlo, T_TOK*DIM, tid, nth);
    split_range(Wk, g_wkh, g_wkl, DIM*DIM, tid, nth);
    split_range(Wv, g_wvh, g_wvl, DIM*DIM, tid, nth);
    split_range(Wq, g_wqh, g_wql, DIM*DIM, tid, nth);
}
__global__ void splitB_kernel(const float* __restrict__ keys0)
{
    int tid = blockIdx.x * blockDim.x + threadIdx.x;
    split_range(keys0, g_k0h, g_k0l, NSLOT*DIM, tid, gridDim.x * blockDim.x);
}
__global__ void splitKB_kernel()
{
    int tid = blockIdx.x * blockDim.x + threadIdx.x;
    split_range(g_kb, g_kbh, g_kbl, NSLOT*DIM, tid, gridDim.x * blockDim.x);
}

__global__ void tsplit_vb()
{
    __shared__ float t[32][33];
    int x = threadIdx.x, y = threadIdx.y;
    int nb = blockIdx.x * 32, db = blockIdx.y * 32;
#pragma unroll
    for (int j = 0; j < 4; j++)
        t[y + 8*j][x] = g_vb[(size_t)(nb + y + 8*j)*DIM + db + x];
    __syncthreads();
#pragma unroll
    for (int j = 0; j < 4; j++){
        float v = t[x][y + 8*j];
        bf16 hi = __float2bfloat16(v);
        size_t o = (size_t)(db + y + 8*j)*NSLOT + nb + x;
        g_vth[o] = hi;
        g_vtl[o] = __float2bfloat16(v - __bfloat162float(hi));
    }
}

// ---------------- combine ----------------
__global__ void combine_kernel(const void* __restrict__ maskptr)
{
    int t = blockIdx.x * blockDim.x + threadIdx.x;
    if (t >= T_TOK) return;
    float best = -CUDART_INF_F; int bi = 0;
#pragma unroll
    for (int s = 0; s < 32; s++){
        float v = g_pmax[s * T_TOK + t];
        int   i = g_pidx[s * T_TOK + t];
        if (v > best){ best = v; bi = i; }
    }
    bool novel = (best * 0.0625f) < 0.5f;
    const unsigned* w = (const unsigned*)maskptr;
    bool bytemode = (w[0] == 0x01010101u);
    bool m;
    if (bytemode) m = ((const unsigned char*)maskptr)[t] != 0;
    else          m = (w[t] != 0);
    g_info[t] = (unsigned)bi | (novel ? 0x10000u : 0u) | (m ? 0x20000u : 0u);
}

// ---------------- fast scan: sorted two-queue merge ------------------------
#define SCAN_SMEM (NSLOT*8 + T_TOK*8 + T_TOK*4 + 64)
__global__ __launch_bounds__(256) void scan_fast(const float* __restrict__ act0)
{
    extern __shared__ char sm[];
    u64* sS = (u64*)sm;
    u64* sQ = (u64*)(sm + NSLOT*8);
    u32* sInfo = (u32*)(sm + NSLOT*8 + T_TOK*8);
    int* sCtl = (int*)(sm + NSLOT*8 + T_TOK*8 + T_TOK*4);
    int tid = threadIdx.x;

    if (tid == 0) sCtl[0] = 0;
    __syncthreads();
    int local = 0;
    for (int t = tid; t < T_TOK; t += 256){
        u32 inf = g_info[t];
        sInfo[t] = inf;
        if ((inf & 0x30000u) == 0x20000u) local = 1;
    }
    if (local) atomicOr(&sCtl[0], 1);
    __syncthreads();
    if (tid == 0) g_scanflag = sCtl[0];
    if (sCtl[0]){ return; }

    for (int i = tid; i < NSLOT; i += 256)
        sS[i] = ((u64)__float_as_uint(act0[i]) << 32) | (u32)i;
    __syncthreads();
    for (int k = 2; k <= NSLOT; k <<= 1){
        for (int j = k >> 1; j > 0; j >>= 1){
            for (int i = tid; i < NSLOT; i += 256){
                int ixj = i ^ j;
                if (ixj > i){
                    u64 a = sS[i], b = sS[ixj];
                    bool up = ((i & k) == 0);
                    if ((a > b) == up){ sS[i] = b; sS[ixj] = a; }
                }
            }
            __syncthreads();
        }
    }

    if (tid == 0){
        int p1 = 0, h2 = 0, t2 = 0;
        for (int t = 0; t < T_TOK; t++){
            u32 inf = sInfo[t];
            if (!(inf & 0x20000u)){ g_pick[t] = 0u; continue; }
            while (p1 < NSLOT && (u32)sS[p1] == 0xFFFFFFFFu) p1++;
            while (h2 < t2 && (u32)sQ[h2] == 0xFFFFFFFFu) h2++;
            u64 k1 = (p1 < NSLOT) ? sS[p1] : ~0ull;
            u64 k2 = (h2 < t2) ? sQ[h2] : ~0ull;
            u32 v1b = (u32)(k1 >> 32), v2b = (u32)(k2 >> 32);
            u32 slot; float v;
            if (v1b < v2b){
                slot = (u32)k1; v = __uint_as_float(v1b); p1++;
            } else {
                u64 best = (v1b == v2b) ? k1 : ~0ull;
                int bj = -1;
                for (int j = h2; j < t2 && (u32)(sQ[j] >> 32) == v2b; j++){
                    u64 kk = sQ[j];
                    if ((u32)kk != 0xFFFFFFFFu && kk < best){ best = kk; bj = j; }
                }
                slot = (u32)best; v = __uint_as_float((u32)(best >> 32));
                if (bj < 0) p1++;
                else if (bj == h2) h2++;
                else sQ[bj] |= 0xFFFFFFFFull;
            }
            float nv = fminf(1.0f, v + 0.1f);
            sQ[t2++] = ((u64)__float_as_uint(nv) << 32) | slot;
            g_pick[t] = slot | 0x30000u;
        }
        sCtl[1] = h2; sCtl[2] = t2;
    }
    __syncthreads();
    int h2 = sCtl[1], t2 = sCtl[2];
    for (int i = tid; i < NSLOT; i += 256) g_act[i] = act0[i];
    __syncthreads();
    for (int e = h2 + tid; e < t2; e += 256){
        u64 key = sQ[e];
        u32 idx = (u32)key;
        if (idx != 0xFFFFFFFFu) g_act[idx] = __uint_as_float((u32)(key >> 32));
    }
}

// ---------------- slow exact scan (fallback) -------------------------------
__global__ __launch_bounds__(256) void scan_kernel(const float* __restrict__ act0)
{
    if (g_scanflag == 0) return;
    __shared__ __align__(16) float s_act[NSLOT];
    __shared__ __align__(16) float s_gmin[128];
    __shared__ int s_gidx[128];
    int tid = threadIdx.x;
    for (int i = tid; i < NSLOT; i += 256) s_act[i] = act0[i];
    __syncthreads();
    int wid = tid >> 5, lane = tid & 31;
    for (int g = wid; g < 128; g += 8){
        float v = s_act[g * 32 + lane];
        unsigned mv = __reduce_min_sync(FULLM, __float_as_uint(v));
        unsigned bal = __ballot_sync(FULLM, __float_as_uint(v) == mv);
        if (lane == 0){ s_gmin[g] = __uint_as_float(mv); s_gidx[g] = g * 32 + (__ffs(bal) - 1); }
    }
    __syncthreads();
    if (wid == 0){
        unsigned myinfo = 0;
        for (int t = 0; t < T_TOK; t++){
            if ((t & 31) == 0) myinfo = __ldg(&g_info[t + lane]);
            unsigned info = __shfl_sync(FULLM, myinfo, t & 31);
            if (info & 0x20000u){
                int slot;
                if (info & 0x10000u){
                    float4 q4 = *(const float4*)&s_gmin[lane * 4];
                    float bv = q4.x; int bg = lane * 4;
                    if (q4.y < bv){ bv = q4.y; bg = lane * 4 + 1; }
                    if (q4.z < bv){ bv = q4.z; bg = lane * 4 + 2; }
                    if (q4.w < bv){ bv = q4.w; bg = lane * 4 + 3; }
                    unsigned mv = __reduce_min_sync(FULLM, __float_as_uint(bv));
                    unsigned bal = __ballot_sync(FULLM, __float_as_uint(bv) == mv);
                    int L = __ffs(bal) - 1;
                    int grp = __shfl_sync(FULLM, bg, L);
                    slot = s_gidx[grp];
                } else {
                    slot = (int)(info & 0xFFFFu);
                }
                float na = fminf(1.0f, s_act[slot] + 0.1f);
                if (lane == 0) s_act[slot] = na;
                __syncwarp();
                int g = slot >> 5;
                float v = s_act[g * 32 + lane];
                unsigned mv2 = __reduce_min_sync(FULLM, __float_as_uint(v));
                unsigned bal2 = __ballot_sync(FULLM, __float_as_uint(v) == mv2);
                if (lane == 0){
                    s_gmin[g] = __uint_as_float(mv2);
                    s_gidx[g] = g * 32 + (__ffs(bal2) - 1);
                    g_pick[t] = (unsigned)slot | (info & 0x10000u) | 0x20000u;
                }
                __syncwarp();
            } else {
                if (lane == 0) g_pick[t] = 0u;
            }
        }
    }
    __syncthreads();
    for (int i = tid; i < NSLOT; i += 256) g_act[i] = s_act[i];
}

// ---------------- rebuild ----------------
__global__ __launch_bounds__(256) void rebuild_kernel(
    const float* __restrict__ keys0, const float* __restrict__ values0)
{
    int wid = threadIdx.x >> 5, lane = threadIdx.x & 31;
    int s = blockIdx.x * 8 + wid;
    float kreg[8], vreg[8];
#pragma unroll
    for (int r = 0; r < 8; r++){
        kreg[r] = keys0[s * DIM + lane + 32 * r];
        vreg[r] = values0[s * DIM + lane + 32 * r];
    }
    for (int base = 0; base < T_TOK; base += 32){
        unsigned pk = __ldg(&g_pick[base + lane]);
        unsigned match = __ballot_sync(FULLM,
            (pk & 0x20000u) && ((pk & 0xFFFFu) == (unsigned)s));
        while (match){
            int bl = __ffs(match) - 1;
            match &= match - 1;
            unsigned pkb = __shfl_sync(FULLM, pk, bl);
            float alpha = (pkb & 0x10000u) ? 0.9f : 0.3f;
            float om = 1.0f - alpha;
            int t = base + bl;
            const float* kr = &g_k[(size_t)t * DIM];
            const float* vr = &g_v[(size_t)t * DIM];
#pragma unroll
            for (int r = 0; r < 8; r++){
                kreg[r] = om * kreg[r] + alpha * __ldg(&kr[lane + 32 * r]);
                vreg[r] = om * vreg[r] + alpha * __ldg(&vr[lane + 32 * r]);
            }
        }
    }
#pragma unroll
    for (int r = 0; r < 8; r++){
        g_kb[s * DIM + lane + 32 * r] = kreg[r];
        g_vb[s * DIM + lane + 32 * r] = vreg[r];
    }
}

// lb + rowsum init
__global__ void actbias_kernel()
{
    int n = blockIdx.x * blockDim.x + threadIdx.x;
    if (n < T_TOK) g_rowsum[n] = 0.f;
    if (n < NSLOT){
        float a = g_act[n];
        g_lb[n] = (a < 0.01f) ? -1e30f : logf(a);
    }
}

// --------------------------------- launch --------------------------------
extern "C" void kernel_launch(void* const* d_in, const int* in_sizes, int n_in,
                              void* d_out, int out_size)
{
    const float* x     = (const float*)d_in[0];
    const void*  wmask = d_in[1];
    const float* keys0 = (const float*)d_in[2];
    const float* vals0 = (const float*)d_in[3];
    const float* act0  = (const float*)d_in[4];
    const float* Wk    = (const float*)d_in[5];
    const float* bk    = (const float*)d_in[6];
    const float* Wv    = (const float*)d_in[7];
    const float* bv    = (const float*)d_in[8];
    const float* Wq    = (const float*)d_in[9];
    const float* bq    = (const float*)d_in[10];
    float* out = (float*)d_out;

    cudaFuncSetAttribute(mm_gemm, cudaFuncAttributeMaxDynamicSharedMemorySize, SMEMSZ);
    cudaFuncSetAttribute(scan_fast, cudaFuncAttributeMaxDynamicSharedMemorySize, SCAN_SMEM);

    splitA_kernel<<<256, 256>>>(x, Wk, Wv, Wq, bk, bv, bq);
    splitB_kernel<<<256, 256>>>(keys0);

    mm_gemm<<<dim3(64,2,3), 256, SMEMSZ>>>(0);        // fused k/v/q projections
    mm_gemm<<<dim3(64,32), 256, SMEMSZ>>>(3);         // simmax 1-term + guard
    mm_gemm<<<dim3(64,32), 256, SMEMSZ>>>(6);         // exact simmax, flag-gated

    combine_kernel<<<T_TOK/256, 256>>>(wmask);
    scan_fast<<<1, 256, SCAN_SMEM>>>(act0);
    scan_kernel<<<1, 256>>>(act0);
    rebuild_kernel<<<NSLOT/8, 256>>>(keys0, vals0);
    splitKB_kernel<<<256, 256>>>();
    actbias_kernel<<<T_TOK/256, 256>>>();
    tsplit_vb<<<dim3(128,8), dim3(32,8)>>>();

    mm_gemm<<<dim3(64,32), 256, SMEMSZ>>>(4);         // attnA: QK + exp + rowsum
    mm_gemm<<<dim3(64,2,4), 256, SMEMSZ>>>(5);        // attnC split-K partials
    attnC_red<<<T_TOK*DIM/1024, 256>>>(out);
}

// round 10
// speedup vs baseline: 4.5519x; 3.3703x over previous
#include <cuda_runtime.h>
#include <cuda_bf16.h>
#include <math_constants.h>

#define T_TOK 8192
#define DIM   256
#define NSLOT 4096
#define FULLM 0xffffffffu
typedef unsigned int u32;
typedef unsigned long long u64;
typedef __nv_bfloat16 bf16;

// ---------------- scratch ----------------
__device__ float g_k[T_TOK * DIM];
__device__ float g_v[T_TOK * DIM];
__device__ float g_q[T_TOK * DIM];
__device__ float g_pmax[32 * T_TOK];
__device__ int   g_pidx[32 * T_TOK];
__device__ unsigned g_info[T_TOK];
__device__ unsigned g_pick[T_TOK];
__device__ float g_act[NSLOT];
__device__ float g_lb[NSLOT];
__device__ float g_bias[3 * DIM];
__device__ float g_kb[NSLOT * DIM];
__device__ float g_vb[NSLOT * DIM];
__device__ float g_rowsum[T_TOK];
__device__ int   g_scanflag;
__device__ int   g_simflag;
__device__ float g_part[4 * T_TOK * DIM];

__device__ bf16 g_xhi[T_TOK*DIM], g_xlo[T_TOK*DIM];
__device__ bf16 g_khi[T_TOK*DIM], g_klo[T_TOK*DIM];
__device__ bf16 g_qhi[T_TOK*DIM], g_qlo[T_TOK*DIM];
__device__ bf16 g_wkh[DIM*DIM], g_wkl[DIM*DIM];
__device__ bf16 g_wvh[DIM*DIM], g_wvl[DIM*DIM];
__device__ bf16 g_wqh[DIM*DIM], g_wql[DIM*DIM];
__device__ bf16 g_k0h[NSLOT*DIM], g_k0l[NSLOT*DIM];
__device__ bf16 g_kbh[NSLOT*DIM], g_kbl[NSLOT*DIM];
__device__ bf16 g_vth[DIM*NSLOT], g_vtl[DIM*NSLOT];
__device__ bf16 g_Eh[(size_t)T_TOK*NSLOT], g_El[(size_t)T_TOK*NSLOT];

// ---------------- helpers ----------------
__device__ __forceinline__ u32 cvta_sm(const void* p){
    u32 a; asm("{.reg .u64 t; cvta.to.shared.u64 t, %1; cvt.u32.u64 %0, t;}" : "=r"(a) : "l"(p));
    return a;
}
#define CPA(dst, src) asm volatile("cp.async.cg.shared.global [%0], [%1], 16;" :: "r"(dst), "l"(src))
#define CPCOMMIT()    asm volatile("cp.async.commit_group;" ::: "memory")
#define CPWAIT1()     asm volatile("cp.async.wait_group 1;" ::: "memory")
#define CPWAIT0()     asm volatile("cp.async.wait_group 0;" ::: "memory")
#define LDX4(r, a) asm volatile("ldmatrix.sync.aligned.m8n8.x4.shared.b16 {%0,%1,%2,%3}, [%4];" \
    : "=r"((r)[0]), "=r"((r)[1]), "=r"((r)[2]), "=r"((r)[3]) : "r"(a))
#define MMA(D, A, B0, B1) asm volatile( \
    "mma.sync.aligned.m16n8k16.row.col.f32.bf16.bf16.f32 " \
    "{%0,%1,%2,%3}, {%4,%5,%6,%7}, {%8,%9}, {%0,%1,%2,%3};" \
    : "+f"((D)[0]), "+f"((D)[1]), "+f"((D)[2]), "+f"((D)[3]) \
    : "r"((A)[0]), "r"((A)[1]), "r"((A)[2]), "r"((A)[3]), "r"(B0), "r"(B1))

#define PITCH 80
#define ABUF  10240
#define BUFSZ 40960
#define SMEMSZ 81920
#define SHIFTC 1.0f

// ---------------- universal mma.sync GEMM (unchanged from R9) --------------
__global__ __launch_bounds__(256, 2) void mm_gemm(int mode)
{
    if (mode == 6 && g_simflag == 0) return;
    const bool guard = (mode == 3);
    const int terms = (mode == 3) ? 1 : 3;
    if (mode == 6) mode = 3;

    extern __shared__ char smx[];
    u32 smb = cvta_sm(smx);
    int tid = threadIdx.x, lane = tid & 31, wid = tid >> 5;
    int wm = wid >> 2, wn = wid & 3;
    int m0 = blockIdx.x * 128, n0 = blockIdx.y * 128;
    int bz = blockIdx.z;

    const bf16 *Ah, *Al, *Bh, *Bl; size_t lda, ldb; int K;
    float* out = 0; bf16 *oh = 0, *ol = 0;
    switch (mode){
    case 0:
        Ah = g_xhi; Al = g_xlo; lda = ldb = DIM; K = DIM;
        if (bz == 0){ Bh=g_wkh; Bl=g_wkl; out=g_k; oh=g_khi; ol=g_klo; }
        else if (bz == 1){ Bh=g_wvh; Bl=g_wvl; out=g_v; }
        else { Bh=g_wqh; Bl=g_wql; out=g_q; oh=g_qhi; ol=g_qlo; }
        break;
    case 3: Ah=g_khi; Al=g_klo; Bh=g_k0h; Bl=g_k0l; lda=ldb=DIM; K=DIM; break;
    case 4: Ah=g_qhi; Al=g_qlo; Bh=g_kbh; Bl=g_kbl; lda=ldb=DIM; K=DIM; break;
    default: Ah=g_Eh; Al=g_El; Bh=g_vth; Bl=g_vtl; lda=ldb=NSLOT; K=NSLOT;
             out=g_part + (size_t)bz * T_TOK * DIM; break;
    }
    int Kper = (mode == 5) ? K / gridDim.z : K;
    size_t kbase = (mode == 5) ? (size_t)bz * Kper * 2 : 0;
    const char* gsrc[4];
    gsrc[0] = (const char*)Ah + (size_t)m0*lda*2 + kbase;
    gsrc[1] = (const char*)Al + (size_t)m0*lda*2 + kbase;
    gsrc[2] = (const char*)Bh + (size_t)n0*ldb*2 + kbase;
    gsrc[3] = (const char*)Bl + (size_t)n0*ldb*2 + kbase;
    size_t rstA = lda*2, rstB = ldb*2;

    int a_ro = (lane & 7) + ((lane & 8) ? 8 : 0);
    int a_ko = (lane & 16) ? 8 : 0;
    int b_ro = (lane & 7) + ((lane & 16) ? 8 : 0);
    int b_ko = (lane & 8) ? 8 : 0;

    float d[4][4][4] = {};
    int nk = Kper / 32;
    {
        int row = (tid >> 2), kc = tid & 3;
#pragma unroll
        for (int arr = 0; arr < 4; arr++){
            if (terms == 1 && (arr & 1)) continue;
            size_t rs = (arr < 2) ? rstA : rstB;
            u32 db = smb + arr*ABUF;
            CPA(db + (u32)row*PITCH + kc*16, gsrc[arr] + (size_t)row*rs + kc*16);
            CPA(db + (u32)(row+64)*PITCH + kc*16, gsrc[arr] + (size_t)(row+64)*rs + kc*16);
        }
        CPCOMMIT();
    }

    for (int ck = 0; ck < nk; ck++){
        if (ck + 1 < nk){
            int row = (tid >> 2), kc = tid & 3;
            size_t koff = (size_t)(ck + 1) * 64;
            u32 db = smb + ((ck + 1) & 1) * BUFSZ;
#pragma unroll
            for (int arr = 0; arr < 4; arr++){
                if (terms == 1 && (arr & 1)) continue;
                size_t rs = (arr < 2) ? rstA : rstB;
                const char* s = gsrc[arr] + koff;
                CPA(db + arr*ABUF + (u32)row*PITCH + kc*16, s + (size_t)row*rs + kc*16);
                CPA(db + arr*ABUF + (u32)(row+64)*PITCH + kc*16, s + (size_t)(row+64)*rs + kc*16);
            }
            CPCOMMIT();
            CPWAIT1();
        } else {
            CPWAIT0();
        }
        __syncthreads();
        u32 bb = smb + (ck & 1) * BUFSZ;
#pragma unroll
        for (int ks = 0; ks < 2; ks++){
            u32 Abase = bb + (u32)(wm*64 + a_ro)*PITCH + (ks*16 + a_ko)*2;
            u32 Bbase = bb + 2*ABUF + (u32)(wn*32 + b_ro)*PITCH + (ks*16 + b_ko)*2;
            u32 bh[2][4], a[4][4];
            LDX4(bh[0], Bbase); LDX4(bh[1], Bbase + 16*PITCH);
#pragma unroll
            for (int ma = 0; ma < 4; ma++) LDX4(a[ma], Abase + ma*16*PITCH);
#pragma unroll
            for (int ma = 0; ma < 4; ma++)
#pragma unroll
                for (int na = 0; na < 4; na++)
                    MMA(d[ma][na], a[ma], bh[na>>1][(na&1)*2], bh[na>>1][(na&1)*2+1]);
            if (terms == 3){
                u32 blr[2][4];
                LDX4(blr[0], Bbase + ABUF); LDX4(blr[1], Bbase + ABUF + 16*PITCH);
#pragma unroll
                for (int ma = 0; ma < 4; ma++)
#pragma unroll
                    for (int na = 0; na < 4; na++)
                        MMA(d[ma][na], a[ma], blr[na>>1][(na&1)*2], blr[na>>1][(na&1)*2+1]);
#pragma unroll
                for (int ma = 0; ma < 4; ma++) LDX4(a[ma], Abase + ABUF + ma*16*PITCH);
#pragma unroll
                for (int ma = 0; ma < 4; ma++)
#pragma unroll
                    for (int na = 0; na < 4; na++)
                        MMA(d[ma][na], a[ma], bh[na>>1][(na&1)*2], bh[na>>1][(na&1)*2+1]);
            }
        }
        __syncthreads();
    }

    float* redv = (float*)smx;
    int*   redi = (int*)(smx + 2048);
    int qr = lane >> 2, qc = lane & 3;

    if (mode == 0){
        const float* bias = g_bias + bz * DIM;
#pragma unroll
        for (int ma = 0; ma < 4; ma++)
#pragma unroll
            for (int rs = 0; rs < 2; rs++){
                int row = m0 + wm*64 + ma*16 + rs*8 + qr;
#pragma unroll
                for (int na = 0; na < 4; na++){
                    int cg = n0 + wn*32 + na*8 + 2*qc;
                    float v0 = d[ma][na][rs*2]   + bias[cg];
                    float v1 = d[ma][na][rs*2+1] + bias[cg+1];
                    *(float2*)&out[(size_t)row*DIM + cg] = make_float2(v0, v1);
                    if (oh){
                        bf16 h0 = __float2bfloat16(v0), h1 = __float2bfloat16(v1);
                        *(__nv_bfloat162*)&oh[(size_t)row*DIM+cg] = __nv_bfloat162(h0, h1);
                        *(__nv_bfloat162*)&ol[(size_t)row*DIM+cg] = __nv_bfloat162(
                            __float2bfloat16(v0 - __bfloat162float(h0)),
                            __float2bfloat16(v1 - __bfloat162float(h1)));
                    }
                }
            }
    } else if (mode == 3){
#pragma unroll
        for (int ma = 0; ma < 4; ma++)
#pragma unroll
            for (int rs = 0; rs < 2; rs++){
                int lrow = wm*64 + ma*16 + rs*8 + qr;
                float bv = -CUDART_INF_F; int bi = 0x7fffffff;
#pragma unroll
                for (int na = 0; na < 4; na++)
#pragma unroll
                    for (int e = 0; e < 2; e++){
                        float v = d[ma][na][rs*2+e];
                        int col = n0 + wn*32 + na*8 + 2*qc + e;
                        if (v > bv){ bv = v; bi = col; }
                    }
#pragma unroll
                for (int o = 1; o < 4; o <<= 1){
                    float ov = __shfl_xor_sync(FULLM, bv, o);
                    int   oi = __shfl_xor_sync(FULLM, bi, o);
                    if (ov > bv || (ov == bv && oi < bi)){ bv = ov; bi = oi; }
                }
                if (qc == 0){ redv[wn*128 + lrow] = bv; redi[wn*128 + lrow] = bi; }
            }
        __syncthreads();
        if (tid < 128){
            float bv = -CUDART_INF_F; int bi = 0x7fffffff;
#pragma unroll
            for (int w = 0; w < 4; w++){
                float v = redv[w*128 + tid]; int i = redi[w*128 + tid];
                if (v > bv || (v == bv && i < bi)){ bv = v; bi = i; }
            }
            g_pmax[blockIdx.y * T_TOK + m0 + tid] = bv;
            g_pidx[blockIdx.y * T_TOK + m0 + tid] = bi;
            if (guard && bv >= 7.4f) atomicOr(&g_simflag, 1);
        }
    } else if (mode == 4){
#pragma unroll
        for (int ma = 0; ma < 4; ma++)
#pragma unroll
            for (int rs = 0; rs < 2; rs++){
                int row = m0 + wm*64 + ma*16 + rs*8 + qr;
                float rsum = 0.f;
#pragma unroll
                for (int na = 0; na < 4; na++){
                    int cg = n0 + wn*32 + na*8 + 2*qc;
                    float e0 = __expf(d[ma][na][rs*2]  *0.0625f + g_lb[cg]   - SHIFTC);
                    float e1 = __expf(d[ma][na][rs*2+1]*0.0625f + g_lb[cg+1] - SHIFTC);
                    rsum += e0 + e1;
                    bf16 h0 = __float2bfloat16(e0), h1 = __float2bfloat16(e1);
                    size_t o = (size_t)row*NSLOT + cg;
                    *(__nv_bfloat162*)&g_Eh[o] = __nv_bfloat162(h0, h1);
                    *(__nv_bfloat162*)&g_El[o] = __nv_bfloat162(
                        __float2bfloat16(e0 - __bfloat162float(h0)),
                        __float2bfloat16(e1 - __bfloat162float(h1)));
                }
                rsum += __shfl_xor_sync(FULLM, rsum, 1);
                rsum += __shfl_xor_sync(FULLM, rsum, 2);
                if (qc == 0) atomicAdd(&g_rowsum[row], rsum);
            }
    } else {
#pragma unroll
        for (int ma = 0; ma < 4; ma++)
#pragma unroll
            for (int rs = 0; rs < 2; rs++){
                int row = m0 + wm*64 + ma*16 + rs*8 + qr;
#pragma unroll
                for (int na = 0; na < 4; na++){
                    int cg = n0 + wn*32 + na*8 + 2*qc;
                    *(float2*)&out[(size_t)row*DIM + cg] =
                        make_float2(d[ma][na][rs*2], d[ma][na][rs*2+1]);
                }
            }
    }
}

// ---------------- attnC reduce ----------------
__global__ void attnC_red(float* __restrict__ out)
{
    int i = blockIdx.x * blockDim.x + threadIdx.x;
    int row = i >> 6;
    float inv = 1.0f / g_rowsum[row];
    float4 s = *(float4*)&g_part[(size_t)i*4];
    float4 b = *(float4*)&g_part[(size_t)T_TOK*DIM + i*4];
    float4 c = *(float4*)&g_part[(size_t)2*T_TOK*DIM + i*4];
    float4 e = *(float4*)&g_part[(size_t)3*T_TOK*DIM + i*4];
    s.x = (s.x+b.x+c.x+e.x)*inv; s.y = (s.y+b.y+c.y+e.y)*inv;
    s.z = (s.z+b.z+c.z+e.z)*inv; s.w = (s.w+b.w+c.w+e.w)*inv;
    *(float4*)&out[(size_t)i*4] = s;
}

// ---------------- splits ----------------
__device__ __forceinline__ void split_range(const float* src, bf16* h, bf16* l, int n, int tid, int nth)
{
    for (int i = tid; i < n; i += nth){
        float v = src[i];
        bf16 hi = __float2bfloat16(v);
        h[i] = hi;
        l[i] = __float2bfloat16(v - __bfloat162float(hi));
    }
}
__global__ void splitA_kernel(const float* __restrict__ x, const float* __restrict__ Wk,
                              const float* __restrict__ Wv, const float* __restrict__ Wq,
                              const float* __restrict__ bk, const float* __restrict__ bv,
                              const float* __restrict__ bq)
{
    int tid = blockIdx.x * blockDim.x + threadIdx.x;
    if (tid == 0) g_simflag = 0;
    int nth = gridDim.x * blockDim.x;
    if (tid < DIM){
        g_bias[tid] = bk[tid];
        g_bias[DIM + tid] = bv[tid];
        g_bias[2*DIM + tid] = bq[tid];
    }
    split_range(x, g_xhi, g_xlo, T_TOK*DIM, tid, nth);
    split_range(Wk, g_wkh, g_wkl, DIM*DIM, tid, nth);
    split_range(Wv, g_wvh, g_wvl, DIM*DIM, tid, nth);
    split_range(Wq, g_wqh, g_wql, DIM*DIM, tid, nth);
}
__global__ void splitB_kernel(const float* __restrict__ keys0)
{
    int tid = blockIdx.x * blockDim.x + threadIdx.x;
    split_range(keys0, g_k0h, g_k0l, NSLOT*DIM, tid, gridDim.x * blockDim.x);
}
__global__ void splitKB_kernel()
{
    int tid = blockIdx.x * blockDim.x + threadIdx.x;
    split_range(g_kb, g_kbh, g_kbl, NSLOT*DIM, tid, gridDim.x * blockDim.x);
}

__global__ void tsplit_vb()
{
    __shared__ float t[32][33];
    int x = threadIdx.x, y = threadIdx.y;
    int nb = blockIdx.x * 32, db = blockIdx.y * 32;
#pragma unroll
    for (int j = 0; j < 4; j++)
        t[y + 8*j][x] = g_vb[(size_t)(nb + y + 8*j)*DIM + db + x];
    __syncthreads();
#pragma unroll
    for (int j = 0; j < 4; j++){
        float v = t[x][y + 8*j];
        bf16 hi = __float2bfloat16(v);
        size_t o = (size_t)(db + y + 8*j)*NSLOT + nb + x;
        g_vth[o] = hi;
        g_vtl[o] = __float2bfloat16(v - __bfloat162float(hi));
    }
}

// ---------------- combine ----------------
__global__ void combine_kernel(const void* __restrict__ maskptr)
{
    int t = blockIdx.x * blockDim.x + threadIdx.x;
    if (t >= T_TOK) return;
    float best = -CUDART_INF_F; int bi = 0;
#pragma unroll
    for (int s = 0; s < 32; s++){
        float v = g_pmax[s * T_TOK + t];
        int   i = g_pidx[s * T_TOK + t];
        if (v > best){ best = v; bi = i; }
    }
    bool novel = (best * 0.0625f) < 0.5f;
    const unsigned* w = (const unsigned*)maskptr;
    bool bytemode = (w[0] == 0x01010101u);
    bool m;
    if (bytemode) m = ((const unsigned char*)maskptr)[t] != 0;
    else          m = (w[t] != 0);
    g_info[t] = (unsigned)bi | (novel ? 0x10000u : 0u) | (m ? 0x20000u : 0u);
}

// ---------------- parallel scan: trajectory sort ---------------------------
// keys 16384*8 + ml 8192*4 + cnt 4096*4 + ctl
#define SP_SMEM (131072 + 32768 + 16384 + 64)
__global__ __launch_bounds__(1024) void scan_par(const float* __restrict__ act0)
{
    extern __shared__ char sm[];
    u64* keys = (u64*)sm;
    u32* ml   = (u32*)(sm + 131072);
    int* cnt  = (int*)(sm + 131072 + 32768);
    int* ctl  = (int*)(sm + 131072 + 32768 + 16384);
    int tid = threadIdx.x;
    if (tid == 0){ ctl[0] = 0; }
    __syncthreads();

    // 1) read info, check masked-non-novel, compact masked token list
    u32 inf8[8]; int myc = 0;
    int base = tid * 8;
#pragma unroll
    for (int j = 0; j < 8; j++){
        inf8[j] = g_info[base + j];
        if ((inf8[j] & 0x30000u) == 0x20000u) atomicOr(&ctl[0], 1);
        if (inf8[j] & 0x20000u) myc++;
    }
    for (int s = tid; s < NSLOT; s += 1024){
        float a = act0[s];
        if (!(a >= 0.0f)) atomicOr(&ctl[0], 1);       // negative or NaN -> fallback
    }
    cnt[tid] = myc;
    __syncthreads();
    for (int off = 1; off < 1024; off <<= 1){
        int v = (tid >= off) ? cnt[tid - off] : 0;
        __syncthreads();
        cnt[tid] += v;
        __syncthreads();
    }
    int mybase = cnt[tid] - myc;
    int m_count = cnt[1023];
    {
        int w = mybase;
#pragma unroll
        for (int j = 0; j < 8; j++)
            if (inf8[j] & 0x20000u) ml[w++] = base + j;
    }
    __syncthreads();

    // 2) binary search V* = smallest value with count(items <= V) >= m_count
    u32 lov = 0, hiv = 0x3F7FFFFFu;   // largest float < 1.0
    for (int pass = 0; pass < 2 || lov < hiv; ){
        u32 mid = (pass < 2) ? hiv : lov + ((hiv - lov) >> 1);
        float V = __uint_as_float(mid);
        __syncthreads();
        if (tid == 0) ctl[1] = 0;
        __syncthreads();
        int c = 0;
        for (int s = tid; s < NSLOT; s += 1024){
            float v = act0[s]; int g = 0;
            while (v < 1.0f && v <= V && g < 64){ c++; g++; v = fminf(1.0f, v + 0.1f); }
        }
#pragma unroll
        for (int o = 16; o; o >>= 1) c += __shfl_xor_sync(FULLM, c, o);
        if ((tid & 31) == 0) atomicAdd(&ctl[1], c);
        __syncthreads();
        int tot = ctl[1];
        if (pass < 2){
            if (pass == 0 && tot < m_count){ if (tid == 0) ctl[0] = 1; }
            pass = 2;                       // feasibility done, start bisection
            if (ctl[0]) break;
            if (tot >= m_count) ; else lov = hiv; // ensured feasible
        } else {
            if (tot >= m_count) hiv = mid; else lov = mid + 1;
        }
    }
    __syncthreads();
    if (ctl[0]){ if (tid == 0) g_scanflag = 1; return; }
    if (tid == 0) g_scanflag = 0;
    float Vf = __uint_as_float(hiv);

    // 3) generate items <= V*
    if (tid == 0) ctl[2] = 0;
    for (int i = tid; i < 16384; i += 1024) keys[i] = ~0ull;
    __syncthreads();
    for (int s = tid; s < NSLOT; s += 1024){
        float v = act0[s]; int g = 0;
        while (v < 1.0f && v <= Vf && g < 64){
            int pos = atomicAdd(&ctl[2], 1);
            keys[pos] = ((u64)__float_as_uint(v) << 32) | (u32)s;
            v = fminf(1.0f, v + 0.1f); g++;
        }
    }
    __syncthreads();

    // 4) bitonic sort 16384 keys ascending
    for (u32 k2 = 2; k2 <= 16384; k2 <<= 1){
        for (u32 j = k2 >> 1; j > 0; j >>= 1){
            for (u32 i = tid; i < 16384; i += 1024){
                u32 ixj = i ^ j;
                if (ixj > i){
                    u64 a = keys[i], b = keys[ixj];
                    bool up = ((i & k2) == 0);
                    if ((a > b) == up){ keys[i] = b; keys[ixj] = a; }
                }
            }
            __syncthreads();
        }
    }

    // 5) picks + per-slot extraction counts + final act
    for (int r = tid; r < m_count; r += 1024){
        u32 slot = (u32)keys[r] & 0xFFFFu;
        g_pick[ml[r]] = slot | 0x30000u;
    }
#pragma unroll
    for (int j = 0; j < 8; j++)
        if (!(inf8[j] & 0x20000u)) g_pick[base + j] = 0u;
    for (int i = tid; i < NSLOT; i += 1024) cnt[i] = 0;
    __syncthreads();
    for (int r = tid; r < m_count; r += 1024)
        atomicAdd(&cnt[(u32)keys[r] & 0xFFFFu], 1);
    __syncthreads();
    for (int s = tid; s < NSLOT; s += 1024){
        float v = act0[s]; int k = cnt[s];
        for (int j = 0; j < k; j++) v = fminf(1.0f, v + 0.1f);
        g_act[s] = v;
    }
}

// ---------------- slow exact scan (fallback, flag-gated) -------------------
__global__ __launch_bounds__(256) void scan_kernel(const float* __restrict__ act0)
{
    if (g_scanflag == 0) return;
    __shared__ __align__(16) float s_act[NSLOT];
    __shared__ __align__(16) float s_gmin[128];
    __shared__ int s_gidx[128];
    int tid = threadIdx.x;
    for (int i = tid; i < NSLOT; i += 256) s_act[i] = act0[i];
    __syncthreads();
    int wid = tid >> 5, lane = tid & 31;
    for (int g = wid; g < 128; g += 8){
        float v = s_act[g * 32 + lane];
        unsigned mv = __reduce_min_sync(FULLM, __float_as_uint(v));
        unsigned bal = __ballot_sync(FULLM, __float_as_uint(v) == mv);
        if (lane == 0){ s_gmin[g] = __uint_as_float(mv); s_gidx[g] = g * 32 + (__ffs(bal) - 1); }
    }
    __syncthreads();
    if (wid == 0){
        unsigned myinfo = 0;
        for (int t = 0; t < T_TOK; t++){
            if ((t & 31) == 0) myinfo = __ldg(&g_info[t + lane]);
            unsigned info = __shfl_sync(FULLM, myinfo, t & 31);
            if (info & 0x20000u){
                int slot;
                if (info & 0x10000u){
                    float4 q4 = *(const float4*)&s_gmin[lane * 4];
                    float bv = q4.x; int bg = lane * 4;
                    if (q4.y < bv){ bv = q4.y; bg = lane * 4 + 1; }
                    if (q4.z < bv){ bv = q4.z; bg = lane * 4 + 2; }
                    if (q4.w < bv){ bv = q4.w; bg = lane * 4 + 3; }
                    unsigned mv = __reduce_min_sync(FULLM, __float_as_uint(bv));
                    unsigned bal = __ballot_sync(FULLM, __float_as_uint(bv) == mv);
                    int L = __ffs(bal) - 1;
                    int grp = __shfl_sync(FULLM, bg, L);
                    slot = s_gidx[grp];
                } else {
                    slot = (int)(info & 0xFFFFu);
                }
                float na = fminf(1.0f, s_act[slot] + 0.1f);
                if (lane == 0) s_act[slot] = na;
                __syncwarp();
                int g = slot >> 5;
                float v = s_act[g * 32 + lane];
                unsigned mv2 = __reduce_min_sync(FULLM, __float_as_uint(v));
                unsigned bal2 = __ballot_sync(FULLM, __float_as_uint(v) == mv2);
                if (lane == 0){
                    s_gmin[g] = __uint_as_float(mv2);
                    s_gidx[g] = g * 32 + (__ffs(bal2) - 1);
                    g_pick[t] = (unsigned)slot | (info & 0x10000u) | 0x20000u;
                }
                __syncwarp();
            } else {
                if (lane == 0) g_pick[t] = 0u;
            }
        }
    }
    __syncthreads();
    for (int i = tid; i < NSLOT; i += 256) g_act[i] = s_act[i];
}

// ---------------- rebuild ----------------
__global__ __launch_bounds__(256) void rebuild_kernel(
    const float* __restrict__ keys0, const float* __restrict__ values0)
{
    int wid = threadIdx.x >> 5, lane = threadIdx.x & 31;
    int s = blockIdx.x * 8 + wid;
    float kreg[8], vreg[8];
#pragma unroll
    for (int r = 0; r < 8; r++){
        kreg[r] = keys0[s * DIM + lane + 32 * r];
        vreg[r] = values0[s * DIM + lane + 32 * r];
    }
    for (int base = 0; base < T_TOK; base += 32){
        unsigned pk = __ldg(&g_pick[base + lane]);
        unsigned match = __ballot_sync(FULLM,
            (pk & 0x20000u) && ((pk & 0xFFFFu) == (unsigned)s));
        while (match){
            int bl = __ffs(match) - 1;
            match &= match - 1;
            unsigned pkb = __shfl_sync(FULLM, pk, bl);
            float alpha = (pkb & 0x10000u) ? 0.9f : 0.3f;
            float om = 1.0f - alpha;
            int t = base + bl;
            const float* kr = &g_k[(size_t)t * DIM];
            const float* vr = &g_v[(size_t)t * DIM];
#pragma unroll
            for (int r = 0; r < 8; r++){
                kreg[r] = om * kreg[r] + alpha * __ldg(&kr[lane + 32 * r]);
                vreg[r] = om * vreg[r] + alpha * __ldg(&vr[lane + 32 * r]);
            }
        }
    }
#pragma unroll
    for (int r = 0; r < 8; r++){
        g_kb[s * DIM + lane + 32 * r] = kreg[r];
        g_vb[s * DIM + lane + 32 * r] = vreg[r];
    }
}

// lb + rowsum init
__global__ void actbias_kernel()
{
    int n = blockIdx.x * blockDim.x + threadIdx.x;
    if (n < T_TOK) g_rowsum[n] = 0.f;
    if (n < NSLOT){
        float a = g_act[n];
        g_lb[n] = (a < 0.01f) ? -1e30f : logf(a);
    }
}

// --------------------------------- launch --------------------------------
extern "C" void kernel_launch(void* const* d_in, const int* in_sizes, int n_in,
                              void* d_out, int out_size)
{
    const float* x     = (const float*)d_in[0];
    const void*  wmask = d_in[1];
    const float* keys0 = (const float*)d_in[2];
    const float* vals0 = (const float*)d_in[3];
    const float* act0  = (const float*)d_in[4];
    const float* Wk    = (const float*)d_in[5];
    const float* bk    = (const float*)d_in[6];
    const float* Wv    = (const float*)d_in[7];
    const float* bv    = (const float*)d_in[8];
    const float* Wq    = (const float*)d_in[9];
    const float* bq    = (const float*)d_in[10];
    float* out = (float*)d_out;

    cudaFuncSetAttribute(mm_gemm, cudaFuncAttributeMaxDynamicSharedMemorySize, SMEMSZ);
    cudaFuncSetAttribute(scan_par, cudaFuncAttributeMaxDynamicSharedMemorySize, SP_SMEM);

    splitA_kernel<<<256, 256>>>(x, Wk, Wv, Wq, bk, bv, bq);
    splitB_kernel<<<256, 256>>>(keys0);

    mm_gemm<<<dim3(64,2,3), 256, SMEMSZ>>>(0);        // fused k/v/q projections
    mm_gemm<<<dim3(64,32), 256, SMEMSZ>>>(3);         // simmax 1-term + guard
    mm_gemm<<<dim3(64,32), 256, SMEMSZ>>>(6);         // exact simmax, flag-gated

    combine_kernel<<<T_TOK/256, 256>>>(wmask);
    scan_par<<<1, 1024, SP_SMEM>>>(act0);             // parallel trajectory-sort scan
    scan_kernel<<<1, 256>>>(act0);                    // exact fallback, flag-gated
    rebuild_kernel<<<NSLOT/8, 256>>>(keys0, vals0);
    splitKB_kernel<<<256, 256>>>();
    actbias_kernel<<<T_TOK/256, 256>>>();
    tsplit_vb<<<dim3(128,8), dim3(32,8)>>>();

    mm_gemm<<<dim3(64,32), 256, SMEMSZ>>>(4);         // attnA: QK + exp + rowsum
    mm_gemm<<<dim3(64,2,4), 256, SMEMSZ>>>(5);        // attnC split-K partials
    attnC_red<<<T_TOK*DIM/1024, 256>>>(out);
}

// round 11
// speedup vs baseline: 4.9675x; 1.0913x over previous
#include <cuda_runtime.h>
#include <cuda_bf16.h>
#include <cuda_fp16.h>
#include <math_constants.h>

#define T_TOK 8192
#define DIM   256
#define NSLOT 4096
#define FULLM 0xffffffffu
typedef unsigned int u32;
typedef unsigned long long u64;
typedef __nv_bfloat16 bf16;

// ---------------- scratch ----------------
__device__ float g_k[T_TOK * DIM];
__device__ float g_v[T_TOK * DIM];
__device__ float g_q[T_TOK * DIM];
__device__ float g_pmax[32 * T_TOK];
__device__ int   g_pidx[32 * T_TOK];
__device__ unsigned g_info[T_TOK];
__device__ unsigned g_pick[T_TOK];
__device__ float g_act[NSLOT];
__device__ float g_lb[NSLOT];
__device__ float g_bias[3 * DIM];
__device__ float g_kb[NSLOT * DIM];
__device__ float g_vb[NSLOT * DIM];
__device__ float g_rowsum[T_TOK];
__device__ int   g_scanflag;
__device__ int   g_simflag;
__device__ float g_part[4 * T_TOK * DIM];

__device__ bf16 g_xhi[T_TOK*DIM], g_xlo[T_TOK*DIM];
__device__ bf16 g_khi[T_TOK*DIM], g_klo[T_TOK*DIM];
__device__ bf16 g_qhi[T_TOK*DIM], g_qlo[T_TOK*DIM];
__device__ bf16 g_wkh[DIM*DIM], g_wkl[DIM*DIM];
__device__ bf16 g_wvh[DIM*DIM], g_wvl[DIM*DIM];
__device__ bf16 g_wqh[DIM*DIM], g_wql[DIM*DIM];
__device__ bf16 g_k0h[NSLOT*DIM], g_k0l[NSLOT*DIM];
__device__ bf16 g_kbh[NSLOT*DIM], g_kbl[NSLOT*DIM];
__device__ __half g_vth[DIM*NSLOT], g_vtl[DIM*NSLOT];
__device__ __half g_Eh[(size_t)T_TOK*NSLOT];

// ---------------- helpers ----------------
__device__ __forceinline__ u32 cvta_sm(const void* p){
    u32 a; asm("{.reg .u64 t; cvta.to.shared.u64 t, %1; cvt.u32.u64 %0, t;}" : "=r"(a) : "l"(p));
    return a;
}
#define CPA(dst, src) asm volatile("cp.async.cg.shared.global [%0], [%1], 16;" :: "r"(dst), "l"(src))
#define CPCOMMIT()    asm volatile("cp.async.commit_group;" ::: "memory")
#define CPWAIT1()     asm volatile("cp.async.wait_group 1;" ::: "memory")
#define CPWAIT0()     asm volatile("cp.async.wait_group 0;" ::: "memory")
#define LDX4(r, a) asm volatile("ldmatrix.sync.aligned.m8n8.x4.shared.b16 {%0,%1,%2,%3}, [%4];" \
    : "=r"((r)[0]), "=r"((r)[1]), "=r"((r)[2]), "=r"((r)[3]) : "r"(a))
#define MMAB(D, A, B0, B1) asm volatile( \
    "mma.sync.aligned.m16n8k16.row.col.f32.bf16.bf16.f32 " \
    "{%0,%1,%2,%3}, {%4,%5,%6,%7}, {%8,%9}, {%0,%1,%2,%3};" \
    : "+f"((D)[0]), "+f"((D)[1]), "+f"((D)[2]), "+f"((D)[3]) \
    : "r"((A)[0]), "r"((A)[1]), "r"((A)[2]), "r"((A)[3]), "r"(B0), "r"(B1))
#define MMAH(D, A, B0, B1) asm volatile( \
    "mma.sync.aligned.m16n8k16.row.col.f32.f16.f16.f32 " \
    "{%0,%1,%2,%3}, {%4,%5,%6,%7}, {%8,%9}, {%0,%1,%2,%3};" \
    : "+f"((D)[0]), "+f"((D)[1]), "+f"((D)[2]), "+f"((D)[3]) \
    : "r"((A)[0]), "r"((A)[1]), "r"((A)[2]), "r"((A)[3]), "r"(B0), "r"(B1))

#define PITCH 80
#define ABUF  10240
#define BUFSZ 40960
#define SMEMSZ 81920
#define SHIFTC 1.0f

// ---------------- universal mma.sync GEMM ----------------
// TERMS=3 bf16 (proj/simmax-exact/attnA), TERMS=1 bf16 (simmax), TERMS=2 fp16 (attnC)
// mode: 0 fused proj (z=k/v/q), 3 simmax(+guard), 4 attnA(exp epilogue),
//       5 attnC splitK, 6 simmax exact (flag-gated)
template<int TERMS, bool H>
__global__ __launch_bounds__(256, 2) void mm_gemm(int mode)
{
    if (mode == 6 && g_simflag == 0) return;
    const bool guard = (mode == 3) && (TERMS == 1);
    if (mode == 6) mode = 3;

    extern __shared__ char smx[];
    u32 smb = cvta_sm(smx);
    int tid = threadIdx.x, lane = tid & 31, wid = tid >> 5;
    int wm = wid >> 2, wn = wid & 3;
    int m0 = blockIdx.x * 128, n0 = blockIdx.y * 128;
    int bz = blockIdx.z;

    const void *pAh, *pAl, *pBh, *pBl; size_t lda, ldb; int K;
    float* out = 0; bf16 *oh = 0, *ol = 0;
    switch (mode){
    case 0:
        pAh = g_xhi; pAl = g_xlo; lda = ldb = DIM; K = DIM;
        if (bz == 0){ pBh=g_wkh; pBl=g_wkl; out=g_k; oh=g_khi; ol=g_klo; }
        else if (bz == 1){ pBh=g_wvh; pBl=g_wvl; out=g_v; }
        else { pBh=g_wqh; pBl=g_wql; out=g_q; oh=g_qhi; ol=g_qlo; }
        break;
    case 3: pAh=g_khi; pAl=g_klo; pBh=g_k0h; pBl=g_k0l; lda=ldb=DIM; K=DIM; break;
    case 4: pAh=g_qhi; pAl=g_qlo; pBh=g_kbh; pBl=g_kbl; lda=ldb=DIM; K=DIM; break;
    default: pAh=g_Eh; pAl=g_Eh; pBh=g_vth; pBl=g_vtl; lda=ldb=NSLOT; K=NSLOT;
             out=g_part + (size_t)bz * T_TOK * DIM; break;
    }
    int Kper = (mode == 5) ? K / gridDim.z : K;
    size_t kbase = (mode == 5) ? (size_t)bz * Kper * 2 : 0;
    const char* gsrc[4];
    gsrc[0] = (const char*)pAh + (size_t)m0*lda*2 + kbase;
    gsrc[1] = (const char*)pAl + (size_t)m0*lda*2 + kbase;
    gsrc[2] = (const char*)pBh + (size_t)n0*ldb*2 + kbase;
    gsrc[3] = (const char*)pBl + (size_t)n0*ldb*2 + kbase;
    size_t rstA = lda*2, rstB = ldb*2;

    int a_ro = (lane & 7) + ((lane & 8) ? 8 : 0);
    int a_ko = (lane & 16) ? 8 : 0;
    int b_ro = (lane & 7) + ((lane & 16) ? 8 : 0);
    int b_ko = (lane & 8) ? 8 : 0;

    float d[4][4][4] = {};
    int nk = Kper / 32;
    {
        int row = (tid >> 2), kc = tid & 3;
#pragma unroll
        for (int arr = 0; arr < 4; arr++){
            if ((TERMS == 1 && (arr & 1)) || (TERMS == 2 && arr == 1)) continue;
            size_t rs = (arr < 2) ? rstA : rstB;
            u32 db = smb + arr*ABUF;
            CPA(db + (u32)row*PITCH + kc*16, gsrc[arr] + (size_t)row*rs + kc*16);
            CPA(db + (u32)(row+64)*PITCH + kc*16, gsrc[arr] + (size_t)(row+64)*rs + kc*16);
        }
        CPCOMMIT();
    }

    for (int ck = 0; ck < nk; ck++){
        if (ck + 1 < nk){
            int row = (tid >> 2), kc = tid & 3;
            size_t koff = (size_t)(ck + 1) * 64;
            u32 db = smb + ((ck + 1) & 1) * BUFSZ;
#pragma unroll
            for (int arr = 0; arr < 4; arr++){
                if ((TERMS == 1 && (arr & 1)) || (TERMS == 2 && arr == 1)) continue;
                size_t rs = (arr < 2) ? rstA : rstB;
                const char* s = gsrc[arr] + koff;
                CPA(db + arr*ABUF + (u32)row*PITCH + kc*16, s + (size_t)row*rs + kc*16);
                CPA(db + arr*ABUF + (u32)(row+64)*PITCH + kc*16, s + (size_t)(row+64)*rs + kc*16);
            }
            CPCOMMIT();
            CPWAIT1();
        } else {
            CPWAIT0();
        }
        __syncthreads();
        u32 bb = smb + (ck & 1) * BUFSZ;
#pragma unroll
        for (int ks = 0; ks < 2; ks++){
            u32 Abase = bb + (u32)(wm*64 + a_ro)*PITCH + (ks*16 + a_ko)*2;
            u32 Bbase = bb + 2*ABUF + (u32)(wn*32 + b_ro)*PITCH + (ks*16 + b_ko)*2;
            u32 bh[2][4], a[4][4];
            LDX4(bh[0], Bbase); LDX4(bh[1], Bbase + 16*PITCH);
#pragma unroll
            for (int ma = 0; ma < 4; ma++) LDX4(a[ma], Abase + ma*16*PITCH);
#pragma unroll
            for (int ma = 0; ma < 4; ma++)
#pragma unroll
                for (int na = 0; na < 4; na++){
                    if (H) MMAH(d[ma][na], a[ma], bh[na>>1][(na&1)*2], bh[na>>1][(na&1)*2+1]);
                    else   MMAB(d[ma][na], a[ma], bh[na>>1][(na&1)*2], bh[na>>1][(na&1)*2+1]);
                }
            if (TERMS >= 2){
                u32 blr[2][4];
                LDX4(blr[0], Bbase + ABUF); LDX4(blr[1], Bbase + ABUF + 16*PITCH);
#pragma unroll
                for (int ma = 0; ma < 4; ma++)
#pragma unroll
                    for (int na = 0; na < 4; na++){
                        if (H) MMAH(d[ma][na], a[ma], blr[na>>1][(na&1)*2], blr[na>>1][(na&1)*2+1]);
                        else   MMAB(d[ma][na], a[ma], blr[na>>1][(na&1)*2], blr[na>>1][(na&1)*2+1]);
                    }
            }
            if (TERMS == 3){
                u32 a2[4][4];
#pragma unroll
                for (int ma = 0; ma < 4; ma++) LDX4(a2[ma], Abase + ABUF + ma*16*PITCH);
#pragma unroll
                for (int ma = 0; ma < 4; ma++)
#pragma unroll
                    for (int na = 0; na < 4; na++)
                        MMAB(d[ma][na], a2[ma], bh[na>>1][(na&1)*2], bh[na>>1][(na&1)*2+1]);
            }
        }
        __syncthreads();
    }

    float* redv = (float*)smx;
    int*   redi = (int*)(smx + 2048);
    int qr = lane >> 2, qc = lane & 3;

    if (mode == 0){
        const float* bias = g_bias + bz * DIM;
#pragma unroll
        for (int ma = 0; ma < 4; ma++)
#pragma unroll
            for (int rs = 0; rs < 2; rs++){
                int row = m0 + wm*64 + ma*16 + rs*8 + qr;
#pragma unroll
                for (int na = 0; na < 4; na++){
                    int cg = n0 + wn*32 + na*8 + 2*qc;
                    float v0 = d[ma][na][rs*2]   + bias[cg];
                    float v1 = d[ma][na][rs*2+1] + bias[cg+1];
                    *(float2*)&out[(size_t)row*DIM + cg] = make_float2(v0, v1);
                    if (oh){
                        bf16 h0 = __float2bfloat16(v0), h1 = __float2bfloat16(v1);
                        *(__nv_bfloat162*)&oh[(size_t)row*DIM+cg] = __nv_bfloat162(h0, h1);
                        *(__nv_bfloat162*)&ol[(size_t)row*DIM+cg] = __nv_bfloat162(
                            __float2bfloat16(v0 - __bfloat162float(h0)),
                            __float2bfloat16(v1 - __bfloat162float(h1)));
                    }
                }
            }
    } else if (mode == 3){
#pragma unroll
        for (int ma = 0; ma < 4; ma++)
#pragma unroll
            for (int rs = 0; rs < 2; rs++){
                int lrow = wm*64 + ma*16 + rs*8 + qr;
                float bv = -CUDART_INF_F; int bi = 0x7fffffff;
#pragma unroll
                for (int na = 0; na < 4; na++)
#pragma unroll
                    for (int e = 0; e < 2; e++){
                        float v = d[ma][na][rs*2+e];
                        int col = n0 + wn*32 + na*8 + 2*qc + e;
                        if (v > bv){ bv = v; bi = col; }
                    }
#pragma unroll
                for (int o = 1; o < 4; o <<= 1){
                    float ov = __shfl_xor_sync(FULLM, bv, o);
                    int   oi = __shfl_xor_sync(FULLM, bi, o);
                    if (ov > bv || (ov == bv && oi < bi)){ bv = ov; bi = oi; }
                }
                if (qc == 0){ redv[wn*128 + lrow] = bv; redi[wn*128 + lrow] = bi; }
            }
        __syncthreads();
        if (tid < 128){
            float bv = -CUDART_INF_F; int bi = 0x7fffffff;
#pragma unroll
            for (int w = 0; w < 4; w++){
                float v = redv[w*128 + tid]; int i = redi[w*128 + tid];
                if (v > bv || (v == bv && i < bi)){ bv = v; bi = i; }
            }
            g_pmax[blockIdx.y * T_TOK + m0 + tid] = bv;
            g_pidx[blockIdx.y * T_TOK + m0 + tid] = bi;
            if (guard && bv >= 7.4f) atomicOr(&g_simflag, 1);
        }
    } else if (mode == 4){
#pragma unroll
        for (int ma = 0; ma < 4; ma++)
#pragma unroll
            for (int rs = 0; rs < 2; rs++){
                int row = m0 + wm*64 + ma*16 + rs*8 + qr;
                float rsum = 0.f;
#pragma unroll
                for (int na = 0; na < 4; na++){
                    int cg = n0 + wn*32 + na*8 + 2*qc;
                    float e0 = __expf(d[ma][na][rs*2]  *0.0625f + g_lb[cg]   - SHIFTC);
                    float e1 = __expf(d[ma][na][rs*2+1]*0.0625f + g_lb[cg+1] - SHIFTC);
                    rsum += e0 + e1;
                    *(__half2*)&g_Eh[(size_t)row*NSLOT + cg] = __floats2half2_rn(e0, e1);
                }
                rsum += __shfl_xor_sync(FULLM, rsum, 1);
                rsum += __shfl_xor_sync(FULLM, rsum, 2);
                if (qc == 0) atomicAdd(&g_rowsum[row], rsum);
            }
    } else {
#pragma unroll
        for (int ma = 0; ma < 4; ma++)
#pragma unroll
            for (int rs = 0; rs < 2; rs++){
                int row = m0 + wm*64 + ma*16 + rs*8 + qr;
#pragma unroll
                for (int na = 0; na < 4; na++){
                    int cg = n0 + wn*32 + na*8 + 2*qc;
                    *(float2*)&out[(size_t)row*DIM + cg] =
                        make_float2(d[ma][na][rs*2], d[ma][na][rs*2+1]);
                }
            }
    }
}

// ---------------- attnC reduce ----------------
__global__ void attnC_red(float* __restrict__ out)
{
    int i = blockIdx.x * blockDim.x + threadIdx.x;
    int row = i >> 6;
    float inv = 1.0f / g_rowsum[row];
    float4 s = *(float4*)&g_part[(size_t)i*4];
    float4 b = *(float4*)&g_part[(size_t)T_TOK*DIM + i*4];
    float4 c = *(float4*)&g_part[(size_t)2*T_TOK*DIM + i*4];
    float4 e = *(float4*)&g_part[(size_t)3*T_TOK*DIM + i*4];
    s.x = (s.x+b.x+c.x+e.x)*inv; s.y = (s.y+b.y+c.y+e.y)*inv;
    s.z = (s.z+b.z+c.z+e.z)*inv; s.w = (s.w+b.w+c.w+e.w)*inv;
    *(float4*)&out[(size_t)i*4] = s;
}

// ---------------- splits ----------------
__device__ __forceinline__ void split_range(const float* src, bf16* h, bf16* l, int n, int tid, int nth)
{
    for (int i = tid; i < n; i += nth){
        float v = src[i];
        bf16 hi = __float2bfloat16(v);
        h[i] = hi;
        l[i] = __float2bfloat16(v - __bfloat162float(hi));
    }
}
__global__ void splitAB_kernel(const float* __restrict__ x, const float* __restrict__ Wk,
                               const float* __restrict__ Wv, const float* __restrict__ Wq,
                               const float* __restrict__ keys0,
                               const float* __restrict__ bk, const float* __restrict__ bv,
                               const float* __restrict__ bq)
{
    int tid = blockIdx.x * blockDim.x + threadIdx.x;
    if (tid == 0) g_simflag = 0;
    int nth = gridDim.x * blockDim.x;
    if (tid < DIM){
        g_bias[tid] = bk[tid];
        g_bias[DIM + tid] = bv[tid];
        g_bias[2*DIM + tid] = bq[tid];
    }
    split_range(x, g_xhi, g_xlo, T_TOK*DIM, tid, nth);
    split_range(Wk, g_wkh, g_wkl, DIM*DIM, tid, nth);
    split_range(Wv, g_wvh, g_wvl, DIM*DIM, tid, nth);
    split_range(Wq, g_wqh, g_wql, DIM*DIM, tid, nth);
    split_range(keys0, g_k0h, g_k0l, NSLOT*DIM, tid, nth);
}
// kb split + lb + rowsum init (post-scan/rebuild)
__global__ void splitKB_kernel()
{
    int tid = blockIdx.x * blockDim.x + threadIdx.x;
    int nth = gridDim.x * blockDim.x;
    split_range(g_kb, g_kbh, g_kbl, NSLOT*DIM, tid, nth);
    for (int n = tid; n < T_TOK; n += nth) g_rowsum[n] = 0.f;
    for (int n = tid; n < NSLOT; n += nth){
        float a = g_act[n];
        g_lb[n] = (a < 0.01f) ? -1e30f : logf(a);
    }
}

__global__ void tsplit_vb()
{
    __shared__ float t[32][33];
    int x = threadIdx.x, y = threadIdx.y;
    int nb = blockIdx.x * 32, db = blockIdx.y * 32;
#pragma unroll
    for (int j = 0; j < 4; j++)
        t[y + 8*j][x] = g_vb[(size_t)(nb + y + 8*j)*DIM + db + x];
    __syncthreads();
#pragma unroll
    for (int j = 0; j < 4; j++){
        float v = t[x][y + 8*j];
        __half hi = __float2half_rn(v);
        size_t o = (size_t)(db + y + 8*j)*NSLOT + nb + x;
        g_vth[o] = hi;
        g_vtl[o] = __float2half_rn(v - __half2float(hi));
    }
}

// ---------------- combine ----------------
__global__ void combine_kernel(const void* __restrict__ maskptr)
{
    int t = blockIdx.x * blockDim.x + threadIdx.x;
    if (t >= T_TOK) return;
    float best = -CUDART_INF_F; int bi = 0;
#pragma unroll
    for (int s = 0; s < 32; s++){
        float v = g_pmax[s * T_TOK + t];
        int   i = g_pidx[s * T_TOK + t];
        if (v > best){ best = v; bi = i; }
    }
    bool novel = (best * 0.0625f) < 0.5f;
    const unsigned* w = (const unsigned*)maskptr;
    bool bytemode = (w[0] == 0x01010101u);
    bool m;
    if (bytemode) m = ((const unsigned char*)maskptr)[t] != 0;
    else          m = (w[t] != 0);
    g_info[t] = (unsigned)bi | (novel ? 0x10000u : 0u) | (m ? 0x20000u : 0u);
}

// ---------------- parallel scan: trajectory sort ---------------------------
#define SP_SMEM (131072 + 32768 + 16384 + 64)
__global__ __launch_bounds__(1024) void scan_par(const float* __restrict__ act0)
{
    extern __shared__ char sm[];
    u64* keys = (u64*)sm;
    u32* ml   = (u32*)(sm + 131072);
    int* cnt  = (int*)(sm + 131072 + 32768);
    int* ctl  = (int*)(sm + 131072 + 32768 + 16384);
    int tid = threadIdx.x;
    if (tid == 0){ ctl[0] = 0; }
    __syncthreads();

    u32 inf8[8]; int myc = 0;
    int base = tid * 8;
#pragma unroll
    for (int j = 0; j < 8; j++){
        inf8[j] = g_info[base + j];
        if ((inf8[j] & 0x30000u) == 0x20000u) atomicOr(&ctl[0], 1);
        if (inf8[j] & 0x20000u) myc++;
    }
    for (int s = tid; s < NSLOT; s += 1024){
        float a = act0[s];
        if (!(a >= 0.0f)) atomicOr(&ctl[0], 1);
    }
    cnt[tid] = myc;
    __syncthreads();
    for (int off = 1; off < 1024; off <<= 1){
        int v = (tid >= off) ? cnt[tid - off] : 0;
        __syncthreads();
        cnt[tid] += v;
        __syncthreads();
    }
    int mybase = cnt[tid] - myc;
    int m_count = cnt[1023];
    {
        int w = mybase;
#pragma unroll
        for (int j = 0; j < 8; j++)
            if (inf8[j] & 0x20000u) ml[w++] = base + j;
    }
    __syncthreads();

    u32 lov = 0, hiv = 0x3F7FFFFFu;
    for (int pass = 0; pass < 2 || lov < hiv; ){
        u32 mid = (pass < 2) ? hiv : lov + ((hiv - lov) >> 1);
        float V = __uint_as_float(mid);
        __syncthreads();
        if (tid == 0) ctl[1] = 0;
        __syncthreads();
        int c = 0;
        for (int s = tid; s < NSLOT; s += 1024){
            float v = act0[s]; int g = 0;
            while (v < 1.0f && v <= V && g < 64){ c++; g++; v = fminf(1.0f, v + 0.1f); }
        }
#pragma unroll
        for (int o = 16; o; o >>= 1) c += __shfl_xor_sync(FULLM, c, o);
        if ((tid & 31) == 0) atomicAdd(&ctl[1], c);
        __syncthreads();
        int tot = ctl[1];
        if (pass < 2){
            if (pass == 0 && tot < m_count){ if (tid == 0) ctl[0] = 1; }
            pass = 2;
            if (ctl[0]) break;
            if (tot >= m_count) ; else lov = hiv;
        } else {
            if (tot >= m_count) hiv = mid; else lov = mid + 1;
        }
    }
    __syncthreads();
    if (ctl[0]){ if (tid == 0) g_scanflag = 1; return; }
    if (tid == 0) g_scanflag = 0;
    float Vf = __uint_as_float(hiv);

    if (tid == 0) ctl[2] = 0;
    for (int i = tid; i < 16384; i += 1024) keys[i] = ~0ull;
    __syncthreads();
    for (int s = tid; s < NSLOT; s += 1024){
        float v = act0[s]; int g = 0;
        while (v < 1.0f && v <= Vf && g < 64){
            int pos = atomicAdd(&ctl[2], 1);
            keys[pos] = ((u64)__float_as_uint(v) << 32) | (u32)s;
            v = fminf(1.0f, v + 0.1f); g++;
        }
    }
    __syncthreads();

    for (u32 k2 = 2; k2 <= 16384; k2 <<= 1){
        for (u32 j = k2 >> 1; j > 0; j >>= 1){
            for (u32 i = tid; i < 16384; i += 1024){
                u32 ixj = i ^ j;
                if (ixj > i){
                    u64 a = keys[i], b = keys[ixj];
                    bool up = ((i & k2) == 0);
                    if ((a > b) == up){ keys[i] = b; keys[ixj] = a; }
                }
            }
            __syncthreads();
        }
    }

    for (int r = tid; r < m_count; r += 1024){
        u32 slot = (u32)keys[r] & 0xFFFFu;
        g_pick[ml[r]] = slot | 0x30000u;
    }
#pragma unroll
    for (int j = 0; j < 8; j++)
        if (!(inf8[j] & 0x20000u)) g_pick[base + j] = 0u;
    for (int i = tid; i < NSLOT; i += 1024) cnt[i] = 0;
    __syncthreads();
    for (int r = tid; r < m_count; r += 1024)
        atomicAdd(&cnt[(u32)keys[r] & 0xFFFFu], 1);
    __syncthreads();
    for (int s = tid; s < NSLOT; s += 1024){
        float v = act0[s]; int k = cnt[s];
        for (int j = 0; j < k; j++) v = fminf(1.0f, v + 0.1f);
        g_act[s] = v;
    }
}

// ---------------- slow exact scan (fallback, flag-gated) -------------------
__global__ __launch_bounds__(256) void scan_kernel(const float* __restrict__ act0)
{
    if (g_scanflag == 0) return;
    __shared__ __align__(16) float s_act[NSLOT];
    __shared__ __align__(16) float s_gmin[128];
    __shared__ int s_gidx[128];
    int tid = threadIdx.x;
    for (int i = tid; i < NSLOT; i += 256) s_act[i] = act0[i];
    __syncthreads();
    int wid = tid >> 5, lane = tid & 31;
    for (int g = wid; g < 128; g += 8){
        float v = s_act[g * 32 + lane];
        unsigned mv = __reduce_min_sync(FULLM, __float_as_uint(v));
        unsigned bal = __ballot_sync(FULLM, __float_as_uint(v) == mv);
        if (lane == 0){ s_gmin[g] = __uint_as_float(mv); s_gidx[g] = g * 32 + (__ffs(bal) - 1); }
    }
    __syncthreads();
    if (wid == 0){
        unsigned myinfo = 0;
        for (int t = 0; t < T_TOK; t++){
            if ((t & 31) == 0) myinfo = __ldg(&g_info[t + lane]);
            unsigned info = __shfl_sync(FULLM, myinfo, t & 31);
            if (info & 0x20000u){
                int slot;
                if (info & 0x10000u){
                    float4 q4 = *(const float4*)&s_gmin[lane * 4];
                    float bv = q4.x; int bg = lane * 4;
                    if (q4.y < bv){ bv = q4.y; bg = lane * 4 + 1; }
                    if (q4.z < bv){ bv = q4.z; bg = lane * 4 + 2; }
                    if (q4.w < bv){ bv = q4.w; bg = lane * 4 + 3; }
                    unsigned mv = __reduce_min_sync(FULLM, __float_as_uint(bv));
                    unsigned bal = __ballot_sync(FULLM, __float_as_uint(bv) == mv);
                    int L = __ffs(bal) - 1;
                    int grp = __shfl_sync(FULLM, bg, L);
                    slot = s_gidx[grp];
                } else {
                    slot = (int)(info & 0xFFFFu);
                }
                float na = fminf(1.0f, s_act[slot] + 0.1f);
                if (lane == 0) s_act[slot] = na;
                __syncwarp();
                int g = slot >> 5;
                float v = s_act[g * 32 + lane];
                unsigned mv2 = __reduce_min_sync(FULLM, __float_as_uint(v));
                unsigned bal2 = __ballot_sync(FULLM, __float_as_uint(v) == mv2);
                if (lane == 0){
                    s_gmin[g] = __uint_as_float(mv2);
                    s_gidx[g] = g * 32 + (__ffs(bal2) - 1);
                    g_pick[t] = (unsigned)slot | (info & 0x10000u) | 0x20000u;
                }
                __syncwarp();
            } else {
                if (lane == 0) g_pick[t] = 0u;
            }
        }
    }
    __syncthreads();
    for (int i = tid; i < NSLOT; i += 256) g_act[i] = s_act[i];
}

// ---------------- rebuild ----------------
__global__ __launch_bounds__(256) void rebuild_kernel(
    const float* __restrict__ keys0, const float* __restrict__ values0)
{
    int wid = threadIdx.x >> 5, lane = threadIdx.x & 31;
    int s = blockIdx.x * 8 + wid;
    float kreg[8], vreg[8];
#pragma unroll
    for (int r = 0; r < 8; r++){
        kreg[r] = keys0[s * DIM + lane + 32 * r];
        vreg[r] = values0[s * DIM + lane + 32 * r];
    }
    for (int base = 0; base < T_TOK; base += 32){
        unsigned pk = __ldg(&g_pick[base + lane]);
        unsigned match = __ballot_sync(FULLM,
            (pk & 0x20000u) && ((pk & 0xFFFFu) == (unsigned)s));
        while (match){
            int bl = __ffs(match) - 1;
            match &= match - 1;
            unsigned pkb = __shfl_sync(FULLM, pk, bl);
            float alpha = (pkb & 0x10000u) ? 0.9f : 0.3f;
            float om = 1.0f - alpha;
            int t = base + bl;
            const float* kr = &g_k[(size_t)t * DIM];
            const float* vr = &g_v[(size_t)t * DIM];
#pragma unroll
            for (int r = 0; r < 8; r++){
                kreg[r] = om * kreg[r] + alpha * __ldg(&kr[lane + 32 * r]);
                vreg[r] = om * vreg[r] + alpha * __ldg(&vr[lane + 32 * r]);
            }
        }
    }
#pragma unroll
    for (int r = 0; r < 8; r++){
        g_kb[s * DIM + lane + 32 * r] = kreg[r];
        g_vb[s * DIM + lane + 32 * r] = vreg[r];
    }
}

// --------------------------------- launch --------------------------------
extern "C" void kernel_launch(void* const* d_in, const int* in_sizes, int n_in,
                              void* d_out, int out_size)
{
    const float* x     = (const float*)d_in[0];
    const void*  wmask = d_in[1];
    const float* keys0 = (const float*)d_in[2];
    const float* vals0 = (const float*)d_in[3];
    const float* act0  = (const float*)d_in[4];
    const float* Wk    = (const float*)d_in[5];
    const float* bk    = (const float*)d_in[6];
    const float* Wv    = (const float*)d_in[7];
    const float* bv    = (const float*)d_in[8];
    const float* Wq    = (const float*)d_in[9];
    const float* bq    = (const float*)d_in[10];
    float* out = (float*)d_out;

    cudaFuncSetAttribute(mm_gemm<3,false>, cudaFuncAttributeMaxDynamicSharedMemorySize, SMEMSZ);
    cudaFuncSetAttribute(mm_gemm<1,false>, cudaFuncAttributeMaxDynamicSharedMemorySize, SMEMSZ);
    cudaFuncSetAttribute(mm_gemm<2,true>,  cudaFuncAttributeMaxDynamicSharedMemorySize, SMEMSZ);
    cudaFuncSetAttribute(scan_par, cudaFuncAttributeMaxDynamicSharedMemorySize, SP_SMEM);

    splitAB_kernel<<<256, 256>>>(x, Wk, Wv, Wq, keys0, bk, bv, bq);

    mm_gemm<3,false><<<dim3(64,2,3), 256, SMEMSZ>>>(0);   // fused k/v/q projections
    mm_gemm<1,false><<<dim3(64,32), 256, SMEMSZ>>>(3);    // simmax 1-term + guard
    mm_gemm<3,false><<<dim3(64,32), 256, SMEMSZ>>>(6);    // exact simmax, flag-gated

    combine_kernel<<<T_TOK/256, 256>>>(wmask);
    scan_par<<<1, 1024, SP_SMEM>>>(act0);                 // parallel trajectory-sort scan
    scan_kernel<<<1, 256>>>(act0);                        // exact fallback, flag-gated
    rebuild_kernel<<<NSLOT/8, 256>>>(keys0, vals0);
    splitKB_kernel<<<256, 256>>>();                       // kb split + lb + rowsum init
    tsplit_vb<<<dim3(128,8), dim3(32,8)>>>();             // vb -> fp16 transpose split

    mm_gemm<3,false><<<dim3(64,32), 256, SMEMSZ>>>(4);    // attnA: QK + exp + rowsum
    mm_gemm<2,true><<<dim3(64,2,4), 256, SMEMSZ>>>(5);    // attnC fp16 2-term splitK
    attnC_red<<<T_TOK*DIM/1024, 256>>>(out);
}

// round 12
// speedup vs baseline: 5.2274x; 1.0523x over previous
#include <cuda_runtime.h>
#include <cuda_bf16.h>
#include <cuda_fp16.h>
#include <math_constants.h>

#define T_TOK 8192
#define DIM   256
#define NSLOT 4096
#define FULLM 0xffffffffu
typedef unsigned int u32;
typedef unsigned long long u64;
typedef __nv_bfloat16 bf16;

// ---------------- scratch ----------------
__device__ float g_k[T_TOK * DIM];
__device__ float g_v[T_TOK * DIM];
__device__ float g_pmax[32 * T_TOK];
__device__ int   g_pidx[32 * T_TOK];
__device__ unsigned g_info[T_TOK];
__device__ unsigned g_pick[T_TOK];
__device__ float g_act[NSLOT];
__device__ float g_lb[NSLOT];
__device__ float g_bias[3 * DIM];
__device__ float g_kb[NSLOT * DIM];
__device__ float g_vb[NSLOT * DIM];
__device__ float g_rowsum[T_TOK];
__device__ int   g_scanflag;
__device__ int   g_simflag;
__device__ float g_part[4 * T_TOK * DIM];

__device__ bf16 g_xhi[T_TOK*DIM], g_xlo[T_TOK*DIM];
__device__ bf16 g_khi[T_TOK*DIM], g_klo[T_TOK*DIM];
__device__ __half g_qh[T_TOK*DIM];
__device__ bf16 g_wkh[DIM*DIM], g_wkl[DIM*DIM];
__device__ bf16 g_wvh[DIM*DIM], g_wvl[DIM*DIM];
__device__ bf16 g_wqh[DIM*DIM], g_wql[DIM*DIM];
__device__ bf16 g_k0h[NSLOT*DIM], g_k0l[NSLOT*DIM];
__device__ __half g_kbh[NSLOT*DIM], g_kbl[NSLOT*DIM];
__device__ __half g_vth[DIM*NSLOT], g_vtl[DIM*NSLOT];
__device__ __half g_Eh[(size_t)T_TOK*NSLOT];

// ---------------- helpers ----------------
__device__ __forceinline__ u32 cvta_sm(const void* p){
    u32 a; asm("{.reg .u64 t; cvta.to.shared.u64 t, %1; cvt.u32.u64 %0, t;}" : "=r"(a) : "l"(p));
    return a;
}
#define CPA(dst, src) asm volatile("cp.async.cg.shared.global [%0], [%1], 16;" :: "r"(dst), "l"(src))
#define CPCOMMIT()    asm volatile("cp.async.commit_group;" ::: "memory")
#define CPWAIT1()     asm volatile("cp.async.wait_group 1;" ::: "memory")
#define CPWAIT0()     asm volatile("cp.async.wait_group 0;" ::: "memory")
#define LDX4(r, a) asm volatile("ldmatrix.sync.aligned.m8n8.x4.shared.b16 {%0,%1,%2,%3}, [%4];" \
    : "=r"((r)[0]), "=r"((r)[1]), "=r"((r)[2]), "=r"((r)[3]) : "r"(a))
#define MMAB(D, A, B0, B1) asm volatile( \
    "mma.sync.aligned.m16n8k16.row.col.f32.bf16.bf16.f32 " \
    "{%0,%1,%2,%3}, {%4,%5,%6,%7}, {%8,%9}, {%0,%1,%2,%3};" \
    : "+f"((D)[0]), "+f"((D)[1]), "+f"((D)[2]), "+f"((D)[3]) \
    : "r"((A)[0]), "r"((A)[1]), "r"((A)[2]), "r"((A)[3]), "r"(B0), "r"(B1))
#define MMAH(D, A, B0, B1) asm volatile( \
    "mma.sync.aligned.m16n8k16.row.col.f32.f16.f16.f32 " \
    "{%0,%1,%2,%3}, {%4,%5,%6,%7}, {%8,%9}, {%0,%1,%2,%3};" \
    : "+f"((D)[0]), "+f"((D)[1]), "+f"((D)[2]), "+f"((D)[3]) \
    : "r"((A)[0]), "r"((A)[1]), "r"((A)[2]), "r"((A)[3]), "r"(B0), "r"(B1))

#define PITCH 80
#define ABUF  10240
#define BUFSZ 40960
#define SMEMSZ 81920
#define SHIFTC 1.0f

// ---------------- universal mma.sync GEMM ----------------
// TERMS=3 bf16 (proj / simmax-exact), TERMS=1 bf16 (simmax+guard),
// TERMS=2 fp16 (attnA: A=qh single, B=kbh+kbl; attnC: A=E single, B=vth+vtl)
// mode: 0 fused proj (z=k/v/q), 3 simmax, 4 attnA, 5 attnC splitK, 6 simmax exact
template<int TERMS, bool H>
__global__ __launch_bounds__(256, 2) void mm_gemm(int mode)
{
    if (mode == 6 && g_simflag == 0) return;
    const bool guard = (mode == 3) && (TERMS == 1);
    if (mode == 6) mode = 3;

    extern __shared__ char smx[];
    u32 smb = cvta_sm(smx);
    int tid = threadIdx.x, lane = tid & 31, wid = tid >> 5;
    int wm = wid >> 2, wn = wid & 3;
    int m0 = blockIdx.x * 128, n0 = blockIdx.y * 128;
    int bz = blockIdx.z;

    const void *pAh, *pAl, *pBh, *pBl; size_t lda, ldb; int K;
    float* out = 0; bf16 *oh = 0, *ol = 0;
    switch (mode){
    case 0:
        pAh = g_xhi; pAl = g_xlo; lda = ldb = DIM; K = DIM;
        if (bz == 0){ pBh=g_wkh; pBl=g_wkl; out=g_k; oh=g_khi; ol=g_klo; }
        else if (bz == 1){ pBh=g_wvh; pBl=g_wvl; out=g_v; }
        else { pBh=g_wqh; pBl=g_wql; }
        break;
    case 3: pAh=g_khi; pAl=g_klo; pBh=g_k0h; pBl=g_k0l; lda=ldb=DIM; K=DIM; break;
    case 4: pAh=g_qh;  pAl=g_qh;  pBh=g_kbh; pBl=g_kbl; lda=ldb=DIM; K=DIM; break;
    default: pAh=g_Eh; pAl=g_Eh; pBh=g_vth; pBl=g_vtl; lda=ldb=NSLOT; K=NSLOT;
             out=g_part + (size_t)bz * T_TOK * DIM; break;
    }
    int Kper = (mode == 5) ? K / gridDim.z : K;
    size_t kbase = (mode == 5) ? (size_t)bz * Kper * 2 : 0;
    const char* gsrc[4];
    gsrc[0] = (const char*)pAh + (size_t)m0*lda*2 + kbase;
    gsrc[1] = (const char*)pAl + (size_t)m0*lda*2 + kbase;
    gsrc[2] = (const char*)pBh + (size_t)n0*ldb*2 + kbase;
    gsrc[3] = (const char*)pBl + (size_t)n0*ldb*2 + kbase;
    size_t rstA = lda*2, rstB = ldb*2;

    int a_ro = (lane & 7) + ((lane & 8) ? 8 : 0);
    int a_ko = (lane & 16) ? 8 : 0;
    int b_ro = (lane & 7) + ((lane & 16) ? 8 : 0);
    int b_ko = (lane & 8) ? 8 : 0;

    float d[4][4][4] = {};
    int nk = Kper / 32;
    {
        int row = (tid >> 2), kc = tid & 3;
#pragma unroll
        for (int arr = 0; arr < 4; arr++){
            if ((TERMS == 1 && (arr & 1)) || (TERMS == 2 && arr == 1)) continue;
            size_t rs = (arr < 2) ? rstA : rstB;
            u32 db = smb + arr*ABUF;
            CPA(db + (u32)row*PITCH + kc*16, gsrc[arr] + (size_t)row*rs + kc*16);
            CPA(db + (u32)(row+64)*PITCH + kc*16, gsrc[arr] + (size_t)(row+64)*rs + kc*16);
        }
        CPCOMMIT();
    }

    for (int ck = 0; ck < nk; ck++){
        if (ck + 1 < nk){
            int row = (tid >> 2), kc = tid & 3;
            size_t koff = (size_t)(ck + 1) * 64;
            u32 db = smb + ((ck + 1) & 1) * BUFSZ;
#pragma unroll
            for (int arr = 0; arr < 4; arr++){
                if ((TERMS == 1 && (arr & 1)) || (TERMS == 2 && arr == 1)) continue;
                size_t rs = (arr < 2) ? rstA : rstB;
                const char* s = gsrc[arr] + koff;
                CPA(db + arr*ABUF + (u32)row*PITCH + kc*16, s + (size_t)row*rs + kc*16);
                CPA(db + arr*ABUF + (u32)(row+64)*PITCH + kc*16, s + (size_t)(row+64)*rs + kc*16);
            }
            CPCOMMIT();
            CPWAIT1();
        } else {
            CPWAIT0();
        }
        __syncthreads();
        u32 bb = smb + (ck & 1) * BUFSZ;
#pragma unroll
        for (int ks = 0; ks < 2; ks++){
            u32 Abase = bb + (u32)(wm*64 + a_ro)*PITCH + (ks*16 + a_ko)*2;
            u32 Bbase = bb + 2*ABUF + (u32)(wn*32 + b_ro)*PITCH + (ks*16 + b_ko)*2;
            u32 bh[2][4], a[4][4];
            LDX4(bh[0], Bbase); LDX4(bh[1], Bbase + 16*PITCH);
#pragma unroll
            for (int ma = 0; ma < 4; ma++) LDX4(a[ma], Abase + ma*16*PITCH);
#pragma unroll
            for (int ma = 0; ma < 4; ma++)
#pragma unroll
                for (int na = 0; na < 4; na++){
                    if (H) MMAH(d[ma][na], a[ma], bh[na>>1][(na&1)*2], bh[na>>1][(na&1)*2+1]);
                    else   MMAB(d[ma][na], a[ma], bh[na>>1][(na&1)*2], bh[na>>1][(na&1)*2+1]);
                }
            if (TERMS >= 2){
                u32 blr[2][4];
                LDX4(blr[0], Bbase + ABUF); LDX4(blr[1], Bbase + ABUF + 16*PITCH);
#pragma unroll
                for (int ma = 0; ma < 4; ma++)
#pragma unroll
                    for (int na = 0; na < 4; na++){
                        if (H) MMAH(d[ma][na], a[ma], blr[na>>1][(na&1)*2], blr[na>>1][(na&1)*2+1]);
                        else   MMAB(d[ma][na], a[ma], blr[na>>1][(na&1)*2], blr[na>>1][(na&1)*2+1]);
                    }
            }
            if (TERMS == 3){
                u32 a2[4][4];
#pragma unroll
                for (int ma = 0; ma < 4; ma++) LDX4(a2[ma], Abase + ABUF + ma*16*PITCH);
#pragma unroll
                for (int ma = 0; ma < 4; ma++)
#pragma unroll
                    for (int na = 0; na < 4; na++)
                        MMAB(d[ma][na], a2[ma], bh[na>>1][(na&1)*2], bh[na>>1][(na&1)*2+1]);
            }
        }
        __syncthreads();
    }

    float* redv = (float*)smx;
    int*   redi = (int*)(smx + 2048);
    int qr = lane >> 2, qc = lane & 3;

    if (mode == 0){
        const float* bias = g_bias + bz * DIM;
#pragma unroll
        for (int ma = 0; ma < 4; ma++)
#pragma unroll
            for (int rs = 0; rs < 2; rs++){
                int row = m0 + wm*64 + ma*16 + rs*8 + qr;
#pragma unroll
                for (int na = 0; na < 4; na++){
                    int cg = n0 + wn*32 + na*8 + 2*qc;
                    float v0 = d[ma][na][rs*2]   + bias[cg];
                    float v1 = d[ma][na][rs*2+1] + bias[cg+1];
                    if (bz == 2){
                        *(__half2*)&g_qh[(size_t)row*DIM + cg] = __floats2half2_rn(v0, v1);
                    } else {
                        *(float2*)&out[(size_t)row*DIM + cg] = make_float2(v0, v1);
                        if (bz == 0){
                            bf16 h0 = __float2bfloat16(v0), h1 = __float2bfloat16(v1);
                            *(__nv_bfloat162*)&oh[(size_t)row*DIM+cg] = __nv_bfloat162(h0, h1);
                            *(__nv_bfloat162*)&ol[(size_t)row*DIM+cg] = __nv_bfloat162(
                                __float2bfloat16(v0 - __bfloat162float(h0)),
                                __float2bfloat16(v1 - __bfloat162float(h1)));
                        }
                    }
                }
            }
    } else if (mode == 3){
#pragma unroll
        for (int ma = 0; ma < 4; ma++)
#pragma unroll
            for (int rs = 0; rs < 2; rs++){
                int lrow = wm*64 + ma*16 + rs*8 + qr;
                float bv = -CUDART_INF_F; int bi = 0x7fffffff;
#pragma unroll
                for (int na = 0; na < 4; na++)
#pragma unroll
                    for (int e = 0; e < 2; e++){
                        float v = d[ma][na][rs*2+e];
                        int col = n0 + wn*32 + na*8 + 2*qc + e;
                        if (v > bv){ bv = v; bi = col; }
                    }
#pragma unroll
                for (int o = 1; o < 4; o <<= 1){
                    float ov = __shfl_xor_sync(FULLM, bv, o);
                    int   oi = __shfl_xor_sync(FULLM, bi, o);
                    if (ov > bv || (ov == bv && oi < bi)){ bv = ov; bi = oi; }
                }
                if (qc == 0){ redv[wn*128 + lrow] = bv; redi[wn*128 + lrow] = bi; }
            }
        __syncthreads();
        if (tid < 128){
            float bv = -CUDART_INF_F; int bi = 0x7fffffff;
#pragma unroll
            for (int w = 0; w < 4; w++){
                float v = redv[w*128 + tid]; int i = redi[w*128 + tid];
                if (v > bv || (v == bv && i < bi)){ bv = v; bi = i; }
            }
            g_pmax[blockIdx.y * T_TOK + m0 + tid] = bv;
            g_pidx[blockIdx.y * T_TOK + m0 + tid] = bi;
            if (guard && bv >= 7.4f) atomicOr(&g_simflag, 1);
        }
    } else if (mode == 4){
#pragma unroll
        for (int ma = 0; ma < 4; ma++)
#pragma unroll
            for (int rs = 0; rs < 2; rs++){
                int row = m0 + wm*64 + ma*16 + rs*8 + qr;
                float rsum = 0.f;
#pragma unroll
                for (int na = 0; na < 4; na++){
                    int cg = n0 + wn*32 + na*8 + 2*qc;
                    float e0 = __expf(d[ma][na][rs*2]  *0.0625f + g_lb[cg]   - SHIFTC);
                    float e1 = __expf(d[ma][na][rs*2+1]*0.0625f + g_lb[cg+1] - SHIFTC);
                    rsum += e0 + e1;
                    *(__half2*)&g_Eh[(size_t)row*NSLOT + cg] = __floats2half2_rn(e0, e1);
                }
                rsum += __shfl_xor_sync(FULLM, rsum, 1);
                rsum += __shfl_xor_sync(FULLM, rsum, 2);
                if (qc == 0) atomicAdd(&g_rowsum[row], rsum);
            }
    } else {
#pragma unroll
        for (int ma = 0; ma < 4; ma++)
#pragma unroll
            for (int rs = 0; rs < 2; rs++){
                int row = m0 + wm*64 + ma*16 + rs*8 + qr;
#pragma unroll
                for (int na = 0; na < 4; na++){
                    int cg = n0 + wn*32 + na*8 + 2*qc;
                    *(float2*)&out[(size_t)row*DIM + cg] =
                        make_float2(d[ma][na][rs*2], d[ma][na][rs*2+1]);
                }
            }
    }
}

// ---------------- attnC reduce ----------------
__global__ void attnC_red(float* __restrict__ out)
{
    int i = blockIdx.x * blockDim.x + threadIdx.x;
    int row = i >> 6;
    float inv = 1.0f / g_rowsum[row];
    float4 s = *(float4*)&g_part[(size_t)i*4];
    float4 b = *(float4*)&g_part[(size_t)T_TOK*DIM + i*4];
    float4 c = *(float4*)&g_part[(size_t)2*T_TOK*DIM + i*4];
    float4 e = *(float4*)&g_part[(size_t)3*T_TOK*DIM + i*4];
    s.x = (s.x+b.x+c.x+e.x)*inv; s.y = (s.y+b.y+c.y+e.y)*inv;
    s.z = (s.z+b.z+c.z+e.z)*inv; s.w = (s.w+b.w+c.w+e.w)*inv;
    *(float4*)&out[(size_t)i*4] = s;
}

// ---------------- splits ----------------
__device__ __forceinline__ void split_range(const float* src, bf16* h, bf16* l, int n, int tid, int nth)
{
    for (int i = tid; i < n; i += nth){
        float v = src[i];
        bf16 hi = __float2bfloat16(v);
        h[i] = hi;
        l[i] = __float2bfloat16(v - __bfloat162float(hi));
    }
}
__global__ void splitAB_kernel(const float* __restrict__ x, const float* __restrict__ Wk,
                               const float* __restrict__ Wv, const float* __restrict__ Wq,
                               const float* __restrict__ keys0,
                               const float* __restrict__ bk, const float* __restrict__ bv,
                               const float* __restrict__ bq)
{
    int tid = blockIdx.x * blockDim.x + threadIdx.x;
    if (tid == 0) g_simflag = 0;
    int nth = gridDim.x * blockDim.x;
    if (tid < DIM){
        g_bias[tid] = bk[tid];
        g_bias[DIM + tid] = bv[tid];
        g_bias[2*DIM + tid] = bq[tid];
    }
    split_range(x, g_xhi, g_xlo, T_TOK*DIM, tid, nth);
    split_range(Wk, g_wkh, g_wkl, DIM*DIM, tid, nth);
    split_range(Wv, g_wvh, g_wvl, DIM*DIM, tid, nth);
    split_range(Wq, g_wqh, g_wql, DIM*DIM, tid, nth);
    split_range(keys0, g_k0h, g_k0l, NSLOT*DIM, tid, nth);
}
// kb fp16 split + lb + rowsum init (post-scan/rebuild)
__global__ void splitKB_kernel()
{
    int tid = blockIdx.x * blockDim.x + threadIdx.x;
    int nth = gridDim.x * blockDim.x;
    for (int i = tid; i < NSLOT*DIM; i += nth){
        float v = g_kb[i];
        __half hi = __float2half_rn(v);
        g_kbh[i] = hi;
        g_kbl[i] = __float2half_rn(v - __half2float(hi));
    }
    for (int n = tid; n < T_TOK; n += nth) g_rowsum[n] = 0.f;
    for (int n = tid; n < NSLOT; n += nth){
        float a = g_act[n];
        g_lb[n] = (a < 0.01f) ? -1e30f : logf(a);
    }
}

__global__ void tsplit_vb()
{
    __shared__ float t[32][33];
    int x = threadIdx.x, y = threadIdx.y;
    int nb = blockIdx.x * 32, db = blockIdx.y * 32;
#pragma unroll
    for (int j = 0; j < 4; j++)
        t[y + 8*j][x] = g_vb[(size_t)(nb + y + 8*j)*DIM + db + x];
    __syncthreads();
#pragma unroll
    for (int j = 0; j < 4; j++){
        float v = t[x][y + 8*j];
        __half hi = __float2half_rn(v);
        size_t o = (size_t)(db + y + 8*j)*NSLOT + nb + x;
        g_vth[o] = hi;
        g_vtl[o] = __float2half_rn(v - __half2float(hi));
    }
}

// ---------------- combine ----------------
__global__ void combine_kernel(const void* __restrict__ maskptr)
{
    int t = blockIdx.x * blockDim.x + threadIdx.x;
    if (t >= T_TOK) return;
    float best = -CUDART_INF_F; int bi = 0;
#pragma unroll
    for (int s = 0; s < 32; s++){
        float v = g_pmax[s * T_TOK + t];
        int   i = g_pidx[s * T_TOK + t];
        if (v > best){ best = v; bi = i; }
    }
    bool novel = (best * 0.0625f) < 0.5f;
    const unsigned* w = (const unsigned*)maskptr;
    bool bytemode = (w[0] == 0x01010101u);
    bool m;
    if (bytemode) m = ((const unsigned char*)maskptr)[t] != 0;
    else          m = (w[t] != 0);
    g_info[t] = (unsigned)bi | (novel ? 0x10000u : 0u) | (m ? 0x20000u : 0u);
}

// ---------------- parallel scan: trajectory sort ---------------------------
#define SP_SMEM (131072 + 32768 + 16384 + 64)
__global__ __launch_bounds__(1024) void scan_par(const float* __restrict__ act0)
{
    extern __shared__ char sm[];
    u64* keys = (u64*)sm;
    u32* ml   = (u32*)(sm + 131072);
    int* cnt  = (int*)(sm + 131072 + 32768);
    int* ctl  = (int*)(sm + 131072 + 32768 + 16384);
    int tid = threadIdx.x;
    if (tid == 0){ ctl[0] = 0; }
    __syncthreads();

    u32 inf8[8]; int myc = 0;
    int base = tid * 8;
#pragma unroll
    for (int j = 0; j < 8; j++){
        inf8[j] = g_info[base + j];
        if ((inf8[j] & 0x30000u) == 0x20000u) atomicOr(&ctl[0], 1);
        if (inf8[j] & 0x20000u) myc++;
    }
    for (int s = tid; s < NSLOT; s += 1024){
        float a = act0[s];
        if (!(a >= 0.0f)) atomicOr(&ctl[0], 1);
    }
    cnt[tid] = myc;
    __syncthreads();
    for (int off = 1; off < 1024; off <<= 1){
        int v = (tid >= off) ? cnt[tid - off] : 0;
        __syncthreads();
        cnt[tid] += v;
        __syncthreads();
    }
    int mybase = cnt[tid] - myc;
    int m_count = cnt[1023];
    {
        int w = mybase;
#pragma unroll
        for (int j = 0; j < 8; j++)
            if (inf8[j] & 0x20000u) ml[w++] = base + j;
    }
    __syncthreads();

    u32 lov = 0, hiv = 0x3F7FFFFFu;
    for (int pass = 0; pass < 2 || lov < hiv; ){
        u32 mid = (pass < 2) ? hiv : lov + ((hiv - lov) >> 1);
        float V = __uint_as_float(mid);
        __syncthreads();
        if (tid == 0) ctl[1] = 0;
        __syncthreads();
        int c = 0;
        for (int s = tid; s < NSLOT; s += 1024){
            float v = act0[s]; int g = 0;
            while (v < 1.0f && v <= V && g < 64){ c++; g++; v = fminf(1.0f, v + 0.1f); }
        }
#pragma unroll
        for (int o = 16; o; o >>= 1) c += __shfl_xor_sync(FULLM, c, o);
        if ((tid & 31) == 0) atomicAdd(&ctl[1], c);
        __syncthreads();
        int tot = ctl[1];
        if (pass < 2){
            if (pass == 0 && tot < m_count){ if (tid == 0) ctl[0] = 1; }
            pass = 2;
            if (ctl[0]) break;
            if (tot >= m_count) ; else lov = hiv;
        } else {
            if (tot >= m_count) hiv = mid; else lov = mid + 1;
        }
    }
    __syncthreads();
    if (ctl[0]){ if (tid == 0) g_scanflag = 1; return; }
    if (tid == 0) g_scanflag = 0;
    float Vf = __uint_as_float(hiv);

    if (tid == 0) ctl[2] = 0;
    for (int i = tid; i < 16384; i += 1024) keys[i] = ~0ull;
    __syncthreads();
    for (int s = tid; s < NSLOT; s += 1024){
        float v = act0[s]; int g = 0;
        while (v < 1.0f && v <= Vf && g < 64){
            int pos = atomicAdd(&ctl[2], 1);
            keys[pos] = ((u64)__float_as_uint(v) << 32) | (u32)s;
            v = fminf(1.0f, v + 0.1f); g++;
        }
    }
    __syncthreads();

    for (u32 k2 = 2; k2 <= 16384; k2 <<= 1){
        for (u32 j = k2 >> 1; j > 0; j >>= 1){
            for (u32 i = tid; i < 16384; i += 1024){
                u32 ixj = i ^ j;
                if (ixj > i){
                    u64 a = keys[i], b = keys[ixj];
                    bool up = ((i & k2) == 0);
                    if ((a > b) == up){ keys[i] = b; keys[ixj] = a; }
                }
            }
            __syncthreads();
        }
    }

    for (int r = tid; r < m_count; r += 1024){
        u32 slot = (u32)keys[r] & 0xFFFFu;
        g_pick[ml[r]] = slot | 0x30000u;
    }
#pragma unroll
    for (int j = 0; j < 8; j++)
        if (!(inf8[j] & 0x20000u)) g_pick[base + j] = 0u;
    for (int i = tid; i < NSLOT; i += 1024) cnt[i] = 0;
    __syncthreads();
    for (int r = tid; r < m_count; r += 1024)
        atomicAdd(&cnt[(u32)keys[r] & 0xFFFFu], 1);
    __syncthreads();
    for (int s = tid; s < NSLOT; s += 1024){
        float v = act0[s]; int k = cnt[s];
        for (int j = 0; j < k; j++) v = fminf(1.0f, v + 0.1f);
        g_act[s] = v;
    }
}

// ---------------- slow exact scan (fallback, flag-gated) -------------------
__global__ __launch_bounds__(256) void scan_kernel(const float* __restrict__ act0)
{
    if (g_scanflag == 0) return;
    __shared__ __align__(16) float s_act[NSLOT];
    __shared__ __align__(16) float s_gmin[128];
    __shared__ int s_gidx[128];
    int tid = threadIdx.x;
    for (int i = tid; i < NSLOT; i += 256) s_act[i] = act0[i];
    __syncthreads();
    int wid = tid >> 5, lane = tid & 31;
    for (int g = wid; g < 128; g += 8){
        float v = s_act[g * 32 + lane];
        unsigned mv = __reduce_min_sync(FULLM, __float_as_uint(v));
        unsigned bal = __ballot_sync(FULLM, __float_as_uint(v) == mv);
        if (lane == 0){ s_gmin[g] = __uint_as_float(mv); s_gidx[g] = g * 32 + (__ffs(bal) - 1); }
    }
    __syncthreads();
    if (wid == 0){
        unsigned myinfo = 0;
        for (int t = 0; t < T_TOK; t++){
            if ((t & 31) == 0) myinfo = __ldg(&g_info[t + lane]);
            unsigned info = __shfl_sync(FULLM, myinfo, t & 31);
            if (info & 0x20000u){
                int slot;
                if (info & 0x10000u){
                    float4 q4 = *(const float4*)&s_gmin[lane * 4];
                    float bv = q4.x; int bg = lane * 4;
                    if (q4.y < bv){ bv = q4.y; bg = lane * 4 + 1; }
                    if (q4.z < bv){ bv = q4.z; bg = lane * 4 + 2; }
                    if (q4.w < bv){ bv = q4.w; bg = lane * 4 + 3; }
                    unsigned mv = __reduce_min_sync(FULLM, __float_as_uint(bv));
                    unsigned bal = __ballot_sync(FULLM, __float_as_uint(bv) == mv);
                    int L = __ffs(bal) - 1;
                    int grp = __shfl_sync(FULLM, bg, L);
                    slot = s_gidx[grp];
                } else {
                    slot = (int)(info & 0xFFFFu);
                }
                float na = fminf(1.0f, s_act[slot] + 0.1f);
                if (lane == 0) s_act[slot] = na;
                __syncwarp();
                int g = slot >> 5;
                float v = s_act[g * 32 + lane];
                unsigned mv2 = __reduce_min_sync(FULLM, __float_as_uint(v));
                unsigned bal2 = __ballot_sync(FULLM, __float_as_uint(v) == mv2);
                if (lane == 0){
                    s_gmin[g] = __uint_as_float(mv2);
                    s_gidx[g] = g * 32 + (__ffs(bal2) - 1);
                    g_pick[t] = (unsigned)slot | (info & 0x10000u) | 0x20000u;
                }
                __syncwarp();
            } else {
                if (lane == 0) g_pick[t] = 0u;
            }
        }
    }
    __syncthreads();
    for (int i = tid; i < NSLOT; i += 256) g_act[i] = s_act[i];
}

// ---------------- rebuild ----------------
__global__ __launch_bounds__(256) void rebuild_kernel(
    const float* __restrict__ keys0, const float* __restrict__ values0)
{
    int wid = threadIdx.x >> 5, lane = threadIdx.x & 31;
    int s = blockIdx.x * 8 + wid;
    float kreg[8], vreg[8];
#pragma unroll
    for (int r = 0; r < 8; r++){
        kreg[r] = keys0[s * DIM + lane + 32 * r];
        vreg[r] = values0[s * DIM + lane + 32 * r];
    }
    for (int base = 0; base < T_TOK; base += 32){
        unsigned pk = __ldg(&g_pick[base + lane]);
        unsigned match = __ballot_sync(FULLM,
            (pk & 0x20000u) && ((pk & 0xFFFFu) == (unsigned)s));
        while (match){
            int bl = __ffs(match) - 1;
            match &= match - 1;
            unsigned pkb = __shfl_sync(FULLM, pk, bl);
            float alpha = (pkb & 0x10000u) ? 0.9f : 0.3f;
            float om = 1.0f - alpha;
            int t = base + bl;
            const float* kr = &g_k[(size_t)t * DIM];
            const float* vr = &g_v[(size_t)t * DIM];
#pragma unroll
            for (int r = 0; r < 8; r++){
                kreg[r] = om * kreg[r] + alpha * __ldg(&kr[lane + 32 * r]);
                vreg[r] = om * vreg[r] + alpha * __ldg(&vr[lane + 32 * r]);
            }
        }
    }
#pragma unroll
    for (int r = 0; r < 8; r++){
        g_kb[s * DIM + lane + 32 * r] = kreg[r];
        g_vb[s * DIM + lane + 32 * r] = vreg[r];
    }
}

// --------------------------------- launch --------------------------------
extern "C" void kernel_launch(void* const* d_in, const int* in_sizes, int n_in,
                              void* d_out, int out_size)
{
    const float* x     = (const float*)d_in[0];
    const void*  wmask = d_in[1];
    const float* keys0 = (const float*)d_in[2];
    const float* vals0 = (const float*)d_in[3];
    const float* act0  = (const float*)d_in[4];
    const float* Wk    = (const float*)d_in[5];
    const float* bk    = (const float*)d_in[6];
    const float* Wv    = (const float*)d_in[7];
    const float* bv    = (const float*)d_in[8];
    const float* Wq    = (const float*)d_in[9];
    const float* bq    = (const float*)d_in[10];
    float* out = (float*)d_out;

    cudaFuncSetAttribute(mm_gemm<3,false>, cudaFuncAttributeMaxDynamicSharedMemorySize, SMEMSZ);
    cudaFuncSetAttribute(mm_gemm<1,false>, cudaFuncAttributeMaxDynamicSharedMemorySize, SMEMSZ);
    cudaFuncSetAttribute(mm_gemm<2,true>,  cudaFuncAttributeMaxDynamicSharedMemorySize, SMEMSZ);
    cudaFuncSetAttribute(scan_par, cudaFuncAttributeMaxDynamicSharedMemorySize, SP_SMEM);

    splitAB_kernel<<<256, 256>>>(x, Wk, Wv, Wq, keys0, bk, bv, bq);

    mm_gemm<3,false><<<dim3(64,2,3), 256, SMEMSZ>>>(0);   // fused k/v/q projections
    mm_gemm<1,false><<<dim3(64,32), 256, SMEMSZ>>>(3);    // simmax 1-term + guard
    mm_gemm<3,false><<<dim3(64,32), 256, SMEMSZ>>>(6);    // exact simmax, flag-gated

    combine_kernel<<<T_TOK/256, 256>>>(wmask);
    scan_par<<<1, 1024, SP_SMEM>>>(act0);                 // parallel trajectory-sort scan
    scan_kernel<<<1, 256>>>(act0);                        // exact fallback, flag-gated
    rebuild_kernel<<<NSLOT/8, 256>>>(keys0, vals0);
    splitKB_kernel<<<256, 256>>>();                       // kb fp16 split + lb + rowsum init
    tsplit_vb<<<dim3(128,8), dim3(32,8)>>>();             // vb -> fp16 transpose split

    mm_gemm<2,true><<<dim3(64,32), 256, SMEMSZ>>>(4);     // attnA fp16 2-term: QK+exp+rowsum
    mm_gemm<2,true><<<dim3(64,2,4), 256, SMEMSZ>>>(5);    // attnC fp16 2-term splitK
    attnC_red<<<T_TOK*DIM/1024, 256>>>(out);
}

// round 13
// speedup vs baseline: 5.2893x; 1.0118x over previous
#include <cuda_runtime.h>
#include <cuda_bf16.h>
#include <cuda_fp16.h>
#include <math_constants.h>

#define T_TOK 8192
#define DIM   256
#define NSLOT 4096
#define FULLM 0xffffffffu
typedef unsigned int u32;
typedef unsigned long long u64;
typedef __nv_bfloat16 bf16;

// ---------------- scratch ----------------
__device__ float g_k[T_TOK * DIM];
__device__ float g_v[T_TOK * DIM];
__device__ u64   g_cmax[T_TOK];
__device__ u64   g_cmax2[T_TOK];
__device__ unsigned g_info[T_TOK];
__device__ unsigned g_pick[T_TOK];
__device__ float g_act[NSLOT];
__device__ float g_lb[NSLOT];
__device__ float g_bias[3 * DIM];
__device__ float g_vb[NSLOT * DIM];
__device__ float g_rowsum[T_TOK];
__device__ int   g_scanflag;
__device__ int   g_simflag;
__device__ float g_part[4 * T_TOK * DIM];

__device__ bf16 g_xhi[T_TOK*DIM], g_xlo[T_TOK*DIM];
__device__ bf16 g_khi[T_TOK*DIM], g_klo[T_TOK*DIM];
__device__ __half g_qh[T_TOK*DIM];
__device__ bf16 g_wkh[DIM*DIM], g_wkl[DIM*DIM];
__device__ bf16 g_wvh[DIM*DIM], g_wvl[DIM*DIM];
__device__ bf16 g_wqh[DIM*DIM], g_wql[DIM*DIM];
__device__ bf16 g_k0h[NSLOT*DIM], g_k0l[NSLOT*DIM];
__device__ __half g_kbh[NSLOT*DIM], g_kbl[NSLOT*DIM];
__device__ __half g_vth[DIM*NSLOT], g_vtl[DIM*NSLOT];
__device__ __half g_Eh[(size_t)T_TOK*NSLOT];

// ---------------- helpers ----------------
__device__ __forceinline__ u32 cvta_sm(const void* p){
    u32 a; asm("{.reg .u64 t; cvta.to.shared.u64 t, %1; cvt.u32.u64 %0, t;}" : "=r"(a) : "l"(p));
    return a;
}
__device__ __forceinline__ u32 fmap(float f){
    u32 b = __float_as_uint(f);
    return (b & 0x80000000u) ? ~b : (b | 0x80000000u);
}
__device__ __forceinline__ float funmap(u32 u){
    u32 b = (u & 0x80000000u) ? (u ^ 0x80000000u) : ~u;
    return __uint_as_float(b);
}
#define CPA(dst, src) asm volatile("cp.async.cg.shared.global [%0], [%1], 16;" :: "r"(dst), "l"(src))
#define CPCOMMIT()    asm volatile("cp.async.commit_group;" ::: "memory")
#define CPWAIT1()     asm volatile("cp.async.wait_group 1;" ::: "memory")
#define CPWAIT0()     asm volatile("cp.async.wait_group 0;" ::: "memory")
#define LDX4(r, a) asm volatile("ldmatrix.sync.aligned.m8n8.x4.shared.b16 {%0,%1,%2,%3}, [%4];" \
    : "=r"((r)[0]), "=r"((r)[1]), "=r"((r)[2]), "=r"((r)[3]) : "r"(a))
#define MMAB(D, A, B0, B1) asm volatile( \
    "mma.sync.aligned.m16n8k16.row.col.f32.bf16.bf16.f32 " \
    "{%0,%1,%2,%3}, {%4,%5,%6,%7}, {%8,%9}, {%0,%1,%2,%3};" \
    : "+f"((D)[0]), "+f"((D)[1]), "+f"((D)[2]), "+f"((D)[3]) \
    : "r"((A)[0]), "r"((A)[1]), "r"((A)[2]), "r"((A)[3]), "r"(B0), "r"(B1))
#define MMAH(D, A, B0, B1) asm volatile( \
    "mma.sync.aligned.m16n8k16.row.col.f32.f16.f16.f32 " \
    "{%0,%1,%2,%3}, {%4,%5,%6,%7}, {%8,%9}, {%0,%1,%2,%3};" \
    : "+f"((D)[0]), "+f"((D)[1]), "+f"((D)[2]), "+f"((D)[3]) \
    : "r"((A)[0]), "r"((A)[1]), "r"((A)[2]), "r"((A)[3]), "r"(B0), "r"(B1))

#define PITCH 80
#define ABUF  10240
#define BUFSZ 40960
#define SMEMSZ 81920
#define SHIFTC 1.0f

// ---------------- universal mma.sync GEMM ----------------
// TERMS=3 bf16 (proj / simmax-exact), TERMS=1 bf16 (simmax+guard),
// TERMS=2 fp16 (attnA: A=qh, B=kbh+kbl; attnC: A=E, B=vth+vtl)
// mode: 0 fused proj (z=k/v/q), 3 simmax, 4 attnA, 5 attnC splitK, 6 simmax exact
template<int TERMS, bool H>
__global__ __launch_bounds__(256, 2) void mm_gemm(int mode)
{
    if (mode == 6 && g_simflag == 0) return;
    const bool guard = (mode == 3) && (TERMS == 1);
    if (mode == 6) mode = 3;

    extern __shared__ char smx[];
    u32 smb = cvta_sm(smx);
    int tid = threadIdx.x, lane = tid & 31, wid = tid >> 5;
    int wm = wid >> 2, wn = wid & 3;
    int m0 = blockIdx.x * 128, n0 = blockIdx.y * 128;
    int bz = blockIdx.z;

    const void *pAh, *pAl, *pBh, *pBl; size_t lda, ldb; int K;
    float* out = 0; bf16 *oh = 0, *ol = 0;
    switch (mode){
    case 0:
        pAh = g_xhi; pAl = g_xlo; lda = ldb = DIM; K = DIM;
        if (bz == 0){ pBh=g_wkh; pBl=g_wkl; out=g_k; oh=g_khi; ol=g_klo; }
        else if (bz == 1){ pBh=g_wvh; pBl=g_wvl; out=g_v; }
        else { pBh=g_wqh; pBl=g_wql; }
        break;
    case 3: pAh=g_khi; pAl=g_klo; pBh=g_k0h; pBl=g_k0l; lda=ldb=DIM; K=DIM; break;
    case 4: pAh=g_qh;  pAl=g_qh;  pBh=g_kbh; pBl=g_kbl; lda=ldb=DIM; K=DIM; break;
    default: pAh=g_Eh; pAl=g_Eh; pBh=g_vth; pBl=g_vtl; lda=ldb=NSLOT; K=NSLOT;
             out=g_part + (size_t)bz * T_TOK * DIM; break;
    }
    int Kper = (mode == 5) ? K / gridDim.z : K;
    size_t kbase = (mode == 5) ? (size_t)bz * Kper * 2 : 0;
    const char* gsrc[4];
    gsrc[0] = (const char*)pAh + (size_t)m0*lda*2 + kbase;
    gsrc[1] = (const char*)pAl + (size_t)m0*lda*2 + kbase;
    gsrc[2] = (const char*)pBh + (size_t)n0*ldb*2 + kbase;
    gsrc[3] = (const char*)pBl + (size_t)n0*ldb*2 + kbase;
    size_t rstA = lda*2, rstB = ldb*2;

    int a_ro = (lane & 7) + ((lane & 8) ? 8 : 0);
    int a_ko = (lane & 16) ? 8 : 0;
    int b_ro = (lane & 7) + ((lane & 16) ? 8 : 0);
    int b_ko = (lane & 8) ? 8 : 0;

    float d[4][4][4] = {};
    int nk = Kper / 32;
    {
        int row = (tid >> 2), kc = tid & 3;
#pragma unroll
        for (int arr = 0; arr < 4; arr++){
            if ((TERMS == 1 && (arr & 1)) || (TERMS == 2 && arr == 1)) continue;
            size_t rs = (arr < 2) ? rstA : rstB;
            u32 db = smb + arr*ABUF;
            CPA(db + (u32)row*PITCH + kc*16, gsrc[arr] + (size_t)row*rs + kc*16);
            CPA(db + (u32)(row+64)*PITCH + kc*16, gsrc[arr] + (size_t)(row+64)*rs + kc*16);
        }
        CPCOMMIT();
    }

    for (int ck = 0; ck < nk; ck++){
        if (ck + 1 < nk){
            int row = (tid >> 2), kc = tid & 3;
            size_t koff = (size_t)(ck + 1) * 64;
            u32 db = smb + ((ck + 1) & 1) * BUFSZ;
#pragma unroll
            for (int arr = 0; arr < 4; arr++){
                if ((TERMS == 1 && (arr & 1)) || (TERMS == 2 && arr == 1)) continue;
                size_t rs = (arr < 2) ? rstA : rstB;
                const char* s = gsrc[arr] + koff;
                CPA(db + arr*ABUF + (u32)row*PITCH + kc*16, s + (size_t)row*rs + kc*16);
                CPA(db + arr*ABUF + (u32)(row+64)*PITCH + kc*16, s + (size_t)(row+64)*rs + kc*16);
            }
            CPCOMMIT();
            CPWAIT1();
        } else {
            CPWAIT0();
        }
        __syncthreads();
        u32 bb = smb + (ck & 1) * BUFSZ;
#pragma unroll
        for (int ks = 0; ks < 2; ks++){
            u32 Abase = bb + (u32)(wm*64 + a_ro)*PITCH + (ks*16 + a_ko)*2;
            u32 Bbase = bb + 2*ABUF + (u32)(wn*32 + b_ro)*PITCH + (ks*16 + b_ko)*2;
            u32 bh[2][4], a[4][4];
            LDX4(bh[0], Bbase); LDX4(bh[1], Bbase + 16*PITCH);
#pragma unroll
            for (int ma = 0; ma < 4; ma++) LDX4(a[ma], Abase + ma*16*PITCH);
#pragma unroll
            for (int ma = 0; ma < 4; ma++)
#pragma unroll
                for (int na = 0; na < 4; na++){
                    if (H) MMAH(d[ma][na], a[ma], bh[na>>1][(na&1)*2], bh[na>>1][(na&1)*2+1]);
                    else   MMAB(d[ma][na], a[ma], bh[na>>1][(na&1)*2], bh[na>>1][(na&1)*2+1]);
                }
            if (TERMS >= 2){
                u32 blr[2][4];
                LDX4(blr[0], Bbase + ABUF); LDX4(blr[1], Bbase + ABUF + 16*PITCH);
#pragma unroll
                for (int ma = 0; ma < 4; ma++)
#pragma unroll
                    for (int na = 0; na < 4; na++){
                        if (H) MMAH(d[ma][na], a[ma], blr[na>>1][(na&1)*2], blr[na>>1][(na&1)*2+1]);
                        else   MMAB(d[ma][na], a[ma], blr[na>>1][(na&1)*2], blr[na>>1][(na&1)*2+1]);
                    }
            }
            if (TERMS == 3){
                u32 a2[4][4];
#pragma unroll
                for (int ma = 0; ma < 4; ma++) LDX4(a2[ma], Abase + ABUF + ma*16*PITCH);
#pragma unroll
                for (int ma = 0; ma < 4; ma++)
#pragma unroll
                    for (int na = 0; na < 4; na++)
                        MMAB(d[ma][na], a2[ma], bh[na>>1][(na&1)*2], bh[na>>1][(na&1)*2+1]);
            }
        }
        __syncthreads();
    }

    int qr = lane >> 2, qc = lane & 3;

    if (mode == 0){
        const float* bias = g_bias + bz * DIM;
#pragma unroll
        for (int ma = 0; ma < 4; ma++)
#pragma unroll
            for (int rs = 0; rs < 2; rs++){
                int row = m0 + wm*64 + ma*16 + rs*8 + qr;
#pragma unroll
                for (int na = 0; na < 4; na++){
                    int cg = n0 + wn*32 + na*8 + 2*qc;
                    float v0 = d[ma][na][rs*2]   + bias[cg];
                    float v1 = d[ma][na][rs*2+1] + bias[cg+1];
                    if (bz == 2){
                        *(__half2*)&g_qh[(size_t)row*DIM + cg] = __floats2half2_rn(v0, v1);
                    } else {
                        *(float2*)&out[(size_t)row*DIM + cg] = make_float2(v0, v1);
                        if (bz == 0){
                            bf16 h0 = __float2bfloat16(v0), h1 = __float2bfloat16(v1);
                            *(__nv_bfloat162*)&oh[(size_t)row*DIM+cg] = __nv_bfloat162(h0, h1);
                            *(__nv_bfloat162*)&ol[(size_t)row*DIM+cg] = __nv_bfloat162(
                                __float2bfloat16(v0 - __bfloat162float(h0)),
                                __float2bfloat16(v1 - __bfloat162float(h1)));
                        }
                    }
                }
            }
    } else if (mode == 3){
        u64* cm = guard ? g_cmax : g_cmax2;
#pragma unroll
        for (int ma = 0; ma < 4; ma++)
#pragma unroll
            for (int rs = 0; rs < 2; rs++){
                int row = m0 + wm*64 + ma*16 + rs*8 + qr;
                float bv = -CUDART_INF_F; int bi = 0x7fffffff;
#pragma unroll
                for (int na = 0; na < 4; na++)
#pragma unroll
                    for (int e = 0; e < 2; e++){
                        float v = d[ma][na][rs*2+e];
                        int col = n0 + wn*32 + na*8 + 2*qc + e;
                        if (v > bv){ bv = v; bi = col; }
                    }
#pragma unroll
                for (int o = 1; o < 4; o <<= 1){
                    float ov = __shfl_xor_sync(FULLM, bv, o);
                    int   oi = __shfl_xor_sync(FULLM, bi, o);
                    if (ov > bv || (ov == bv && oi < bi)){ bv = ov; bi = oi; }
                }
                if (qc == 0){
                    atomicMax(&cm[row], ((u64)fmap(bv) << 32) | (u32)(~(u32)bi));
                    if (guard && bv >= 7.4f) atomicOr(&g_simflag, 1);
                }
            }
    } else if (mode == 4){
#pragma unroll
        for (int ma = 0; ma < 4; ma++)
#pragma unroll
            for (int rs = 0; rs < 2; rs++){
                int row = m0 + wm*64 + ma*16 + rs*8 + qr;
                float rsum = 0.f;
#pragma unroll
                for (int na = 0; na < 4; na++){
                    int cg = n0 + wn*32 + na*8 + 2*qc;
                    float e0 = __expf(d[ma][na][rs*2]  *0.0625f + g_lb[cg]   - SHIFTC);
                    float e1 = __expf(d[ma][na][rs*2+1]*0.0625f + g_lb[cg+1] - SHIFTC);
                    rsum += e0 + e1;
                    *(__half2*)&g_Eh[(size_t)row*NSLOT + cg] = __floats2half2_rn(e0, e1);
                }
                rsum += __shfl_xor_sync(FULLM, rsum, 1);
                rsum += __shfl_xor_sync(FULLM, rsum, 2);
                if (qc == 0) atomicAdd(&g_rowsum[row], rsum);
            }
    } else {
#pragma unroll
        for (int ma = 0; ma < 4; ma++)
#pragma unroll
            for (int rs = 0; rs < 2; rs++){
                int row = m0 + wm*64 + ma*16 + rs*8 + qr;
#pragma unroll
                for (int na = 0; na < 4; na++){
                    int cg = n0 + wn*32 + na*8 + 2*qc;
                    *(float2*)&out[(size_t)row*DIM + cg] =
                        make_float2(d[ma][na][rs*2], d[ma][na][rs*2+1]);
                }
            }
    }
}

// ---------------- attnC reduce ----------------
__global__ void attnC_red(float* __restrict__ out)
{
    int i = blockIdx.x * blockDim.x + threadIdx.x;
    int row = i >> 6;
    float inv = 1.0f / g_rowsum[row];
    float4 s = *(float4*)&g_part[(size_t)i*4];
    float4 b = *(float4*)&g_part[(size_t)T_TOK*DIM + i*4];
    float4 c = *(float4*)&g_part[(size_t)2*T_TOK*DIM + i*4];
    float4 e = *(float4*)&g_part[(size_t)3*T_TOK*DIM + i*4];
    s.x = (s.x+b.x+c.x+e.x)*inv; s.y = (s.y+b.y+c.y+e.y)*inv;
    s.z = (s.z+b.z+c.z+e.z)*inv; s.w = (s.w+b.w+c.w+e.w)*inv;
    *(float4*)&out[(size_t)i*4] = s;
}

// ---------------- splits ----------------
__device__ __forceinline__ void split_range(const float* src, bf16* h, bf16* l, int n, int tid, int nth)
{
    for (int i = tid; i < n; i += nth){
        float v = src[i];
        bf16 hi = __float2bfloat16(v);
        h[i] = hi;
        l[i] = __float2bfloat16(v - __bfloat162float(hi));
    }
}
__global__ void splitAB_kernel(const float* __restrict__ x, const float* __restrict__ Wk,
                               const float* __restrict__ Wv, const float* __restrict__ Wq,
                               const float* __restrict__ keys0,
                               const float* __restrict__ bk, const float* __restrict__ bv,
                               const float* __restrict__ bq)
{
    int tid = blockIdx.x * blockDim.x + threadIdx.x;
    if (tid == 0) g_simflag = 0;
    int nth = gridDim.x * blockDim.x;
    if (tid < DIM){
        g_bias[tid] = bk[tid];
        g_bias[DIM + tid] = bv[tid];
        g_bias[2*DIM + tid] = bq[tid];
    }
    for (int t = tid; t < T_TOK; t += nth){ g_cmax[t] = 0ull; g_cmax2[t] = 0ull; }
    split_range(x, g_xhi, g_xlo, T_TOK*DIM, tid, nth);
    split_range(Wk, g_wkh, g_wkl, DIM*DIM, tid, nth);
    split_range(Wv, g_wvh, g_wvl, DIM*DIM, tid, nth);
    split_range(Wq, g_wqh, g_wql, DIM*DIM, tid, nth);
    split_range(keys0, g_k0h, g_k0l, NSLOT*DIM, tid, nth);
}

// vb fp16 transpose split + lb + rowsum init
__global__ void tsplit_vb()
{
    __shared__ float t[32][33];
    int x = threadIdx.x, y = threadIdx.y;
    int nb = blockIdx.x * 32, db = blockIdx.y * 32;
#pragma unroll
    for (int j = 0; j < 4; j++)
        t[y + 8*j][x] = g_vb[(size_t)(nb + y + 8*j)*DIM + db + x];
    __syncthreads();
#pragma unroll
    for (int j = 0; j < 4; j++){
        float v = t[x][y + 8*j];
        __half hi = __float2half_rn(v);
        size_t o = (size_t)(db + y + 8*j)*NSLOT + nb + x;
        g_vth[o] = hi;
        g_vtl[o] = __float2half_rn(v - __half2float(hi));
    }
    if (blockIdx.x == 0 && blockIdx.y == 0){
        int tid = y * 32 + x;
        for (int n = tid; n < T_TOK; n += 256) g_rowsum[n] = 0.f;
        for (int n = tid; n < NSLOT; n += 256){
            float a = g_act[n];
            g_lb[n] = (a < 0.01f) ? -1e30f : logf(a);
        }
    }
}

// ---------------- parallel scan: trajectory sort ---------------------------
#define SP_SMEM (131072 + 32768 + 16384 + 64)
__global__ __launch_bounds__(1024) void scan_par(const float* __restrict__ act0,
                                                 const void* __restrict__ maskptr)
{
    extern __shared__ char sm[];
    u64* keys = (u64*)sm;
    u32* ml   = (u32*)(sm + 131072);
    int* cnt  = (int*)(sm + 131072 + 32768);
    int* ctl  = (int*)(sm + 131072 + 32768 + 16384);
    int tid = threadIdx.x;
    if (tid == 0){ ctl[0] = 0; }
    __syncthreads();

    const u64* cm = g_simflag ? g_cmax2 : g_cmax;
    const unsigned* w = (const unsigned*)maskptr;
    bool bytemode = (w[0] == 0x01010101u);

    u32 inf8[8]; int myc = 0;
    int base = tid * 8;
#pragma unroll
    for (int j = 0; j < 8; j++){
        int t = base + j;
        u64 c = cm[t];
        float best = funmap((u32)(c >> 32));
        int bi = (int)(~(u32)c) & 0xFFFF;
        bool novel = (best * 0.0625f) < 0.5f;
        bool m = bytemode ? (((const unsigned char*)maskptr)[t] != 0) : (w[t] != 0);
        u32 inf = (u32)bi | (novel ? 0x10000u : 0u) | (m ? 0x20000u : 0u);
        g_info[t] = inf;
        inf8[j] = inf;
        if ((inf & 0x30000u) == 0x20000u) atomicOr(&ctl[0], 1);
        if (inf & 0x20000u) myc++;
    }
    for (int s = tid; s < NSLOT; s += 1024){
        float a = act0[s];
        if (!(a >= 0.0f)) atomicOr(&ctl[0], 1);
    }
    cnt[tid] = myc;
    __syncthreads();
    for (int off = 1; off < 1024; off <<= 1){
        int v = (tid >= off) ? cnt[tid - off] : 0;
        __syncthreads();
        cnt[tid] += v;
        __syncthreads();
    }
    int mybase = cnt[tid] - myc;
    int m_count = cnt[1023];
    {
        int wr = mybase;
#pragma unroll
        for (int j = 0; j < 8; j++)
            if (inf8[j] & 0x20000u) ml[wr++] = base + j;
    }
    __syncthreads();

    u32 lov = 0, hiv = 0x3F7FFFFFu;
    for (int pass = 0; pass < 2 || lov < hiv; ){
        u32 mid = (pass < 2) ? hiv : lov + ((hiv - lov) >> 1);
        float V = __uint_as_float(mid);
        __syncthreads();
        if (tid == 0) ctl[1] = 0;
        __syncthreads();
        int c = 0;
        for (int s = tid; s < NSLOT; s += 1024){
            float v = act0[s]; int g = 0;
            while (v < 1.0f && v <= V && g < 64){ c++; g++; v = fminf(1.0f, v + 0.1f); }
        }
#pragma unroll
        for (int o = 16; o; o >>= 1) c += __shfl_xor_sync(FULLM, c, o);
        if ((tid & 31) == 0) atomicAdd(&ctl[1], c);
        __syncthreads();
        int tot = ctl[1];
        if (pass < 2){
            if (pass == 0 && tot < m_count){ if (tid == 0) ctl[0] = 1; }
            pass = 2;
            if (ctl[0]) break;
            if (tot >= m_count) ; else lov = hiv;
        } else {
            if (tot >= m_count) hiv = mid; else lov = mid + 1;
        }
    }
    __syncthreads();
    if (ctl[0]){ if (tid == 0) g_scanflag = 1; return; }
    if (tid == 0) g_scanflag = 0;
    float Vf = __uint_as_float(hiv);

    if (tid == 0) ctl[2] = 0;
    for (int i = tid; i < 16384; i += 1024) keys[i] = ~0ull;
    __syncthreads();
    for (int s = tid; s < NSLOT; s += 1024){
        float v = act0[s]; int g = 0;
        while (v < 1.0f && v <= Vf && g < 64){
            int pos = atomicAdd(&ctl[2], 1);
            keys[pos] = ((u64)__float_as_uint(v) << 32) | (u32)s;
            v = fminf(1.0f, v + 0.1f); g++;
        }
    }
    __syncthreads();

    for (u32 k2 = 2; k2 <= 16384; k2 <<= 1){
        for (u32 j = k2 >> 1; j > 0; j >>= 1){
            for (u32 i = tid; i < 16384; i += 1024){
                u32 ixj = i ^ j;
                if (ixj > i){
                    u64 a = keys[i], b = keys[ixj];
                    bool up = ((i & k2) == 0);
                    if ((a > b) == up){ keys[i] = b; keys[ixj] = a; }
                }
            }
            __syncthreads();
        }
    }

    for (int r = tid; r < m_count; r += 1024){
        u32 slot = (u32)keys[r] & 0xFFFFu;
        g_pick[ml[r]] = slot | 0x30000u;
    }
#pragma unroll
    for (int j = 0; j < 8; j++)
        if (!(inf8[j] & 0x20000u)) g_pick[base + j] = 0u;
    for (int i = tid; i < NSLOT; i += 1024) cnt[i] = 0;
    __syncthreads();
    for (int r = tid; r < m_count; r += 1024)
        atomicAdd(&cnt[(u32)keys[r] & 0xFFFFu], 1);
    __syncthreads();
    for (int s = tid; s < NSLOT; s += 1024){
        float v = act0[s]; int k = cnt[s];
        for (int j = 0; j < k; j++) v = fminf(1.0f, v + 0.1f);
        g_act[s] = v;
    }
}

// ---------------- slow exact scan (fallback, flag-gated) -------------------
__global__ __launch_bounds__(256) void scan_kernel(const float* __restrict__ act0)
{
    if (g_scanflag == 0) return;
    __shared__ __align__(16) float s_act[NSLOT];
    __shared__ __align__(16) float s_gmin[128];
    __shared__ int s_gidx[128];
    int tid = threadIdx.x;
    for (int i = tid; i < NSLOT; i += 256) s_act[i] = act0[i];
    __syncthreads();
    int wid = tid >> 5, lane = tid & 31;
    for (int g = wid; g < 128; g += 8){
        float v = s_act[g * 32 + lane];
        unsigned mv = __reduce_min_sync(FULLM, __float_as_uint(v));
        unsigned bal = __ballot_sync(FULLM, __float_as_uint(v) == mv);
        if (lane == 0){ s_gmin[g] = __uint_as_float(mv); s_gidx[g] = g * 32 + (__ffs(bal) - 1); }
    }
    __syncthreads();
    if (wid == 0){
        unsigned myinfo = 0;
        for (int t = 0; t < T_TOK; t++){
            if ((t & 31) == 0) myinfo = __ldg(&g_info[t + lane]);
            unsigned info = __shfl_sync(FULLM, myinfo, t & 31);
            if (info & 0x20000u){
                int slot;
                if (info & 0x10000u){
                    float4 q4 = *(const float4*)&s_gmin[lane * 4];
                    float bv = q4.x; int bg = lane * 4;
                    if (q4.y < bv){ bv = q4.y; bg = lane * 4 + 1; }
                    if (q4.z < bv){ bv = q4.z; bg = lane * 4 + 2; }
                    if (q4.w < bv){ bv = q4.w; bg = lane * 4 + 3; }
                    unsigned mv = __reduce_min_sync(FULLM, __float_as_uint(bv));
                    unsigned bal = __ballot_sync(FULLM, __float_as_uint(bv) == mv);
                    int L = __ffs(bal) - 1;
                    int grp = __shfl_sync(FULLM, bg, L);
                    slot = s_gidx[grp];
                } else {
                    slot = (int)(info & 0xFFFFu);
                }
                float na = fminf(1.0f, s_act[slot] + 0.1f);
                if (lane == 0) s_act[slot] = na;
                __syncwarp();
                int g = slot >> 5;
                float v = s_act[g * 32 + lane];
                unsigned mv2 = __reduce_min_sync(FULLM, __float_as_uint(v));
                unsigned bal2 = __ballot_sync(FULLM, __float_as_uint(v) == mv2);
                if (lane == 0){
                    s_gmin[g] = __uint_as_float(mv2);
                    s_gidx[g] = g * 32 + (__ffs(bal2) - 1);
                    g_pick[t] = (unsigned)slot | (info & 0x10000u) | 0x20000u;
                }
                __syncwarp();
            } else {
                if (lane == 0) g_pick[t] = 0u;
            }
        }
    }
    __syncthreads();
    for (int i = tid; i < NSLOT; i += 256) g_act[i] = s_act[i];
}

// ---------------- rebuild: EMA replay + direct fp16 kb split ---------------
__global__ __launch_bounds__(256) void rebuild_kernel(
    const float* __restrict__ keys0, const float* __restrict__ values0)
{
    int wid = threadIdx.x >> 5, lane = threadIdx.x & 31;
    int s = blockIdx.x * 8 + wid;
    float kreg[8], vreg[8];
#pragma unroll
    for (int r = 0; r < 8; r++){
        kreg[r] = keys0[s * DIM + lane + 32 * r];
        vreg[r] = values0[s * DIM + lane + 32 * r];
    }
    for (int base = 0; base < T_TOK; base += 32){
        unsigned pk = __ldg(&g_pick[base + lane]);
        unsigned match = __ballot_sync(FULLM,
            (pk & 0x20000u) && ((pk & 0xFFFFu) == (unsigned)s));
        while (match){
            int bl = __ffs(match) - 1;
            match &= match - 1;
            unsigned pkb = __shfl_sync(FULLM, pk, bl);
            float alpha = (pkb & 0x10000u) ? 0.9f : 0.3f;
            float om = 1.0f - alpha;
            int t = base + bl;
            const float* kr = &g_k[(size_t)t * DIM];
            const float* vr = &g_v[(size_t)t * DIM];
#pragma unroll
            for (int r = 0; r < 8; r++){
                kreg[r] = om * kreg[r] + alpha * __ldg(&kr[lane + 32 * r]);
                vreg[r] = om * vreg[r] + alpha * __ldg(&vr[lane + 32 * r]);
            }
        }
    }
#pragma unroll
    for (int r = 0; r < 8; r++){
        int d0 = s * DIM + lane + 32 * r;
        g_vb[d0] = vreg[r];
        __half hi = __float2half_rn(kreg[r]);
        g_kbh[d0] = hi;
        g_kbl[d0] = __float2half_rn(kreg[r] - __half2float(hi));
    }
}

// --------------------------------- launch --------------------------------
extern "C" void kernel_launch(void* const* d_in, const int* in_sizes, int n_in,
                              void* d_out, int out_size)
{
    const float* x     = (const float*)d_in[0];
    const void*  wmask = d_in[1];
    const float* keys0 = (const float*)d_in[2];
    const float* vals0 = (const float*)d_in[3];
    const float* act0  = (const float*)d_in[4];
    const float* Wk    = (const float*)d_in[5];
    const float* bk    = (const float*)d_in[6];
    const float* Wv    = (const float*)d_in[7];
    const float* bv    = (const float*)d_in[8];
    const float* Wq    = (const float*)d_in[9];
    const float* bq    = (const float*)d_in[10];
    float* out = (float*)d_out;

    cudaFuncSetAttribute(mm_gemm<3,false>, cudaFuncAttributeMaxDynamicSharedMemorySize, SMEMSZ);
    cudaFuncSetAttribute(mm_gemm<1,false>, cudaFuncAttributeMaxDynamicSharedMemorySize, SMEMSZ);
    cudaFuncSetAttribute(mm_gemm<2,true>,  cudaFuncAttributeMaxDynamicSharedMemorySize, SMEMSZ);
    cudaFuncSetAttribute(scan_par, cudaFuncAttributeMaxDynamicSharedMemorySize, SP_SMEM);

    splitAB_kernel<<<256, 256>>>(x, Wk, Wv, Wq, keys0, bk, bv, bq);

    mm_gemm<3,false><<<dim3(64,2,3), 256, SMEMSZ>>>(0);   // fused k/v/q projections
    mm_gemm<1,false><<<dim3(64,32), 256, SMEMSZ>>>(3);    // simmax 1-term + guard + atomic combine
    mm_gemm<3,false><<<dim3(64,32), 256, SMEMSZ>>>(6);    // exact simmax, flag-gated

    scan_par<<<1, 1024, SP_SMEM>>>(act0, wmask);          // info decode + trajectory-sort scan
    scan_kernel<<<1, 256>>>(act0);                        // exact fallback, flag-gated
    rebuild_kernel<<<NSLOT/8, 256>>>(keys0, vals0);       // EMA replay + fp16 kb split
    tsplit_vb<<<dim3(128,8), dim3(32,8)>>>();             // vb fp16 transpose split + lb/rowsum

    mm_gemm<2,true><<<dim3(64,32), 256, SMEMSZ>>>(4);     // attnA fp16 2-term: QK+exp+rowsum
    mm_gemm<2,true><<<dim3(64,2,4), 256, SMEMSZ>>>(5);    // attnC fp16 2-term splitK
    attnC_red<<<T_TOK*DIM/1024, 256>>>(out);
}

// round 14
// speedup vs baseline: 5.5759x; 1.0542x over previous
#include <cuda_runtime.h>
#include <cuda_bf16.h>
#include <cuda_fp16.h>
#include <math_constants.h>

#define T_TOK 8192
#define DIM   256
#define NSLOT 4096
#define FULLM 0xffffffffu
typedef unsigned int u32;
typedef unsigned long long u64;
typedef __nv_bfloat16 bf16;

// ---------------- scratch ----------------
__device__ float g_k[T_TOK * DIM];
__device__ float g_v[T_TOK * DIM];
__device__ u64   g_cmax[T_TOK];
__device__ u64   g_cmax2[T_TOK];
__device__ unsigned g_info[T_TOK];
__device__ unsigned g_pick[T_TOK];
__device__ float g_act[NSLOT];
__device__ float g_lb[NSLOT];
__device__ float g_bias[3 * DIM];
__device__ float g_vb[NSLOT * DIM];
__device__ float g_rowsum[T_TOK];
__device__ int   g_scanflag;
__device__ int   g_simflag;
__device__ float g_part[2 * T_TOK * DIM];

__device__ bf16 g_xhi[T_TOK*DIM], g_xlo[T_TOK*DIM];
__device__ bf16 g_khi[T_TOK*DIM], g_klo[T_TOK*DIM];
__device__ __half g_qh[T_TOK*DIM];
__device__ bf16 g_wkh[DIM*DIM], g_wkl[DIM*DIM];
__device__ bf16 g_wvh[DIM*DIM], g_wvl[DIM*DIM];
__device__ bf16 g_wqh[DIM*DIM], g_wql[DIM*DIM];
__device__ bf16 g_k0h[NSLOT*DIM], g_k0l[NSLOT*DIM];
__device__ __half g_kbh[NSLOT*DIM], g_kbl[NSLOT*DIM];
__device__ __half g_vth[DIM*NSLOT], g_vtl[DIM*NSLOT];
__device__ __half g_Eh[(size_t)T_TOK*NSLOT];

// ---------------- helpers ----------------
__device__ __forceinline__ u32 cvta_sm(const void* p){
    u32 a; asm("{.reg .u64 t; cvta.to.shared.u64 t, %1; cvt.u32.u64 %0, t;}" : "=r"(a) : "l"(p));
    return a;
}
__device__ __forceinline__ u32 fmap(float f){
    u32 b = __float_as_uint(f);
    return (b & 0x80000000u) ? ~b : (b | 0x80000000u);
}
__device__ __forceinline__ float funmap(u32 u){
    u32 b = (u & 0x80000000u) ? (u ^ 0x80000000u) : ~u;
    return __uint_as_float(b);
}
#define CPA(dst, src) asm volatile("cp.async.cg.shared.global [%0], [%1], 16;" :: "r"(dst), "l"(src))
#define CPCOMMIT()    asm volatile("cp.async.commit_group;" ::: "memory")
#define CPWAIT1()     asm volatile("cp.async.wait_group 1;" ::: "memory")
#define CPWAIT0()     asm volatile("cp.async.wait_group 0;" ::: "memory")
#define LDX4(r, a) asm volatile("ldmatrix.sync.aligned.m8n8.x4.shared.b16 {%0,%1,%2,%3}, [%4];" \
    : "=r"((r)[0]), "=r"((r)[1]), "=r"((r)[2]), "=r"((r)[3]) : "r"(a))
#define MMAB(D, A, B0, B1) asm volatile( \
    "mma.sync.aligned.m16n8k16.row.col.f32.bf16.bf16.f32 " \
    "{%0,%1,%2,%3}, {%4,%5,%6,%7}, {%8,%9}, {%0,%1,%2,%3};" \
    : "+f"((D)[0]), "+f"((D)[1]), "+f"((D)[2]), "+f"((D)[3]) \
    : "r"((A)[0]), "r"((A)[1]), "r"((A)[2]), "r"((A)[3]), "r"(B0), "r"(B1))
#define MMAH(D, A, B0, B1) asm volatile( \
    "mma.sync.aligned.m16n8k16.row.col.f32.f16.f16.f32 " \
    "{%0,%1,%2,%3}, {%4,%5,%6,%7}, {%8,%9}, {%0,%1,%2,%3};" \
    : "+f"((D)[0]), "+f"((D)[1]), "+f"((D)[2]), "+f"((D)[3]) \
    : "r"((A)[0]), "r"((A)[1]), "r"((A)[2]), "r"((A)[3]), "r"(B0), "r"(B1))

#define PITCH 80
#define ABUF  10240
#define BUFSZ 40960
#define SMEMSZ 81920
#define SHIFTC 1.0f

// ---------------- universal mma.sync GEMM ----------------
// TERMS=3 bf16 (proj / simmax-exact), TERMS=1 bf16 (simmax+guard),
// TERMS=1 fp16 (attnA: A=qh, B=kbh), TERMS=2 fp16 (attnC: A=E, B=vth+vtl)
// mode: 0 fused proj (z=k/v/q), 3 simmax, 4 attnA, 5 attnC splitK, 6 simmax exact
template<int TERMS, bool H>
__global__ __launch_bounds__(256, 2) void mm_gemm(int mode)
{
    if (mode == 6 && g_simflag == 0) return;
    const bool guard = (mode == 3) && (TERMS == 1);
    if (mode == 6) mode = 3;

    extern __shared__ char smx[];
    u32 smb = cvta_sm(smx);
    int tid = threadIdx.x, lane = tid & 31, wid = tid >> 5;
    int wm = wid >> 2, wn = wid & 3;
    int m0 = blockIdx.x * 128, n0 = blockIdx.y * 128;
    int bz = blockIdx.z;

    const void *pAh, *pAl, *pBh, *pBl; size_t lda, ldb; int K;
    float* out = 0; bf16 *oh = 0, *ol = 0;
    switch (mode){
    case 0:
        pAh = g_xhi; pAl = g_xlo; lda = ldb = DIM; K = DIM;
        if (bz == 0){ pBh=g_wkh; pBl=g_wkl; out=g_k; oh=g_khi; ol=g_klo; }
        else if (bz == 1){ pBh=g_wvh; pBl=g_wvl; out=g_v; }
        else { pBh=g_wqh; pBl=g_wql; }
        break;
    case 3: pAh=g_khi; pAl=g_klo; pBh=g_k0h; pBl=g_k0l; lda=ldb=DIM; K=DIM; break;
    case 4: pAh=g_qh;  pAl=g_qh;  pBh=g_kbh; pBl=g_kbl; lda=ldb=DIM; K=DIM; break;
    default: pAh=g_Eh; pAl=g_Eh; pBh=g_vth; pBl=g_vtl; lda=ldb=NSLOT; K=NSLOT;
             out=g_part + (size_t)bz * T_TOK * DIM; break;
    }
    int Kper = (mode == 5) ? K / gridDim.z : K;
    size_t kbase = (mode == 5) ? (size_t)bz * Kper * 2 : 0;
    const char* gsrc[4];
    gsrc[0] = (const char*)pAh + (size_t)m0*lda*2 + kbase;
    gsrc[1] = (const char*)pAl + (size_t)m0*lda*2 + kbase;
    gsrc[2] = (const char*)pBh + (size_t)n0*ldb*2 + kbase;
    gsrc[3] = (const char*)pBl + (size_t)n0*ldb*2 + kbase;
    size_t rstA = lda*2, rstB = ldb*2;

    int a_ro = (lane & 7) + ((lane & 8) ? 8 : 0);
    int a_ko = (lane & 16) ? 8 : 0;
    int b_ro = (lane & 7) + ((lane & 16) ? 8 : 0);
    int b_ko = (lane & 8) ? 8 : 0;

    float d[4][4][4] = {};
    int nk = Kper / 32;
    {
        int row = (tid >> 2), kc = tid & 3;
#pragma unroll
        for (int arr = 0; arr < 4; arr++){
            if ((TERMS == 1 && (arr & 1)) || (TERMS == 2 && arr == 1)) continue;
            size_t rs = (arr < 2) ? rstA : rstB;
            u32 db = smb + arr*ABUF;
            CPA(db + (u32)row*PITCH + kc*16, gsrc[arr] + (size_t)row*rs + kc*16);
            CPA(db + (u32)(row+64)*PITCH + kc*16, gsrc[arr] + (size_t)(row+64)*rs + kc*16);
        }
        CPCOMMIT();
    }

    for (int ck = 0; ck < nk; ck++){
        if (ck + 1 < nk){
            int row = (tid >> 2), kc = tid & 3;
            size_t koff = (size_t)(ck + 1) * 64;
            u32 db = smb + ((ck + 1) & 1) * BUFSZ;
#pragma unroll
            for (int arr = 0; arr < 4; arr++){
                if ((TERMS == 1 && (arr & 1)) || (TERMS == 2 && arr == 1)) continue;
                size_t rs = (arr < 2) ? rstA : rstB;
                const char* s = gsrc[arr] + koff;
                CPA(db + arr*ABUF + (u32)row*PITCH + kc*16, s + (size_t)row*rs + kc*16);
                CPA(db + arr*ABUF + (u32)(row+64)*PITCH + kc*16, s + (size_t)(row+64)*rs + kc*16);
            }
            CPCOMMIT();
            CPWAIT1();
        } else {
            CPWAIT0();
        }
        __syncthreads();
        u32 bb = smb + (ck & 1) * BUFSZ;
#pragma unroll
        for (int ks = 0; ks < 2; ks++){
            u32 Abase = bb + (u32)(wm*64 + a_ro)*PITCH + (ks*16 + a_ko)*2;
            u32 Bbase = bb + 2*ABUF + (u32)(wn*32 + b_ro)*PITCH + (ks*16 + b_ko)*2;
            u32 bh[2][4], a[4][4];
            LDX4(bh[0], Bbase); LDX4(bh[1], Bbase + 16*PITCH);
#pragma unroll
            for (int ma = 0; ma < 4; ma++) LDX4(a[ma], Abase + ma*16*PITCH);
#pragma unroll
            for (int ma = 0; ma < 4; ma++)
#pragma unroll
                for (int na = 0; na < 4; na++){
                    if (H) MMAH(d[ma][na], a[ma], bh[na>>1][(na&1)*2], bh[na>>1][(na&1)*2+1]);
                    else   MMAB(d[ma][na], a[ma], bh[na>>1][(na&1)*2], bh[na>>1][(na&1)*2+1]);
                }
            if (TERMS >= 2){
                u32 blr[2][4];
                LDX4(blr[0], Bbase + ABUF); LDX4(blr[1], Bbase + ABUF + 16*PITCH);
#pragma unroll
                for (int ma = 0; ma < 4; ma++)
#pragma unroll
                    for (int na = 0; na < 4; na++){
                        if (H) MMAH(d[ma][na], a[ma], blr[na>>1][(na&1)*2], blr[na>>1][(na&1)*2+1]);
                        else   MMAB(d[ma][na], a[ma], blr[na>>1][(na&1)*2], blr[na>>1][(na&1)*2+1]);
                    }
            }
            if (TERMS == 3){
                u32 a2[4][4];
#pragma unroll
                for (int ma = 0; ma < 4; ma++) LDX4(a2[ma], Abase + ABUF + ma*16*PITCH);
#pragma unroll
                for (int ma = 0; ma < 4; ma++)
#pragma unroll
                    for (int na = 0; na < 4; na++)
                        MMAB(d[ma][na], a2[ma], bh[na>>1][(na&1)*2], bh[na>>1][(na&1)*2+1]);
            }
        }
        __syncthreads();
    }

    int qr = lane >> 2, qc = lane & 3;

    if (mode == 0){
        const float* bias = g_bias + bz * DIM;
#pragma unroll
        for (int ma = 0; ma < 4; ma++)
#pragma unroll
            for (int rs = 0; rs < 2; rs++){
                int row = m0 + wm*64 + ma*16 + rs*8 + qr;
#pragma unroll
                for (int na = 0; na < 4; na++){
                    int cg = n0 + wn*32 + na*8 + 2*qc;
                    float v0 = d[ma][na][rs*2]   + bias[cg];
                    float v1 = d[ma][na][rs*2+1] + bias[cg+1];
                    if (bz == 2){
                        *(__half2*)&g_qh[(size_t)row*DIM + cg] = __floats2half2_rn(v0, v1);
                    } else {
                        *(float2*)&out[(size_t)row*DIM + cg] = make_float2(v0, v1);
                        if (bz == 0){
                            bf16 h0 = __float2bfloat16(v0), h1 = __float2bfloat16(v1);
                            *(__nv_bfloat162*)&oh[(size_t)row*DIM+cg] = __nv_bfloat162(h0, h1);
                            *(__nv_bfloat162*)&ol[(size_t)row*DIM+cg] = __nv_bfloat162(
                                __float2bfloat16(v0 - __bfloat162float(h0)),
                                __float2bfloat16(v1 - __bfloat162float(h1)));
                        }
                    }
                }
            }
    } else if (mode == 3){
        u64* cm = guard ? g_cmax : g_cmax2;
#pragma unroll
        for (int ma = 0; ma < 4; ma++)
#pragma unroll
            for (int rs = 0; rs < 2; rs++){
                int row = m0 + wm*64 + ma*16 + rs*8 + qr;
                float bv = -CUDART_INF_F; int bi = 0x7fffffff;
#pragma unroll
                for (int na = 0; na < 4; na++)
#pragma unroll
                    for (int e = 0; e < 2; e++){
                        float v = d[ma][na][rs*2+e];
                        int col = n0 + wn*32 + na*8 + 2*qc + e;
                        if (v > bv){ bv = v; bi = col; }
                    }
#pragma unroll
                for (int o = 1; o < 4; o <<= 1){
                    float ov = __shfl_xor_sync(FULLM, bv, o);
                    int   oi = __shfl_xor_sync(FULLM, bi, o);
                    if (ov > bv || (ov == bv && oi < bi)){ bv = ov; bi = oi; }
                }
                if (qc == 0){
                    atomicMax(&cm[row], ((u64)fmap(bv) << 32) | (u32)(~(u32)bi));
                    if (guard && bv >= 7.4f) atomicOr(&g_simflag, 1);
                }
            }
    } else if (mode == 4){
#pragma unroll
        for (int ma = 0; ma < 4; ma++)
#pragma unroll
            for (int rs = 0; rs < 2; rs++){
                int row = m0 + wm*64 + ma*16 + rs*8 + qr;
                float rsum = 0.f;
#pragma unroll
                for (int na = 0; na < 4; na++){
                    int cg = n0 + wn*32 + na*8 + 2*qc;
                    float e0 = __expf(d[ma][na][rs*2]  *0.0625f + g_lb[cg]   - SHIFTC);
                    float e1 = __expf(d[ma][na][rs*2+1]*0.0625f + g_lb[cg+1] - SHIFTC);
                    rsum += e0 + e1;
                    *(__half2*)&g_Eh[(size_t)row*NSLOT + cg] = __floats2half2_rn(e0, e1);
                }
                rsum += __shfl_xor_sync(FULLM, rsum, 1);
                rsum += __shfl_xor_sync(FULLM, rsum, 2);
                if (qc == 0) atomicAdd(&g_rowsum[row], rsum);
            }
    } else {
#pragma unroll
        for (int ma = 0; ma < 4; ma++)
#pragma unroll
            for (int rs = 0; rs < 2; rs++){
                int row = m0 + wm*64 + ma*16 + rs*8 + qr;
#pragma unroll
                for (int na = 0; na < 4; na++){
                    int cg = n0 + wn*32 + na*8 + 2*qc;
                    *(float2*)&out[(size_t)row*DIM + cg] =
                        make_float2(d[ma][na][rs*2], d[ma][na][rs*2+1]);
                }
            }
    }
}

// ---------------- attnC reduce (2 partials) ----------------
__global__ void attnC_red(float* __restrict__ out)
{
    int i = blockIdx.x * blockDim.x + threadIdx.x;
    int row = i >> 6;
    float inv = 1.0f / g_rowsum[row];
    float4 s = *(float4*)&g_part[(size_t)i*4];
    float4 b = *(float4*)&g_part[(size_t)T_TOK*DIM + i*4];
    s.x = (s.x+b.x)*inv; s.y = (s.y+b.y)*inv;
    s.z = (s.z+b.z)*inv; s.w = (s.w+b.w)*inv;
    *(float4*)&out[(size_t)i*4] = s;
}

// ---------------- splits ----------------
__device__ __forceinline__ void split_range(const float* src, bf16* h, bf16* l, int n, int tid, int nth)
{
    for (int i = tid; i < n; i += nth){
        float v = src[i];
        bf16 hi = __float2bfloat16(v);
        h[i] = hi;
        l[i] = __float2bfloat16(v - __bfloat162float(hi));
    }
}
__global__ void splitAB_kernel(const float* __restrict__ x, const float* __restrict__ Wk,
                               const float* __restrict__ Wv, const float* __restrict__ Wq,
                               const float* __restrict__ keys0,
                               const float* __restrict__ bk, const float* __restrict__ bv,
                               const float* __restrict__ bq)
{
    int tid = blockIdx.x * blockDim.x + threadIdx.x;
    if (tid == 0) g_simflag = 0;
    int nth = gridDim.x * blockDim.x;
    if (tid < DIM){
        g_bias[tid] = bk[tid];
        g_bias[DIM + tid] = bv[tid];
        g_bias[2*DIM + tid] = bq[tid];
    }
    for (int t = tid; t < T_TOK; t += nth){ g_cmax[t] = 0ull; g_cmax2[t] = 0ull; }
    split_range(x, g_xhi, g_xlo, T_TOK*DIM, tid, nth);
    split_range(Wk, g_wkh, g_wkl, DIM*DIM, tid, nth);
    split_range(Wv, g_wvh, g_wvl, DIM*DIM, tid, nth);
    split_range(Wq, g_wqh, g_wql, DIM*DIM, tid, nth);
    split_range(keys0, g_k0h, g_k0l, NSLOT*DIM, tid, nth);
}

// vb fp16 transpose split + lb + rowsum init
__global__ void tsplit_vb()
{
    __shared__ float t[32][33];
    int x = threadIdx.x, y = threadIdx.y;
    int nb = blockIdx.x * 32, db = blockIdx.y * 32;
#pragma unroll
    for (int j = 0; j < 4; j++)
        t[y + 8*j][x] = g_vb[(size_t)(nb + y + 8*j)*DIM + db + x];
    __syncthreads();
#pragma unroll
    for (int j = 0; j < 4; j++){
        float v = t[x][y + 8*j];
        __half hi = __float2half_rn(v);
        size_t o = (size_t)(db + y + 8*j)*NSLOT + nb + x;
        g_vth[o] = hi;
        g_vtl[o] = __float2half_rn(v - __half2float(hi));
    }
    if (blockIdx.x == 0 && blockIdx.y == 0){
        int tid = y * 32 + x;
        for (int n = tid; n < T_TOK; n += 256) g_rowsum[n] = 0.f;
        for (int n = tid; n < NSLOT; n += 256){
            float a = g_act[n];
            g_lb[n] = (a < 0.01f) ? -1e30f : logf(a);
        }
    }
}

// ---------------- parallel scan: trajectory sort ---------------------------
#define SP_SMEM (131072 + 32768 + 16384 + 64)
__global__ __launch_bounds__(1024) void scan_par(const float* __restrict__ act0,
                                                 const void* __restrict__ maskptr)
{
    extern __shared__ char sm[];
    u64* keys = (u64*)sm;
    u32* ml   = (u32*)(sm + 131072);
    int* cnt  = (int*)(sm + 131072 + 32768);
    int* ctl  = (int*)(sm + 131072 + 32768 + 16384);
    int tid = threadIdx.x;
    if (tid == 0){ ctl[0] = 0; }
    __syncthreads();

    const u64* cm = g_simflag ? g_cmax2 : g_cmax;
    const unsigned* w = (const unsigned*)maskptr;
    bool bytemode = (w[0] == 0x01010101u);

    u32 inf8[8]; int myc = 0;
    int base = tid * 8;
#pragma unroll
    for (int j = 0; j < 8; j++){
        int t = base + j;
        u64 c = cm[t];
        float best = funmap((u32)(c >> 32));
        int bi = (int)(~(u32)c) & 0xFFFF;
        bool novel = (best * 0.0625f) < 0.5f;
        bool m = bytemode ? (((const unsigned char*)maskptr)[t] != 0) : (w[t] != 0);
        u32 inf = (u32)bi | (novel ? 0x10000u : 0u) | (m ? 0x20000u : 0u);
        g_info[t] = inf;
        inf8[j] = inf;
        if ((inf & 0x30000u) == 0x20000u) atomicOr(&ctl[0], 1);
        if (inf & 0x20000u) myc++;
    }
    for (int s = tid; s < NSLOT; s += 1024){
        float a = act0[s];
        if (!(a >= 0.0f)) atomicOr(&ctl[0], 1);
    }
    cnt[tid] = myc;
    __syncthreads();
    for (int off = 1; off < 1024; off <<= 1){
        int v = (tid >= off) ? cnt[tid - off] : 0;
        __syncthreads();
        cnt[tid] += v;
        __syncthreads();
    }
    int mybase = cnt[tid] - myc;
    int m_count = cnt[1023];
    {
        int wr = mybase;
#pragma unroll
        for (int j = 0; j < 8; j++)
            if (inf8[j] & 0x20000u) ml[wr++] = base + j;
    }
    __syncthreads();

    u32 lov = 0, hiv = 0x3F7FFFFFu;
    for (int pass = 0; pass < 2 || lov < hiv; ){
        u32 mid = (pass < 2) ? hiv : lov + ((hiv - lov) >> 1);
        float V = __uint_as_float(mid);
        __syncthreads();
        if (tid == 0) ctl[1] = 0;
        __syncthreads();
        int c = 0;
        for (int s = tid; s < NSLOT; s += 1024){
            float v = act0[s]; int g = 0;
            while (v < 1.0f && v <= V && g < 64){ c++; g++; v = fminf(1.0f, v + 0.1f); }
        }
#pragma unroll
        for (int o = 16; o; o >>= 1) c += __shfl_xor_sync(FULLM, c, o);
        if ((tid & 31) == 0) atomicAdd(&ctl[1], c);
        __syncthreads();
        int tot = ctl[1];
        if (pass < 2){
            if (pass == 0 && tot < m_count){ if (tid == 0) ctl[0] = 1; }
            pass = 2;
            if (ctl[0]) break;
            if (tot >= m_count) ; else lov = hiv;
        } else {
            if (tot >= m_count) hiv = mid; else lov = mid + 1;
        }
    }
    __syncthreads();
    if (ctl[0]){ if (tid == 0) g_scanflag = 1; return; }
    if (tid == 0) g_scanflag = 0;
    float Vf = __uint_as_float(hiv);

    if (tid == 0) ctl[2] = 0;
    for (int i = tid; i < 16384; i += 1024) keys[i] = ~0ull;
    __syncthreads();
    for (int s = tid; s < NSLOT; s += 1024){
        float v = act0[s]; int g = 0;
        while (v < 1.0f && v <= Vf && g < 64){
            int pos = atomicAdd(&ctl[2], 1);
            keys[pos] = ((u64)__float_as_uint(v) << 32) | (u32)s;
            v = fminf(1.0f, v + 0.1f); g++;
        }
    }
    __syncthreads();

    for (u32 k2 = 2; k2 <= 16384; k2 <<= 1){
        for (u32 j = k2 >> 1; j > 0; j >>= 1){
            for (u32 i = tid; i < 16384; i += 1024){
                u32 ixj = i ^ j;
                if (ixj > i){
                    u64 a = keys[i], b = keys[ixj];
                    bool up = ((i & k2) == 0);
                    if ((a > b) == up){ keys[i] = b; keys[ixj] = a; }
                }
            }
            __syncthreads();
        }
    }

    for (int r = tid; r < m_count; r += 1024){
        u32 slot = (u32)keys[r] & 0xFFFFu;
        g_pick[ml[r]] = slot | 0x30000u;
    }
#pragma unroll
    for (int j = 0; j < 8; j++)
        if (!(inf8[j] & 0x20000u)) g_pick[base + j] = 0u;
    for (int i = tid; i < NSLOT; i += 1024) cnt[i] = 0;
    __syncthreads();
    for (int r = tid; r < m_count; r += 1024)
        atomicAdd(&cnt[(u32)keys[r] & 0xFFFFu], 1);
    __syncthreads();
    for (int s = tid; s < NSLOT; s += 1024){
        float v = act0[s]; int k = cnt[s];
        for (int j = 0; j < k; j++) v = fminf(1.0f, v + 0.1f);
        g_act[s] = v;
    }
}

// ---------------- slow exact scan (fallback, flag-gated) -------------------
__global__ __launch_bounds__(256) void scan_kernel(const float* __restrict__ act0)
{
    if (g_scanflag == 0) return;
    __shared__ __align__(16) float s_act[NSLOT];
    __shared__ __align__(16) float s_gmin[128];
    __shared__ int s_gidx[128];
    int tid = threadIdx.x;
    for (int i = tid; i < NSLOT; i += 256) s_act[i] = act0[i];
    __syncthreads();
    int wid = tid >> 5, lane = tid & 31;
    for (int g = wid; g < 128; g += 8){
        float v = s_act[g * 32 + lane];
        unsigned mv = __reduce_min_sync(FULLM, __float_as_uint(v));
        unsigned bal = __ballot_sync(FULLM, __float_as_uint(v) == mv);
        if (lane == 0){ s_gmin[g] = __uint_as_float(mv); s_gidx[g] = g * 32 + (__ffs(bal) - 1); }
    }
    __syncthreads();
    if (wid == 0){
        unsigned myinfo = 0;
        for (int t = 0; t < T_TOK; t++){
            if ((t & 31) == 0) myinfo = __ldg(&g_info[t + lane]);
            unsigned info = __shfl_sync(FULLM, myinfo, t & 31);
            if (info & 0x20000u){
                int slot;
                if (info & 0x10000u){
                    float4 q4 = *(const float4*)&s_gmin[lane * 4];
                    float bv = q4.x; int bg = lane * 4;
                    if (q4.y < bv){ bv = q4.y; bg = lane * 4 + 1; }
                    if (q4.z < bv){ bv = q4.z; bg = lane * 4 + 2; }
                    if (q4.w < bv){ bv = q4.w; bg = lane * 4 + 3; }
                    unsigned mv = __reduce_min_sync(FULLM, __float_as_uint(bv));
                    unsigned bal = __ballot_sync(FULLM, __float_as_uint(bv) == mv);
                    int L = __ffs(bal) - 1;
                    int grp = __shfl_sync(FULLM, bg, L);
                    slot = s_gidx[grp];
                } else {
                    slot = (int)(info & 0xFFFFu);
                }
                float na = fminf(1.0f, s_act[slot] + 0.1f);
                if (lane == 0) s_act[slot] = na;
                __syncwarp();
                int g = slot >> 5;
                float v = s_act[g * 32 + lane];
                unsigned mv2 = __reduce_min_sync(FULLM, __float_as_uint(v));
                unsigned bal2 = __ballot_sync(FULLM, __float_as_uint(v) == mv2);
                if (lane == 0){
                    s_gmin[g] = __uint_as_float(mv2);
                    s_gidx[g] = g * 32 + (__ffs(bal2) - 1);
                    g_pick[t] = (unsigned)slot | (info & 0x10000u) | 0x20000u;
                }
                __syncwarp();
            } else {
                if (lane == 0) g_pick[t] = 0u;
            }
        }
    }
    __syncthreads();
    for (int i = tid; i < NSLOT; i += 256) g_act[i] = s_act[i];
}

// ---------------- rebuild: EMA replay + direct fp16 kb split ---------------
__global__ __launch_bounds__(256) void rebuild_kernel(
    const float* __restrict__ keys0, const float* __restrict__ values0)
{
    int wid = threadIdx.x >> 5, lane = threadIdx.x & 31;
    int s = blockIdx.x * 8 + wid;
    float kreg[8], vreg[8];
#pragma unroll
    for (int r = 0; r < 8; r++){
        kreg[r] = keys0[s * DIM + lane + 32 * r];
        vreg[r] = values0[s * DIM + lane + 32 * r];
    }
    for (int base = 0; base < T_TOK; base += 32){
        unsigned pk = __ldg(&g_pick[base + lane]);
        unsigned match = __ballot_sync(FULLM,
            (pk & 0x20000u) && ((pk & 0xFFFFu) == (unsigned)s));
        while (match){
            int bl = __ffs(match) - 1;
            match &= match - 1;
            unsigned pkb = __shfl_sync(FULLM, pk, bl);
            float alpha = (pkb & 0x10000u) ? 0.9f : 0.3f;
            float om = 1.0f - alpha;
            int t = base + bl;
            const float* kr = &g_k[(size_t)t * DIM];
            const float* vr = &g_v[(size_t)t * DIM];
#pragma unroll
            for (int r = 0; r < 8; r++){
                kreg[r] = om * kreg[r] + alpha * __ldg(&kr[lane + 32 * r]);
                vreg[r] = om * vreg[r] + alpha * __ldg(&vr[lane + 32 * r]);
            }
        }
    }
#pragma unroll
    for (int r = 0; r < 8; r++){
        int d0 = s * DIM + lane + 32 * r;
        g_vb[d0] = vreg[r];
        __half hi = __float2half_rn(kreg[r]);
        g_kbh[d0] = hi;
        g_kbl[d0] = __float2half_rn(kreg[r] - __half2float(hi));
    }
}

// --------------------------------- launch --------------------------------
extern "C" void kernel_launch(void* const* d_in, const int* in_sizes, int n_in,
                              void* d_out, int out_size)
{
    const float* x     = (const float*)d_in[0];
    const void*  wmask = d_in[1];
    const float* keys0 = (const float*)d_in[2];
    const float* vals0 = (const float*)d_in[3];
    const float* act0  = (const float*)d_in[4];
    const float* Wk    = (const float*)d_in[5];
    const float* bk    = (const float*)d_in[6];
    const float* Wv    = (const float*)d_in[7];
    const float* bv    = (const float*)d_in[8];
    const float* Wq    = (const float*)d_in[9];
    const float* bq    = (const float*)d_in[10];
    float* out = (float*)d_out;

    cudaFuncSetAttribute(mm_gemm<3,false>, cudaFuncAttributeMaxDynamicSharedMemorySize, SMEMSZ);
    cudaFuncSetAttribute(mm_gemm<1,false>, cudaFuncAttributeMaxDynamicSharedMemorySize, SMEMSZ);
    cudaFuncSetAttribute(mm_gemm<1,true>,  cudaFuncAttributeMaxDynamicSharedMemorySize, SMEMSZ);
    cudaFuncSetAttribute(mm_gemm<2,true>,  cudaFuncAttributeMaxDynamicSharedMemorySize, SMEMSZ);
    cudaFuncSetAttribute(scan_par, cudaFuncAttributeMaxDynamicSharedMemorySize, SP_SMEM);

    splitAB_kernel<<<256, 256>>>(x, Wk, Wv, Wq, keys0, bk, bv, bq);

    mm_gemm<3,false><<<dim3(64,2,3), 256, SMEMSZ>>>(0);   // fused k/v/q projections
    mm_gemm<1,false><<<dim3(64,32), 256, SMEMSZ>>>(3);    // simmax 1-term + guard + atomic combine
    mm_gemm<3,false><<<dim3(64,32), 256, SMEMSZ>>>(6);    // exact simmax, flag-gated

    scan_par<<<1, 1024, SP_SMEM>>>(act0, wmask);          // info decode + trajectory-sort scan
    scan_kernel<<<1, 256>>>(act0);                        // exact fallback, flag-gated
    rebuild_kernel<<<NSLOT/8, 256>>>(keys0, vals0);       // EMA replay + fp16 kb split
    tsplit_vb<<<dim3(128,8), dim3(32,8)>>>();             // vb fp16 transpose split + lb/rowsum

    mm_gemm<1,true><<<dim3(64,32), 256, SMEMSZ>>>(4);     // attnA fp16 1-term: QK+exp+rowsum
    mm_gemm<2,true><<<dim3(64,2,2), 256, SMEMSZ>>>(5);    // attnC fp16 2-term splitK=2
    attnC_red<<<T_TOK*DIM/1024, 256>>>(out);
}

// round 15
// speedup vs baseline: 5.9454x; 1.0663x over previous
#include <cuda_runtime.h>
#include <cuda_bf16.h>
#include <cuda_fp16.h>
#include <math_constants.h>

#define T_TOK 8192
#define DIM   256
#define NSLOT 4096
#define FULLM 0xffffffffu
typedef unsigned int u32;
typedef unsigned long long u64;
typedef __nv_bfloat16 bf16;

// ---------------- scratch ----------------
__device__ float g_k[T_TOK * DIM];
__device__ float g_v[T_TOK * DIM];
__device__ u64   g_cmax[T_TOK];
__device__ u64   g_cmax2[T_TOK];
__device__ unsigned g_info[T_TOK];
__device__ unsigned g_pick[T_TOK];
__device__ float g_act[NSLOT];
__device__ float g_lb[NSLOT];
__device__ float g_bias[3 * DIM];
__device__ float g_vb[NSLOT * DIM];
__device__ float g_rowsum[T_TOK];
__device__ int   g_scanflag;
__device__ int   g_simflag;
__device__ float g_part[2 * T_TOK * DIM];

__device__ bf16 g_xhi[T_TOK*DIM], g_xlo[T_TOK*DIM];
__device__ bf16 g_khi[T_TOK*DIM], g_klo[T_TOK*DIM];
__device__ __half g_qh[T_TOK*DIM];
__device__ bf16 g_wkh[DIM*DIM], g_wkl[DIM*DIM];
__device__ bf16 g_wvh[DIM*DIM], g_wvl[DIM*DIM];
__device__ bf16 g_wqh[DIM*DIM], g_wql[DIM*DIM];
__device__ bf16 g_k0h[NSLOT*DIM], g_k0l[NSLOT*DIM];
__device__ __half g_kbh[NSLOT*DIM], g_kbl[NSLOT*DIM];
__device__ __half g_vth[DIM*NSLOT];
__device__ __half g_Eh[(size_t)T_TOK*NSLOT];

// ---------------- helpers ----------------
__device__ __forceinline__ u32 cvta_sm(const void* p){
    u32 a; asm("{.reg .u64 t; cvta.to.shared.u64 t, %1; cvt.u32.u64 %0, t;}" : "=r"(a) : "l"(p));
    return a;
}
__device__ __forceinline__ u32 fmap(float f){
    u32 b = __float_as_uint(f);
    return (b & 0x80000000u) ? ~b : (b | 0x80000000u);
}
__device__ __forceinline__ float funmap(u32 u){
    u32 b = (u & 0x80000000u) ? (u ^ 0x80000000u) : ~u;
    return __uint_as_float(b);
}
#define CPA(dst, src) asm volatile("cp.async.cg.shared.global [%0], [%1], 16;" :: "r"(dst), "l"(src))
#define CPCOMMIT()    asm volatile("cp.async.commit_group;" ::: "memory")
#define CPWAIT1()     asm volatile("cp.async.wait_group 1;" ::: "memory")
#define CPWAIT0()     asm volatile("cp.async.wait_group 0;" ::: "memory")
#define LDX4(r, a) asm volatile("ldmatrix.sync.aligned.m8n8.x4.shared.b16 {%0,%1,%2,%3}, [%4];" \
    : "=r"((r)[0]), "=r"((r)[1]), "=r"((r)[2]), "=r"((r)[3]) : "r"(a))
#define MMAB(D, A, B0, B1) asm volatile( \
    "mma.sync.aligned.m16n8k16.row.col.f32.bf16.bf16.f32 " \
    "{%0,%1,%2,%3}, {%4,%5,%6,%7}, {%8,%9}, {%0,%1,%2,%3};" \
    : "+f"((D)[0]), "+f"((D)[1]), "+f"((D)[2]), "+f"((D)[3]) \
    : "r"((A)[0]), "r"((A)[1]), "r"((A)[2]), "r"((A)[3]), "r"(B0), "r"(B1))
#define MMAH(D, A, B0, B1) asm volatile( \
    "mma.sync.aligned.m16n8k16.row.col.f32.f16.f16.f32 " \
    "{%0,%1,%2,%3}, {%4,%5,%6,%7}, {%8,%9}, {%0,%1,%2,%3};" \
    : "+f"((D)[0]), "+f"((D)[1]), "+f"((D)[2]), "+f"((D)[3]) \
    : "r"((A)[0]), "r"((A)[1]), "r"((A)[2]), "r"((A)[3]), "r"(B0), "r"(B1))

#define PITCH 80
#define ABUF  10240
#define BUFSZ 40960
#define SMEMSZ 81920
#define SHIFTC 1.0f

// ---------------- universal mma.sync GEMM ----------------
// TERMS=3 bf16 (proj / simmax-exact), TERMS=1 bf16 (simmax+guard),
// TERMS=1 fp16 (attnA: A=qh,B=kbh; attnC: A=E,B=vth), TERMS=2 fp16 (unused spare)
// mode: 0 fused proj (z=k/v/q), 3 simmax, 4 attnA, 5 attnC splitK, 6 simmax exact
template<int TERMS, bool H>
__global__ __launch_bounds__(256, 2) void mm_gemm(int mode)
{
    if (mode == 6 && g_simflag == 0) return;
    const bool guard = (mode == 3) && (TERMS == 1);
    if (mode == 6) mode = 3;

    extern __shared__ char smx[];
    u32 smb = cvta_sm(smx);
    int tid = threadIdx.x, lane = tid & 31, wid = tid >> 5;
    int wm = wid >> 2, wn = wid & 3;
    int m0 = blockIdx.x * 128, n0 = blockIdx.y * 128;
    int bz = blockIdx.z;

    const void *pAh, *pAl, *pBh, *pBl; size_t lda, ldb; int K;
    float* out = 0; bf16 *oh = 0, *ol = 0;
    switch (mode){
    case 0:
        pAh = g_xhi; pAl = g_xlo; lda = ldb = DIM; K = DIM;
        if (bz == 0){ pBh=g_wkh; pBl=g_wkl; out=g_k; oh=g_khi; ol=g_klo; }
        else if (bz == 1){ pBh=g_wvh; pBl=g_wvl; out=g_v; }
        else { pBh=g_wqh; pBl=g_wql; }
        break;
    case 3: pAh=g_khi; pAl=g_klo; pBh=g_k0h; pBl=g_k0l; lda=ldb=DIM; K=DIM; break;
    case 4: pAh=g_qh;  pAl=g_qh;  pBh=g_kbh; pBl=g_kbl; lda=ldb=DIM; K=DIM; break;
    default: pAh=g_Eh; pAl=g_Eh; pBh=g_vth; pBl=g_vth; lda=ldb=NSLOT; K=NSLOT;
             out=g_part + (size_t)bz * T_TOK * DIM; break;
    }
    int Kper = (mode == 5) ? K / gridDim.z : K;
    size_t kbase = (mode == 5) ? (size_t)bz * Kper * 2 : 0;
    const char* gsrc[4];
    gsrc[0] = (const char*)pAh + (size_t)m0*lda*2 + kbase;
    gsrc[1] = (const char*)pAl + (size_t)m0*lda*2 + kbase;
    gsrc[2] = (const char*)pBh + (size_t)n0*ldb*2 + kbase;
    gsrc[3] = (const char*)pBl + (size_t)n0*ldb*2 + kbase;
    size_t rstA = lda*2, rstB = ldb*2;

    int a_ro = (lane & 7) + ((lane & 8) ? 8 : 0);
    int a_ko = (lane & 16) ? 8 : 0;
    int b_ro = (lane & 7) + ((lane & 16) ? 8 : 0);
    int b_ko = (lane & 8) ? 8 : 0;

    float d[4][4][4] = {};
    int nk = Kper / 32;
    {
        int row = (tid >> 2), kc = tid & 3;
#pragma unroll
        for (int arr = 0; arr < 4; arr++){
            if ((TERMS == 1 && (arr & 1)) || (TERMS == 2 && arr == 1)) continue;
            size_t rs = (arr < 2) ? rstA : rstB;
            u32 db = smb + arr*ABUF;
            CPA(db + (u32)row*PITCH + kc*16, gsrc[arr] + (size_t)row*rs + kc*16);
            CPA(db + (u32)(row+64)*PITCH + kc*16, gsrc[arr] + (size_t)(row+64)*rs + kc*16);
        }
        CPCOMMIT();
    }

    for (int ck = 0; ck < nk; ck++){
        if (ck + 1 < nk){
            int row = (tid >> 2), kc = tid & 3;
            size_t koff = (size_t)(ck + 1) * 64;
            u32 db = smb + ((ck + 1) & 1) * BUFSZ;
#pragma unroll
            for (int arr = 0; arr < 4; arr++){
                if ((TERMS == 1 && (arr & 1)) || (TERMS == 2 && arr == 1)) continue;
                size_t rs = (arr < 2) ? rstA : rstB;
                const char* s = gsrc[arr] + koff;
                CPA(db + arr*ABUF + (u32)row*PITCH + kc*16, s + (size_t)row*rs + kc*16);
                CPA(db + arr*ABUF + (u32)(row+64)*PITCH + kc*16, s + (size_t)(row+64)*rs + kc*16);
            }
            CPCOMMIT();
            CPWAIT1();
        } else {
            CPWAIT0();
        }
        __syncthreads();
        u32 bb = smb + (ck & 1) * BUFSZ;
#pragma unroll
        for (int ks = 0; ks < 2; ks++){
            u32 Abase = bb + (u32)(wm*64 + a_ro)*PITCH + (ks*16 + a_ko)*2;
            u32 Bbase = bb + 2*ABUF + (u32)(wn*32 + b_ro)*PITCH + (ks*16 + b_ko)*2;
            u32 bh[2][4], a[4][4];
            LDX4(bh[0], Bbase); LDX4(bh[1], Bbase + 16*PITCH);
#pragma unroll
            for (int ma = 0; ma < 4; ma++) LDX4(a[ma], Abase + ma*16*PITCH);
#pragma unroll
            for (int ma = 0; ma < 4; ma++)
#pragma unroll
                for (int na = 0; na < 4; na++){
                    if (H) MMAH(d[ma][na], a[ma], bh[na>>1][(na&1)*2], bh[na>>1][(na&1)*2+1]);
                    else   MMAB(d[ma][na], a[ma], bh[na>>1][(na&1)*2], bh[na>>1][(na&1)*2+1]);
                }
            if (TERMS >= 2){
                u32 blr[2][4];
                LDX4(blr[0], Bbase + ABUF); LDX4(blr[1], Bbase + ABUF + 16*PITCH);
#pragma unroll
                for (int ma = 0; ma < 4; ma++)
#pragma unroll
                    for (int na = 0; na < 4; na++){
                        if (H) MMAH(d[ma][na], a[ma], blr[na>>1][(na&1)*2], blr[na>>1][(na&1)*2+1]);
                        else   MMAB(d[ma][na], a[ma], blr[na>>1][(na&1)*2], blr[na>>1][(na&1)*2+1]);
                    }
            }
            if (TERMS == 3){
                u32 a2[4][4];
#pragma unroll
                for (int ma = 0; ma < 4; ma++) LDX4(a2[ma], Abase + ABUF + ma*16*PITCH);
#pragma unroll
                for (int ma = 0; ma < 4; ma++)
#pragma unroll
                    for (int na = 0; na < 4; na++)
                        MMAB(d[ma][na], a2[ma], bh[na>>1][(na&1)*2], bh[na>>1][(na&1)*2+1]);
            }
        }
        __syncthreads();
    }

    int qr = lane >> 2, qc = lane & 3;

    if (mode == 0){
        const float* bias = g_bias + bz * DIM;
#pragma unroll
        for (int ma = 0; ma < 4; ma++)
#pragma unroll
            for (int rs = 0; rs < 2; rs++){
                int row = m0 + wm*64 + ma*16 + rs*8 + qr;
#pragma unroll
                for (int na = 0; na < 4; na++){
                    int cg = n0 + wn*32 + na*8 + 2*qc;
                    float v0 = d[ma][na][rs*2]   + bias[cg];
                    float v1 = d[ma][na][rs*2+1] + bias[cg+1];
                    if (bz == 2){
                        *(__half2*)&g_qh[(size_t)row*DIM + cg] = __floats2half2_rn(v0, v1);
                    } else {
                        *(float2*)&out[(size_t)row*DIM + cg] = make_float2(v0, v1);
                        if (bz == 0){
                            bf16 h0 = __float2bfloat16(v0), h1 = __float2bfloat16(v1);
                            *(__nv_bfloat162*)&oh[(size_t)row*DIM+cg] = __nv_bfloat162(h0, h1);
                            *(__nv_bfloat162*)&ol[(size_t)row*DIM+cg] = __nv_bfloat162(
                                __float2bfloat16(v0 - __bfloat162float(h0)),
                                __float2bfloat16(v1 - __bfloat162float(h1)));
                        }
                    }
                }
            }
    } else if (mode == 3){
        u64* cm = guard ? g_cmax : g_cmax2;
#pragma unroll
        for (int ma = 0; ma < 4; ma++)
#pragma unroll
            for (int rs = 0; rs < 2; rs++){
                int row = m0 + wm*64 + ma*16 + rs*8 + qr;
                float bv = -CUDART_INF_F; int bi = 0x7fffffff;
#pragma unroll
                for (int na = 0; na < 4; na++)
#pragma unroll
                    for (int e = 0; e < 2; e++){
                        float v = d[ma][na][rs*2+e];
                        int col = n0 + wn*32 + na*8 + 2*qc + e;
                        if (v > bv){ bv = v; bi = col; }
                    }
#pragma unroll
                for (int o = 1; o < 4; o <<= 1){
                    float ov = __shfl_xor_sync(FULLM, bv, o);
                    int   oi = __shfl_xor_sync(FULLM, bi, o);
                    if (ov > bv || (ov == bv && oi < bi)){ bv = ov; bi = oi; }
                }
                if (qc == 0){
                    atomicMax(&cm[row], ((u64)fmap(bv) << 32) | (u32)(~(u32)bi));
                    if (guard && bv >= 7.4f) atomicOr(&g_simflag, 1);
                }
            }
    } else if (mode == 4){
#pragma unroll
        for (int ma = 0; ma < 4; ma++)
#pragma unroll
            for (int rs = 0; rs < 2; rs++){
                int row = m0 + wm*64 + ma*16 + rs*8 + qr;
                float rsum = 0.f;
#pragma unroll
                for (int na = 0; na < 4; na++){
                    int cg = n0 + wn*32 + na*8 + 2*qc;
                    float e0 = __expf(d[ma][na][rs*2]  *0.0625f + g_lb[cg]   - SHIFTC);
                    float e1 = __expf(d[ma][na][rs*2+1]*0.0625f + g_lb[cg+1] - SHIFTC);
                    rsum += e0 + e1;
                    *(__half2*)&g_Eh[(size_t)row*NSLOT + cg] = __floats2half2_rn(e0, e1);
                }
                rsum += __shfl_xor_sync(FULLM, rsum, 1);
                rsum += __shfl_xor_sync(FULLM, rsum, 2);
                if (qc == 0) atomicAdd(&g_rowsum[row], rsum);
            }
    } else {
#pragma unroll
        for (int ma = 0; ma < 4; ma++)
#pragma unroll
            for (int rs = 0; rs < 2; rs++){
                int row = m0 + wm*64 + ma*16 + rs*8 + qr;
#pragma unroll
                for (int na = 0; na < 4; na++){
                    int cg = n0 + wn*32 + na*8 + 2*qc;
                    *(float2*)&out[(size_t)row*DIM + cg] =
                        make_float2(d[ma][na][rs*2], d[ma][na][rs*2+1]);
                }
            }
    }
}

// ---------------- attnC reduce (2 partials) ----------------
__global__ void attnC_red(float* __restrict__ out)
{
    int i = blockIdx.x * blockDim.x + threadIdx.x;
    int row = i >> 6;
    float inv = 1.0f / g_rowsum[row];
    float4 s = *(float4*)&g_part[(size_t)i*4];
    float4 b = *(float4*)&g_part[(size_t)T_TOK*DIM + i*4];
    s.x = (s.x+b.x)*inv; s.y = (s.y+b.y)*inv;
    s.z = (s.z+b.z)*inv; s.w = (s.w+b.w)*inv;
    *(float4*)&out[(size_t)i*4] = s;
}

// ---------------- splits ----------------
__device__ __forceinline__ void split_range(const float* src, bf16* h, bf16* l, int n, int tid, int nth)
{
    for (int i = tid; i < n; i += nth){
        float v = src[i];
        bf16 hi = __float2bfloat16(v);
        h[i] = hi;
        l[i] = __float2bfloat16(v - __bfloat162float(hi));
    }
}
__global__ void splitAB_kernel(const float* __restrict__ x, const float* __restrict__ Wk,
                               const float* __restrict__ Wv, const float* __restrict__ Wq,
                               const float* __restrict__ keys0,
                               const float* __restrict__ bk, const float* __restrict__ bv,
                               const float* __restrict__ bq)
{
    int tid = blockIdx.x * blockDim.x + threadIdx.x;
    if (tid == 0) g_simflag = 0;
    int nth = gridDim.x * blockDim.x;
    if (tid < DIM){
        g_bias[tid] = bk[tid];
        g_bias[DIM + tid] = bv[tid];
        g_bias[2*DIM + tid] = bq[tid];
    }
    for (int t = tid; t < T_TOK; t += nth){ g_cmax[t] = 0ull; g_cmax2[t] = 0ull; }
    split_range(x, g_xhi, g_xlo, T_TOK*DIM, tid, nth);
    split_range(Wk, g_wkh, g_wkl, DIM*DIM, tid, nth);
    split_range(Wv, g_wvh, g_wvl, DIM*DIM, tid, nth);
    split_range(Wq, g_wqh, g_wql, DIM*DIM, tid, nth);
    split_range(keys0, g_k0h, g_k0l, NSLOT*DIM, tid, nth);
}

// vb fp16 transpose (single) + lb + rowsum init
__global__ void tsplit_vb()
{
    __shared__ float t[32][33];
    int x = threadIdx.x, y = threadIdx.y;
    int nb = blockIdx.x * 32, db = blockIdx.y * 32;
#pragma unroll
    for (int j = 0; j < 4; j++)
        t[y + 8*j][x] = g_vb[(size_t)(nb + y + 8*j)*DIM + db + x];
    __syncthreads();
#pragma unroll
    for (int j = 0; j < 4; j++){
        float v = t[x][y + 8*j];
        g_vth[(size_t)(db + y + 8*j)*NSLOT + nb + x] = __float2half_rn(v);
    }
    if (blockIdx.x == 0 && blockIdx.y == 0){
        int tid = y * 32 + x;
        for (int n = tid; n < T_TOK; n += 256) g_rowsum[n] = 0.f;
        for (int n = tid; n < NSLOT; n += 256){
            float a = g_act[n];
            g_lb[n] = (a < 0.01f) ? -1e30f : logf(a);
        }
    }
}

// ---------------- parallel scan: trajectory sort ---------------------------
#define SP_SMEM (131072 + 32768 + 16384 + 64)
__global__ __launch_bounds__(1024) void scan_par(const float* __restrict__ act0,
                                                 const void* __restrict__ maskptr)
{
    extern __shared__ char sm[];
    u64* keys = (u64*)sm;
    u32* ml   = (u32*)(sm + 131072);
    int* cnt  = (int*)(sm + 131072 + 32768);
    int* ctl  = (int*)(sm + 131072 + 32768 + 16384);
    int tid = threadIdx.x;
    if (tid == 0){ ctl[0] = 0; }
    __syncthreads();

    const u64* cm = g_simflag ? g_cmax2 : g_cmax;
    const unsigned* w = (const unsigned*)maskptr;
    bool bytemode = (w[0] == 0x01010101u);

    u32 inf8[8]; int myc = 0;
    int base = tid * 8;
#pragma unroll
    for (int j = 0; j < 8; j++){
        int t = base + j;
        u64 c = cm[t];
        float best = funmap((u32)(c >> 32));
        int bi = (int)(~(u32)c) & 0xFFFF;
        bool novel = (best * 0.0625f) < 0.5f;
        bool m = bytemode ? (((const unsigned char*)maskptr)[t] != 0) : (w[t] != 0);
        u32 inf = (u32)bi | (novel ? 0x10000u : 0u) | (m ? 0x20000u : 0u);
        g_info[t] = inf;
        inf8[j] = inf;
        if ((inf & 0x30000u) == 0x20000u) atomicOr(&ctl[0], 1);
        if (inf & 0x20000u) myc++;
    }
    for (int s = tid; s < NSLOT; s += 1024){
        float a = act0[s];
        if (!(a >= 0.0f)) atomicOr(&ctl[0], 1);
    }
    cnt[tid] = myc;
    __syncthreads();
    for (int off = 1; off < 1024; off <<= 1){
        int v = (tid >= off) ? cnt[tid - off] : 0;
        __syncthreads();
        cnt[tid] += v;
        __syncthreads();
    }
    int mybase = cnt[tid] - myc;
    int m_count = cnt[1023];
    {
        int wr = mybase;
#pragma unroll
        for (int j = 0; j < 8; j++)
            if (inf8[j] & 0x20000u) ml[wr++] = base + j;
    }
    __syncthreads();

    u32 lov = 0, hiv = 0x3F7FFFFFu;
    for (int pass = 0; pass < 2 || lov < hiv; ){
        u32 mid = (pass < 2) ? hiv : lov + ((hiv - lov) >> 1);
        float V = __uint_as_float(mid);
        __syncthreads();
        if (tid == 0) ctl[1] = 0;
        __syncthreads();
        int c = 0;
        for (int s = tid; s < NSLOT; s += 1024){
            float v = act0[s]; int g = 0;
            while (v < 1.0f && v <= V && g < 64){ c++; g++; v = fminf(1.0f, v + 0.1f); }
        }
#pragma unroll
        for (int o = 16; o; o >>= 1) c += __shfl_xor_sync(FULLM, c, o);
        if ((tid & 31) == 0) atomicAdd(&ctl[1], c);
        __syncthreads();
        int tot = ctl[1];
        if (pass < 2){
            if (pass == 0 && tot < m_count){ if (tid == 0) ctl[0] = 1; }
            pass = 2;
            if (ctl[0]) break;
            if (tot >= m_count) ; else lov = hiv;
        } else {
            if (tot >= m_count) hiv = mid; else lov = mid + 1;
        }
    }
    __syncthreads();
    if (ctl[0]){ if (tid == 0) g_scanflag = 1; return; }
    if (tid == 0) g_scanflag = 0;
    float Vf = __uint_as_float(hiv);

    if (tid == 0) ctl[2] = 0;
    for (int i = tid; i < 16384; i += 1024) keys[i] = ~0ull;
    __syncthreads();
    for (int s = tid; s < NSLOT; s += 1024){
        float v = act0[s]; int g = 0;
        while (v < 1.0f && v <= Vf && g < 64){
            int pos = atomicAdd(&ctl[2], 1);
            keys[pos] = ((u64)__float_as_uint(v) << 32) | (u32)s;
            v = fminf(1.0f, v + 0.1f); g++;
        }
    }
    __syncthreads();

    for (u32 k2 = 2; k2 <= 16384; k2 <<= 1){
        for (u32 j = k2 >> 1; j > 0; j >>= 1){
            for (u32 i = tid; i < 16384; i += 1024){
                u32 ixj = i ^ j;
                if (ixj > i){
                    u64 a = keys[i], b = keys[ixj];
                    bool up = ((i & k2) == 0);
                    if ((a > b) == up){ keys[i] = b; keys[ixj] = a; }
                }
            }
            __syncthreads();
        }
    }

    for (int r = tid; r < m_count; r += 1024){
        u32 slot = (u32)keys[r] & 0xFFFFu;
        g_pick[ml[r]] = slot | 0x30000u;
    }
#pragma unroll
    for (int j = 0; j < 8; j++)
        if (!(inf8[j] & 0x20000u)) g_pick[base + j] = 0u;
    for (int i = tid; i < NSLOT; i += 1024) cnt[i] = 0;
    __syncthreads();
    for (int r = tid; r < m_count; r += 1024)
        atomicAdd(&cnt[(u32)keys[r] & 0xFFFFu], 1);
    __syncthreads();
    for (int s = tid; s < NSLOT; s += 1024){
        float v = act0[s]; int k = cnt[s];
        for (int j = 0; j < k; j++) v = fminf(1.0f, v + 0.1f);
        g_act[s] = v;
    }
}

// ---------------- slow exact scan (fallback, flag-gated) -------------------
__global__ __launch_bounds__(256) void scan_kernel(const float* __restrict__ act0)
{
    if (g_scanflag == 0) return;
    __shared__ __align__(16) float s_act[NSLOT];
    __shared__ __align__(16) float s_gmin[128];
    __shared__ int s_gidx[128];
    int tid = threadIdx.x;
    for (int i = tid; i < NSLOT; i += 256) s_act[i] = act0[i];
    __syncthreads();
    int wid = tid >> 5, lane = tid & 31;
    for (int g = wid; g < 128; g += 8){
        float v = s_act[g * 32 + lane];
        unsigned mv = __reduce_min_sync(FULLM, __float_as_uint(v));
        unsigned bal = __ballot_sync(FULLM, __float_as_uint(v) == mv);
        if (lane == 0){ s_gmin[g] = __uint_as_float(mv); s_gidx[g] = g * 32 + (__ffs(bal) - 1); }
    }
    __syncthreads();
    if (wid == 0){
        unsigned myinfo = 0;
        for (int t = 0; t < T_TOK; t++){
            if ((t & 31) == 0) myinfo = __ldg(&g_info[t + lane]);
            unsigned info = __shfl_sync(FULLM, myinfo, t & 31);
            if (info & 0x20000u){
                int slot;
                if (info & 0x10000u){
                    float4 q4 = *(const float4*)&s_gmin[lane * 4];
                    float bv = q4.x; int bg = lane * 4;
                    if (q4.y < bv){ bv = q4.y; bg = lane * 4 + 1; }
                    if (q4.z < bv){ bv = q4.z; bg = lane * 4 + 2; }
                    if (q4.w < bv){ bv = q4.w; bg = lane * 4 + 3; }
                    unsigned mv = __reduce_min_sync(FULLM, __float_as_uint(bv));
                    unsigned bal = __ballot_sync(FULLM, __float_as_uint(bv) == mv);
                    int L = __ffs(bal) - 1;
                    int grp = __shfl_sync(FULLM, bg, L);
                    slot = s_gidx[grp];
                } else {
                    slot = (int)(info & 0xFFFFu);
                }
                float na = fminf(1.0f, s_act[slot] + 0.1f);
                if (lane == 0) s_act[slot] = na;
                __syncwarp();
                int g = slot >> 5;
                float v = s_act[g * 32 + lane];
                unsigned mv2 = __reduce_min_sync(FULLM, __float_as_uint(v));
                unsigned bal2 = __ballot_sync(FULLM, __float_as_uint(v) == mv2);
                if (lane == 0){
                    s_gmin[g] = __uint_as_float(mv2);
                    s_gidx[g] = g * 32 + (__ffs(bal2) - 1);
                    g_pick[t] = (unsigned)slot | (info & 0x10000u) | 0x20000u;
                }
                __syncwarp();
            } else {
                if (lane == 0) g_pick[t] = 0u;
            }
        }
    }
    __syncthreads();
    for (int i = tid; i < NSLOT; i += 256) g_act[i] = s_act[i];
}

// ---------------- rebuild: EMA replay + direct fp16 kb split ---------------
__global__ __launch_bounds__(256) void rebuild_kernel(
    const float* __restrict__ keys0, const float* __restrict__ values0)
{
    int wid = threadIdx.x >> 5, lane = threadIdx.x & 31;
    int s = blockIdx.x * 8 + wid;
    float kreg[8], vreg[8];
#pragma unroll
    for (int r = 0; r < 8; r++){
        kreg[r] = keys0[s * DIM + lane + 32 * r];
        vreg[r] = values0[s * DIM + lane + 32 * r];
    }
    for (int base = 0; base < T_TOK; base += 32){
        unsigned pk = __ldg(&g_pick[base + lane]);
        unsigned match = __ballot_sync(FULLM,
            (pk & 0x20000u) && ((pk & 0xFFFFu) == (unsigned)s));
        while (match){
            int bl = __ffs(match) - 1;
            match &= match - 1;
            unsigned pkb = __shfl_sync(FULLM, pk, bl);
            float alpha = (pkb & 0x10000u) ? 0.9f : 0.3f;
            float om = 1.0f - alpha;
            int t = base + bl;
            const float* kr = &g_k[(size_t)t * DIM];
            const float* vr = &g_v[(size_t)t * DIM];
#pragma unroll
            for (int r = 0; r < 8; r++){
                kreg[r] = om * kreg[r] + alpha * __ldg(&kr[lane + 32 * r]);
                vreg[r] = om * vreg[r] + alpha * __ldg(&vr[lane + 32 * r]);
            }
        }
    }
#pragma unroll
    for (int r = 0; r < 8; r++){
        int d0 = s * DIM + lane + 32 * r;
        g_vb[d0] = vreg[r];
        __half hi = __float2half_rn(kreg[r]);
        g_kbh[d0] = hi;
        g_kbl[d0] = __float2half_rn(kreg[r] - __half2float(hi));
    }
}

// --------------------------------- launch --------------------------------
extern "C" void kernel_launch(void* const* d_in, const int* in_sizes, int n_in,
                              void* d_out, int out_size)
{
    const float* x     = (const float*)d_in[0];
    const void*  wmask = d_in[1];
    const float* keys0 = (const float*)d_in[2];
    const float* vals0 = (const float*)d_in[3];
    const float* act0  = (const float*)d_in[4];
    const float* Wk    = (const float*)d_in[5];
    const float* bk    = (const float*)d_in[6];
    const float* Wv    = (const float*)d_in[7];
    const float* bv    = (const float*)d_in[8];
    const float* Wq    = (const float*)d_in[9];
    const float* bq    = (const float*)d_in[10];
    float* out = (float*)d_out;

    cudaFuncSetAttribute(mm_gemm<3,false>, cudaFuncAttributeMaxDynamicSharedMemorySize, SMEMSZ);
    cudaFuncSetAttribute(mm_gemm<1,false>, cudaFuncAttributeMaxDynamicSharedMemorySize, SMEMSZ);
    cudaFuncSetAttribute(mm_gemm<1,true>,  cudaFuncAttributeMaxDynamicSharedMemorySize, SMEMSZ);
    cudaFuncSetAttribute(scan_par, cudaFuncAttributeMaxDynamicSharedMemorySize, SP_SMEM);

    splitAB_kernel<<<256, 256>>>(x, Wk, Wv, Wq, keys0, bk, bv, bq);

    mm_gemm<3,false><<<dim3(64,2,3), 256, SMEMSZ>>>(0);   // fused k/v/q projections
    mm_gemm<1,false><<<dim3(64,32), 256, SMEMSZ>>>(3);    // simmax 1-term + guard + atomic combine
    mm_gemm<3,false><<<dim3(64,32), 256, SMEMSZ>>>(6);    // exact simmax, flag-gated

    scan_par<<<1, 1024, SP_SMEM>>>(act0, wmask);          // info decode + trajectory-sort scan
    scan_kernel<<<1, 256>>>(act0);                        // exact fallback, flag-gated
    rebuild_kernel<<<NSLOT/8, 256>>>(keys0, vals0);       // EMA replay + fp16 kb split
    tsplit_vb<<<dim3(128,8), dim3(32,8)>>>();             // vb fp16 transpose + lb/rowsum

    mm_gemm<1,true><<<dim3(64,32), 256, SMEMSZ>>>(4);     // attnA fp16 1-term: QK+exp+rowsum
    mm_gemm<1,true><<<dim3(64,2,2), 256, SMEMSZ>>>(5);    // attnC fp16 1-term splitK=2
    attnC_red<<<T_TOK*DIM/1024, 256>>>(out);
}